// round 7
// baseline (speedup 1.0000x reference)
#include <cuda_runtime.h>
#include <math.h>

#define NPT 2048
#define NTOT 4096
typedef unsigned long long ull;

__device__ float g_xf[(size_t)NTOT * 784];
__device__ float g_cm[(size_t)NTOT * 49];
__device__ float g_r[NTOT];
// pre-transposed weights (written once per launch by k_prep)
__device__ __align__(16) float g_w1t[3136];
__device__ __align__(16) float g_w2t[6400];
__device__ __align__(16) float g_w3t[2304];
__device__ __align__(16) float g_w4t[2304];

__device__ __forceinline__ float lrelu(float v) { return v >= 0.f ? v : 0.01f * v; }
__device__ __forceinline__ ull pack2(float x) {
  ull r; asm("mov.b64 %0,{%1,%1};" : "=l"(r) : "f"(x)); return r;
}
__device__ __forceinline__ void ffma2(ull& d, ull a, ull b) {
  asm("fma.rn.f32x2 %0,%1,%2,%0;" : "+l"(d) : "l"(a), "l"(b));
}
__device__ __forceinline__ float2 unpack2(ull v) {
  float2 r; asm("mov.b64 {%0,%1},%2;" : "=f"(r.x), "=f"(r.y) : "l"(v)); return r;
}

// smem float offsets — 15176 floats = 60704 B -> 3 blocks/SM
#define OFF_ACT26 0        // 10816  [co*676 + p]
#define OFF_K26   10816    // 832    [w*32 + k] (32-padded rows)
#define OFF_K11   11648    // 132    [w*12 + k]
#define OFF_SB1   11780
#define OFF_SB2   11796
#define OFF_SB3   11812
#define OFF_SB4   11828
#define OFF_SCM   11844    // 100
#define OFF_ACT11 11944    // 1936   [co*121 + p]
#define OFF_ACT9  13880    // 1296   [co*81 + p]
#define OFF_W1    11944    // 3136 (aliases ACT11/ACT9; dead before conv2)
#define SMEM_FLOATS 15176

// ---------------- one-time weight transpose ----------------
__global__ void k_prep(const float* __restrict__ w1, const float* __restrict__ w2,
                       const float* __restrict__ w3, const float* __restrict__ w4) {
  int tid = blockIdx.x * blockDim.x + threadIdx.x;
  for (int i = tid; i < 3136; i += 2048) {
    int co = i & 15, r = i >> 4, ci = r & 3, kk = r >> 2;
    g_w1t[i] = w1[co * 196 + ci * 49 + kk];
  }
  for (int i = tid; i < 6400; i += 2048) g_w2t[i] = w2[(i & 15) * 400 + (i >> 4)];
  for (int i = tid; i < 2304; i += 2048) g_w3t[i] = w3[(i & 15) * 144 + (i >> 4)];
  for (int i = tid; i < 2304; i += 2048) g_w4t[i] = w4[(i & 15) * 144 + (i >> 4)];
}

__global__ __launch_bounds__(256, 3) void k_net(
    const float* __restrict__ ti, const float* __restrict__ tj,
    const float* __restrict__ g26i, const float* __restrict__ g26j,
    const float* __restrict__ g11i, const float* __restrict__ g11j,
    const float* __restrict__ b1, const float* __restrict__ b2,
    const float* __restrict__ b3, const float* __restrict__ b4) {
  extern __shared__ float sm[];
  int n = blockIdx.x, tid = threadIdx.x;
  const float sc = 1.0f / (0.7f * 0.3f);

  const float* x   = (n < NPT) ? ti   + (size_t)n * 28224 : tj   + (size_t)(n - NPT) * 28224;
  const float* g26 = (n < NPT) ? g26i + (size_t)n * 676   : g26j + (size_t)(n - NPT) * 676;
  const float* g11 = (n < NPT) ? g11i + (size_t)n * 121   : g11j + (size_t)(n - NPT) * 121;

  // ---- phase 0: W1 (smem, aliased), gaze kernels, biases ----
  {
    const float4* w1g = (const float4*)g_w1t;
    float4* w1s = (float4*)(sm + OFF_W1);
    for (int i = tid; i < 784; i += 256) w1s[i] = w1g[i];
  }
  for (int i = tid; i < 832; i += 256) {
    int wdx = i >> 5, k = i & 31;
    sm[OFF_K26 + i] = (k < 26) ? (g26[wdx * 26 + k] - 0.3f) * sc : 0.f;
  }
  for (int i = tid; i < 132; i += 256) {
    int wdx = i / 12, k = i - wdx * 12;
    sm[OFF_K11 + i] = (k < 11) ? (g11[wdx * 11 + k] - 0.3f) * sc : 0.f;
  }
  if (tid < 16) {
    sm[OFF_SB1 + tid] = b1[tid]; sm[OFF_SB2 + tid] = b2[tid];
    sm[OFF_SB3 + tid] = b3[tid]; sm[OFF_SB4 + tid] = b4[tid];
  }
  __syncthreads();

  // ---- phase 1: conv1 7x7 s3 4->16, leaky. Pixel-pairs, input from global ----
  {
    const float4* xg = (const float4*)x;
    const float* sw1 = sm + OFF_W1;
    const float* sb1 = sm + OFF_SB1;
    for (int i = tid; i < 338; i += 256) {
      int oh = i / 13, j = i - oh * 13;
      int ow0 = 2 * j;
      ull a0[8], a1[8];
#pragma unroll
      for (int q = 0; q < 8; q++) { a0[q] = 0ULL; a1[q] = 0ULL; }
      for (int kh = 0; kh < 7; kh++) {
        const float4* xr = xg + (oh * 3 + kh) * 84 + 6 * j;
        // chunk A: kw 0..2 (uses idx 0..5)
        {
          float4 xv[6];
#pragma unroll
          for (int q = 0; q < 6; q++) xv[q] = xr[q];
#pragma unroll
          for (int kw = 0; kw < 3; kw++) {
            const ulonglong2* wq = (const ulonglong2*)(sw1 + (kh * 7 + kw) * 64);
            float xa[4] = {xv[kw].x, xv[kw].y, xv[kw].z, xv[kw].w};
            float xb[4] = {xv[kw + 3].x, xv[kw + 3].y, xv[kw + 3].z, xv[kw + 3].w};
#pragma unroll
            for (int ci = 0; ci < 4; ci++) {
              ull xx0 = pack2(xa[ci]);
              ull xx1 = pack2(xb[ci]);
              ulonglong2 q0 = wq[ci * 4 + 0], q1 = wq[ci * 4 + 1];
              ulonglong2 q2 = wq[ci * 4 + 2], q3 = wq[ci * 4 + 3];
              ffma2(a0[0], xx0, q0.x); ffma2(a0[1], xx0, q0.y);
              ffma2(a0[2], xx0, q1.x); ffma2(a0[3], xx0, q1.y);
              ffma2(a0[4], xx0, q2.x); ffma2(a0[5], xx0, q2.y);
              ffma2(a0[6], xx0, q3.x); ffma2(a0[7], xx0, q3.y);
              ffma2(a1[0], xx1, q0.x); ffma2(a1[1], xx1, q0.y);
              ffma2(a1[2], xx1, q1.x); ffma2(a1[3], xx1, q1.y);
              ffma2(a1[4], xx1, q2.x); ffma2(a1[5], xx1, q2.y);
              ffma2(a1[6], xx1, q3.x); ffma2(a1[7], xx1, q3.y);
            }
          }
        }
        // chunk B: kw 3..6 (uses idx 3..9)
        {
          float4 yv[7];
#pragma unroll
          for (int q = 0; q < 7; q++) yv[q] = xr[3 + q];
#pragma unroll
          for (int kw = 3; kw < 7; kw++) {
            const ulonglong2* wq = (const ulonglong2*)(sw1 + (kh * 7 + kw) * 64);
            float xa[4] = {yv[kw - 3].x, yv[kw - 3].y, yv[kw - 3].z, yv[kw - 3].w};
            float xb[4] = {yv[kw].x, yv[kw].y, yv[kw].z, yv[kw].w};
#pragma unroll
            for (int ci = 0; ci < 4; ci++) {
              ull xx0 = pack2(xa[ci]);
              ull xx1 = pack2(xb[ci]);
              ulonglong2 q0 = wq[ci * 4 + 0], q1 = wq[ci * 4 + 1];
              ulonglong2 q2 = wq[ci * 4 + 2], q3 = wq[ci * 4 + 3];
              ffma2(a0[0], xx0, q0.x); ffma2(a0[1], xx0, q0.y);
              ffma2(a0[2], xx0, q1.x); ffma2(a0[3], xx0, q1.y);
              ffma2(a0[4], xx0, q2.x); ffma2(a0[5], xx0, q2.y);
              ffma2(a0[6], xx0, q3.x); ffma2(a0[7], xx0, q3.y);
              ffma2(a1[0], xx1, q0.x); ffma2(a1[1], xx1, q0.y);
              ffma2(a1[2], xx1, q1.x); ffma2(a1[3], xx1, q1.y);
              ffma2(a1[4], xx1, q2.x); ffma2(a1[5], xx1, q2.y);
              ffma2(a1[6], xx1, q3.x); ffma2(a1[7], xx1, q3.y);
            }
          }
        }
      }
      float* sact = sm + OFF_ACT26;
      int p0 = oh * 26 + ow0;
#pragma unroll
      for (int q = 0; q < 8; q++) {
        float2 v0 = unpack2(a0[q]);
        float2 v1 = unpack2(a1[q]);
        int co = 2 * q;
        sact[co * 676 + p0]           = lrelu(v0.x + sb1[co]);
        sact[(co + 1) * 676 + p0]     = lrelu(v0.y + sb1[co + 1]);
        sact[co * 676 + p0 + 1]       = lrelu(v1.x + sb1[co]);
        sact[(co + 1) * 676 + p0 + 1] = lrelu(v1.y + sb1[co + 1]);
      }
    }
  }
  __syncthreads();

  // ---- phase 2: gaze26 in-place (row per thread) ----
  for (int i = tid; i < 416; i += 256) {
    int c = i / 26, h = i - c * 26;
    float* row = sm + OFF_ACT26 + c * 676 + h * 26;
    const float* K = sm + OFF_K26;
    float a[26];
#pragma unroll
    for (int w = 0; w < 26; w++) a[w] = row[w];
    ull acc[14];
#pragma unroll
    for (int q = 0; q < 14; q++) acc[q] = 0ULL;
#pragma unroll
    for (int w = 0; w < 26; w++) {
      ull xx = pack2(a[w]);
      const ulonglong2* kr = (const ulonglong2*)(K + w * 32);
#pragma unroll
      for (int q = 0; q < 7; q++) {
        ulonglong2 kv = kr[q];
        ffma2(acc[2 * q], xx, kv.x);
        ffma2(acc[2 * q + 1], xx, kv.y);
      }
    }
#pragma unroll
    for (int q = 0; q < 13; q++) {
      float2 v = unpack2(acc[q]);
      row[2 * q] = v.x; row[2 * q + 1] = v.y;
    }
  }
  __syncthreads();

  // ---- phase 3: conv2 5x5 s2 16->16, leaky. px x co-half (242); W from global ----
  if (tid < 242) {
    int half = tid & 1, p = tid >> 1;
    int oh = p / 11, ow = p - oh * 11;
    int ih0 = oh * 2, iw0 = ow * 2;
    ull acc[4] = {0ULL, 0ULL, 0ULL, 0ULL};
    const float* sact = sm + OFF_ACT26;
    for (int ci = 0; ci < 16; ci++) {
      const float* irow = sact + ci * 676;
#pragma unroll
      for (int kh = 0; kh < 5; kh++) {
        const float* ir = irow + (ih0 + kh) * 26 + iw0;
#pragma unroll
        for (int kw = 0; kw < 5; kw++) {
          ull xx = pack2(ir[kw]);
          const ulonglong2* wq =
              (const ulonglong2*)(g_w2t + (ci * 25 + kh * 5 + kw) * 16 + half * 8);
          ulonglong2 q0 = wq[0], q1 = wq[1];
          ffma2(acc[0], xx, q0.x); ffma2(acc[1], xx, q0.y);
          ffma2(acc[2], xx, q1.x); ffma2(acc[3], xx, q1.y);
        }
      }
    }
    float* act11 = sm + OFF_ACT11;
    const float* sb2 = sm + OFF_SB2;
#pragma unroll
    for (int q = 0; q < 4; q++) {
      float2 v = unpack2(acc[q]);
      int co = half * 8 + 2 * q;
      act11[co * 121 + p]       = lrelu(v.x + sb2[co]);
      act11[(co + 1) * 121 + p] = lrelu(v.y + sb2[co + 1]);
    }
  }
  __syncthreads();

  // ---- phase 4: gaze11 in-place (176) ----
  if (tid < 176) {
    int c = tid / 11, h = tid - c * 11;
    float* row = sm + OFF_ACT11 + c * 121 + h * 11;
    const float* K = sm + OFF_K11;
    float a[11];
#pragma unroll
    for (int w = 0; w < 11; w++) a[w] = row[w];
    ull acc[6];
#pragma unroll
    for (int q = 0; q < 6; q++) acc[q] = 0ULL;
#pragma unroll
    for (int w = 0; w < 11; w++) {
      ull xx = pack2(a[w]);
      const ulonglong2* kr = (const ulonglong2*)(K + w * 12);
#pragma unroll
      for (int q = 0; q < 3; q++) {
        ulonglong2 kv = kr[q];
        ffma2(acc[2 * q], xx, kv.x);
        ffma2(acc[2 * q + 1], xx, kv.y);
      }
    }
#pragma unroll
    for (int q = 0; q < 5; q++) {
      float2 v = unpack2(acc[q]);
      row[2 * q] = v.x; row[2 * q + 1] = v.y;
    }
    row[10] = unpack2(acc[5]).x;
  }
  __syncthreads();

  // ---- phase 5: conv3 3x3 16->16, leaky. px x co-half (162); W from global ----
  if (tid < 162) {
    int half = tid & 1, p = tid >> 1;
    int oh = p / 9, ow = p - oh * 9;
    ull acc[4] = {0ULL, 0ULL, 0ULL, 0ULL};
    const float* act11 = sm + OFF_ACT11;
    for (int ci = 0; ci < 16; ci++) {
      const float* irow = act11 + ci * 121;
#pragma unroll
      for (int kh = 0; kh < 3; kh++) {
        const float* ir = irow + (oh + kh) * 11 + ow;
#pragma unroll
        for (int kw = 0; kw < 3; kw++) {
          ull xx = pack2(ir[kw]);
          const ulonglong2* wq =
              (const ulonglong2*)(g_w3t + (ci * 9 + kh * 3 + kw) * 16 + half * 8);
          ulonglong2 q0 = wq[0], q1 = wq[1];
          ffma2(acc[0], xx, q0.x); ffma2(acc[1], xx, q0.y);
          ffma2(acc[2], xx, q1.x); ffma2(acc[3], xx, q1.y);
        }
      }
    }
    float* act9 = sm + OFF_ACT9;
    const float* sb3 = sm + OFF_SB3;
#pragma unroll
    for (int q = 0; q < 4; q++) {
      float2 v = unpack2(acc[q]);
      int co = half * 8 + 2 * q;
      act9[co * 81 + p]       = lrelu(v.x + sb3[co]);
      act9[(co + 1) * 81 + p] = lrelu(v.y + sb3[co + 1]);
    }
  }
  __syncthreads();

  // ---- phase 6: conv4 3x3 16->16, leaky -> g_xf + cm. px x co-half (98) ----
  if (tid < 98) {
    int half = tid & 1, p = tid >> 1;
    int oh = p / 7, ow = p - oh * 7;
    ull acc[4] = {0ULL, 0ULL, 0ULL, 0ULL};
    const float* act9 = sm + OFF_ACT9;
    for (int ci = 0; ci < 16; ci++) {
      const float* irow = act9 + ci * 81;
#pragma unroll
      for (int kh = 0; kh < 3; kh++) {
        const float* ir = irow + (oh + kh) * 9 + ow;
#pragma unroll
        for (int kw = 0; kw < 3; kw++) {
          ull xx = pack2(ir[kw]);
          const ulonglong2* wq =
              (const ulonglong2*)(g_w4t + (ci * 9 + kh * 3 + kw) * 16 + half * 8);
          ulonglong2 q0 = wq[0], q1 = wq[1];
          ffma2(acc[0], xx, q0.x); ffma2(acc[1], xx, q0.y);
          ffma2(acc[2], xx, q1.x); ffma2(acc[3], xx, q1.y);
        }
      }
    }
    const float* sb4 = sm + OFF_SB4;
    float* xp = g_xf + (size_t)n * 784 + p;
    float cs = 0.f;
#pragma unroll
    for (int q = 0; q < 4; q++) {
      float2 v = unpack2(acc[q]);
      int co = half * 8 + 2 * q;
      float v0 = lrelu(v.x + sb4[co]);
      float v1 = lrelu(v.y + sb4[co + 1]);
      xp[co * 49] = v0;
      xp[(co + 1) * 49] = v1;
      cs += v0 + v1;
    }
    sm[OFF_SCM + tid] = cs;
  }
  __syncthreads();
  if (tid < 49)
    g_cm[(size_t)n * 49 + tid] = sm[OFF_SCM + 2 * tid] + sm[OFF_SCM + 2 * tid + 1];
}

// ---------------- fc ----------------
__global__ __launch_bounds__(256) void k_fc(const float* __restrict__ w1,
                                            const float* __restrict__ b1,
                                            const float* __restrict__ w2,
                                            const float* __restrict__ b2) {
  __shared__ float As[64][17];
  __shared__ float Bs[16][68];
  __shared__ float prs[16][64];
  int tid = threadIdx.x;
  int s0 = blockIdx.x * 64;
  int sg = tid >> 4, jg = tid & 15;
  float acc[4][4];
#pragma unroll
  for (int i = 0; i < 4; i++)
#pragma unroll
    for (int u = 0; u < 4; u++) acc[i][u] = 0.f;
  for (int k0 = 0; k0 < 784; k0 += 16) {
    for (int i = tid; i < 1024; i += 256) {
      int s = i >> 4, kk = i & 15;
      As[s][kk] = g_xf[(size_t)(s0 + s) * 784 + k0 + kk];
    }
    for (int i = tid; i < 1024; i += 256) {
      int j = i >> 4, kk = i & 15;
      Bs[kk][j] = w1[j * 784 + k0 + kk];
    }
    __syncthreads();
#pragma unroll
    for (int kk = 0; kk < 16; kk++) {
      float av[4], bv[4];
#pragma unroll
      for (int i = 0; i < 4; i++) av[i] = As[sg * 4 + i][kk];
#pragma unroll
      for (int u = 0; u < 4; u++) bv[u] = Bs[kk][jg * 4 + u];
#pragma unroll
      for (int i = 0; i < 4; i++)
#pragma unroll
        for (int u = 0; u < 4; u++) acc[i][u] += av[i] * bv[u];
    }
    __syncthreads();
  }
#pragma unroll
  for (int i = 0; i < 4; i++) {
    float pr = 0.f;
#pragma unroll
    for (int u = 0; u < 4; u++) {
      int j = jg * 4 + u;
      float h = acc[i][u] + b1[j];
      h = lrelu(h);
      pr += h * w2[j];
    }
    prs[jg][sg * 4 + i] = pr;
  }
  __syncthreads();
  if (tid < 64) {
    float s = 0.f;
#pragma unroll
    for (int j = 0; j < 16; j++) s += prs[j][tid];
    g_r[s0 + tid] = s + b2[0];
  }
}

__global__ void k_reduce_r(float* __restrict__ out) {
  __shared__ float sab[64];
  int tid = threadIdx.x;
  int traj = tid >> 5, b = tid & 31;
  float s = 0.f, sa = 0.f;
  for (int t = 0; t < 64; t++) {
    float r = g_r[traj * 2048 + t * 32 + b];
    s += r;
    sa += fabsf(r);
  }
  out[tid] = s;
  sab[tid] = sa;
  __syncthreads();
  if (tid < 32) out[64 + tid] = sab[tid] + sab[32 + tid];
}

__global__ __launch_bounds__(256) void k_cmnorm(float* __restrict__ out) {
  __shared__ float sv[1568];
  __shared__ float smn[8], smx[8];
  __shared__ float fmn, fmx;
  int idx = blockIdx.x;
  int traj = idx >> 6, t = idx & 63;
  int tid = threadIdx.x;
  const float* base = g_cm + ((size_t)(traj * 2048 + t * 32)) * 49;
  float mn = 1e30f, mx = -1e30f;
  for (int i = tid; i < 1568; i += 256) {
    float v = base[i];
    sv[i] = v;
    mn = fminf(mn, v);
    mx = fmaxf(mx, v);
  }
#pragma unroll
  for (int o = 16; o; o >>= 1) {
    mn = fminf(mn, __shfl_xor_sync(0xffffffffu, mn, o));
    mx = fmaxf(mx, __shfl_xor_sync(0xffffffffu, mx, o));
  }
  if ((tid & 31) == 0) { smn[tid >> 5] = mn; smx[tid >> 5] = mx; }
  __syncthreads();
  if (tid == 0) {
    float a = smn[0], bb = smx[0];
    for (int i = 1; i < 8; i++) { a = fminf(a, smn[i]); bb = fmaxf(bb, smx[i]); }
    fmn = a; fmx = bb;
  }
  __syncthreads();
  float m = fmn, inv = 1.f / (fmx - m);
  float* o = out + 96 + (size_t)traj * 100352 + (size_t)t * 1568;
  for (int i = tid; i < 1568; i += 256) o[i] = (sv[i] - m) * inv;
}

extern "C" void kernel_launch(void* const* d_in, const int* in_sizes, int n_in,
                              void* d_out, int out_size) {
  const float* ti   = (const float*)d_in[0];
  const float* tj   = (const float*)d_in[1];
  const float* g26i = (const float*)d_in[2];
  const float* g11i = (const float*)d_in[3];
  const float* g26j = (const float*)d_in[4];
  const float* g11j = (const float*)d_in[5];
  const float* w1 = (const float*)d_in[6];  const float* b1 = (const float*)d_in[7];
  const float* w2 = (const float*)d_in[8];  const float* b2 = (const float*)d_in[9];
  const float* w3 = (const float*)d_in[10]; const float* b3 = (const float*)d_in[11];
  const float* w4 = (const float*)d_in[12]; const float* b4 = (const float*)d_in[13];
  const float* f1w = (const float*)d_in[14]; const float* f1b = (const float*)d_in[15];
  const float* f2w = (const float*)d_in[16]; const float* f2b = (const float*)d_in[17];
  float* out = (float*)d_out;

  cudaFuncSetAttribute(k_net, cudaFuncAttributeMaxDynamicSharedMemorySize,
                       SMEM_FLOATS * 4);

  k_prep<<<4, 512>>>(w1, w2, w3, w4);
  k_net<<<NTOT, 256, SMEM_FLOATS * 4>>>(ti, tj, g26i, g26j, g11i, g11j,
                                        b1, b2, b3, b4);
  k_fc<<<NTOT / 64, 256>>>(f1w, f1b, f2w, f2b);
  k_reduce_r<<<1, 64>>>(out);
  k_cmnorm<<<128, 256>>>(out);
}

// round 9
// speedup vs baseline: 1.1651x; 1.1651x over previous
#include <cuda_runtime.h>
#include <math.h>

#define NPT 2048
#define NTOT 4096
#define TPB 352
typedef unsigned long long ull;

__device__ float g_xf[(size_t)NTOT * 784];
__device__ float g_cm[(size_t)NTOT * 49];
__device__ float g_r[NTOT];
// pre-transposed weights (written once per launch by k_prep)
__device__ __align__(16) float g_w1t[3136];
__device__ __align__(16) float g_w2t[6400];
__device__ __align__(16) float g_w3t[2304];
__device__ __align__(16) float g_w4t[2304];

__device__ __forceinline__ float lrelu(float v) { return v >= 0.f ? v : 0.01f * v; }
__device__ __forceinline__ ull pack2(float x) {
  ull r; asm("mov.b64 %0,{%1,%1};" : "=l"(r) : "f"(x)); return r;
}
__device__ __forceinline__ void ffma2(ull& d, ull a, ull b) {
  asm("fma.rn.f32x2 %0,%1,%2,%0;" : "+l"(d) : "l"(a), "l"(b));
}
__device__ __forceinline__ float2 unpack2(ull v) {
  float2 r; asm("mov.b64 {%0,%1},%2;" : "=f"(r.x), "=f"(r.y) : "l"(v)); return r;
}

// smem float offsets (total 26078 floats = 104312 B -> 2 blocks/SM at 352 thr)
#define OFF_ACT26 0        // 10816  [co*676 + p]
#define OFF_W2T   10816    // 6400   [(ci*25+t)*16 + co]
#define OFF_W3T   17216    // 2304
#define OFF_W4T   19520    // 2304
#define OFF_K26   21824    // 728    [w*28 + k]
#define OFF_K11   22552    // 132    [w*12 + k]
#define OFF_ACT11 22684    // 1936   [co*121 + p]   (aliases W1 region)
#define OFF_ACT9  24620    // 1296   [co*81 + p]
#define OFF_W1    22684    // 3136   [(kh*7+kw)*64 + ci*16 + co] (dead after conv1)
#define OFF_SB1   25916
#define OFF_SB2   25932
#define OFF_SB3   25948
#define OFF_SB4   25964
#define OFF_SCM   25980    // 98
#define SMEM_FLOATS 26078

// ---------------- one-time weight transpose ----------------
__global__ void k_prep(const float* __restrict__ w1, const float* __restrict__ w2,
                       const float* __restrict__ w3, const float* __restrict__ w4) {
  int tid = blockIdx.x * blockDim.x + threadIdx.x;
  for (int i = tid; i < 3136; i += 2048) {
    int co = i & 15, r = i >> 4, ci = r & 3, kk = r >> 2;
    g_w1t[i] = w1[co * 196 + ci * 49 + kk];
  }
  for (int i = tid; i < 6400; i += 2048) g_w2t[i] = w2[(i & 15) * 400 + (i >> 4)];
  for (int i = tid; i < 2304; i += 2048) g_w3t[i] = w3[(i & 15) * 144 + (i >> 4)];
  for (int i = tid; i < 2304; i += 2048) g_w4t[i] = w4[(i & 15) * 144 + (i >> 4)];
}

__global__ __launch_bounds__(TPB, 2) void k_net(
    const float* __restrict__ ti, const float* __restrict__ tj,
    const float* __restrict__ g26i, const float* __restrict__ g26j,
    const float* __restrict__ g11i, const float* __restrict__ g11j,
    const float* __restrict__ b1, const float* __restrict__ b2,
    const float* __restrict__ b3, const float* __restrict__ b4) {
  extern __shared__ float sm[];
  int n = blockIdx.x, tid = threadIdx.x;
  const float sc = 1.0f / (0.7f * 0.3f);

  const float* x   = (n < NPT) ? ti   + (size_t)n * 28224 : tj   + (size_t)(n - NPT) * 28224;
  const float* g26 = (n < NPT) ? g26i + (size_t)n * 676   : g26j + (size_t)(n - NPT) * 676;
  const float* g11 = (n < NPT) ? g11i + (size_t)n * 121   : g11j + (size_t)(n - NPT) * 121;

  // ---- phase 0: load weights (coalesced from pre-transposed) / gaze kernels ----
  for (int i = tid; i < 3136; i += TPB) sm[OFF_W1 + i] = g_w1t[i];
  for (int i = tid; i < 6400; i += TPB) sm[OFF_W2T + i] = g_w2t[i];
  for (int i = tid; i < 2304; i += TPB) sm[OFF_W3T + i] = g_w3t[i];
  for (int i = tid; i < 2304; i += TPB) sm[OFF_W4T + i] = g_w4t[i];
  for (int i = tid; i < 728; i += TPB) {
    int wdx = i / 28, k = i - wdx * 28;
    sm[OFF_K26 + i] = (k < 26) ? (g26[wdx * 26 + k] - 0.3f) * sc : 0.f;
  }
  for (int i = tid; i < 132; i += TPB) {
    int wdx = i / 12, k = i - wdx * 12;
    sm[OFF_K11 + i] = (k < 11) ? (g11[wdx * 11 + k] - 0.3f) * sc : 0.f;
  }
  if (tid < 16) {
    sm[OFF_SB1 + tid] = b1[tid]; sm[OFF_SB2 + tid] = b2[tid];
    sm[OFF_SB3 + tid] = b3[tid]; sm[OFF_SB4 + tid] = b4[tid];
  }
  __syncthreads();

  // ---- phase 1: conv1 7x7 s3 4->16, leaky. Pixel-pair per thread (338 items) ----
  if (tid < 338) {
    const float4* xg = (const float4*)x;
    const float* sw1 = sm + OFF_W1;
    const float* sb1 = sm + OFF_SB1;
    int oh = tid / 13, j = tid - oh * 13;
    int ow0 = 2 * j;
    ull a0[8], a1[8];
#pragma unroll
    for (int q = 0; q < 8; q++) { a0[q] = 0ULL; a1[q] = 0ULL; }
    for (int kh = 0; kh < 7; kh++) {
      const float4* xr = xg + (oh * 3 + kh) * 84 + 6 * j;
      // chunk A: kw 0..2 (uses idx 0..5)
      {
        float4 xv[6];
#pragma unroll
        for (int q = 0; q < 6; q++) xv[q] = xr[q];
#pragma unroll
        for (int kw = 0; kw < 3; kw++) {
          const ulonglong2* wq = (const ulonglong2*)(sw1 + (kh * 7 + kw) * 64);
          float xa[4] = {xv[kw].x, xv[kw].y, xv[kw].z, xv[kw].w};
          float xb[4] = {xv[kw + 3].x, xv[kw + 3].y, xv[kw + 3].z, xv[kw + 3].w};
#pragma unroll
          for (int ci = 0; ci < 4; ci++) {
            ull xx0 = pack2(xa[ci]);
            ull xx1 = pack2(xb[ci]);
            ulonglong2 q0 = wq[ci * 4 + 0], q1 = wq[ci * 4 + 1];
            ulonglong2 q2 = wq[ci * 4 + 2], q3 = wq[ci * 4 + 3];
            ffma2(a0[0], xx0, q0.x); ffma2(a0[1], xx0, q0.y);
            ffma2(a0[2], xx0, q1.x); ffma2(a0[3], xx0, q1.y);
            ffma2(a0[4], xx0, q2.x); ffma2(a0[5], xx0, q2.y);
            ffma2(a0[6], xx0, q3.x); ffma2(a0[7], xx0, q3.y);
            ffma2(a1[0], xx1, q0.x); ffma2(a1[1], xx1, q0.y);
            ffma2(a1[2], xx1, q1.x); ffma2(a1[3], xx1, q1.y);
            ffma2(a1[4], xx1, q2.x); ffma2(a1[5], xx1, q2.y);
            ffma2(a1[6], xx1, q3.x); ffma2(a1[7], xx1, q3.y);
          }
        }
      }
      // chunk B: kw 3..6 (uses idx 3..9)
      {
        float4 yv[7];
#pragma unroll
        for (int q = 0; q < 7; q++) yv[q] = xr[3 + q];
#pragma unroll
        for (int kw = 3; kw < 7; kw++) {
          const ulonglong2* wq = (const ulonglong2*)(sw1 + (kh * 7 + kw) * 64);
          float xa[4] = {yv[kw - 3].x, yv[kw - 3].y, yv[kw - 3].z, yv[kw - 3].w};
          float xb[4] = {yv[kw].x, yv[kw].y, yv[kw].z, yv[kw].w};
#pragma unroll
          for (int ci = 0; ci < 4; ci++) {
            ull xx0 = pack2(xa[ci]);
            ull xx1 = pack2(xb[ci]);
            ulonglong2 q0 = wq[ci * 4 + 0], q1 = wq[ci * 4 + 1];
            ulonglong2 q2 = wq[ci * 4 + 2], q3 = wq[ci * 4 + 3];
            ffma2(a0[0], xx0, q0.x); ffma2(a0[1], xx0, q0.y);
            ffma2(a0[2], xx0, q1.x); ffma2(a0[3], xx0, q1.y);
            ffma2(a0[4], xx0, q2.x); ffma2(a0[5], xx0, q2.y);
            ffma2(a0[6], xx0, q3.x); ffma2(a0[7], xx0, q3.y);
            ffma2(a1[0], xx1, q0.x); ffma2(a1[1], xx1, q0.y);
            ffma2(a1[2], xx1, q1.x); ffma2(a1[3], xx1, q1.y);
            ffma2(a1[4], xx1, q2.x); ffma2(a1[5], xx1, q2.y);
            ffma2(a1[6], xx1, q3.x); ffma2(a1[7], xx1, q3.y);
          }
        }
      }
    }
    float* sact = sm + OFF_ACT26;
    int p0 = oh * 26 + ow0;
#pragma unroll
    for (int q = 0; q < 8; q++) {
      float2 v0 = unpack2(a0[q]);
      float2 v1 = unpack2(a1[q]);
      int co = 2 * q;
      sact[co * 676 + p0]           = lrelu(v0.x + sb1[co]);
      sact[(co + 1) * 676 + p0]     = lrelu(v0.y + sb1[co + 1]);
      sact[co * 676 + p0 + 1]       = lrelu(v1.x + sb1[co]);
      sact[(co + 1) * 676 + p0 + 1] = lrelu(v1.y + sb1[co + 1]);
    }
  }
  __syncthreads();

  // ---- phase 2: gaze26 in-place (row per thread, 416 items) ----
  for (int i = tid; i < 416; i += TPB) {
    int c = i / 26, h = i - c * 26;
    float* row = sm + OFF_ACT26 + c * 676 + h * 26;
    const float* K = sm + OFF_K26;
    float a[26];
#pragma unroll
    for (int w = 0; w < 26; w++) a[w] = row[w];
    ull acc[14];
#pragma unroll
    for (int q = 0; q < 14; q++) acc[q] = 0ULL;
#pragma unroll
    for (int w = 0; w < 26; w++) {
      ull xx = pack2(a[w]);
      const ulonglong2* kr = (const ulonglong2*)(K + w * 28);
#pragma unroll
      for (int q = 0; q < 7; q++) {
        ulonglong2 kv = kr[q];
        ffma2(acc[2 * q], xx, kv.x);
        ffma2(acc[2 * q + 1], xx, kv.y);
      }
    }
#pragma unroll
    for (int q = 0; q < 13; q++) {
      float2 v = unpack2(acc[q]);
      row[2 * q] = v.x; row[2 * q + 1] = v.y;
    }
  }
  __syncthreads();

  // ---- phase 3: conv2 5x5 s2 16->16, leaky. px x co-half (242) ----
  if (tid < 242) {
    int half = tid & 1, p = tid >> 1;
    int oh = p / 11, ow = p - oh * 11;
    int ih0 = oh * 2, iw0 = ow * 2;
    ull acc[4] = {0ULL, 0ULL, 0ULL, 0ULL};
    const float* w2t = sm + OFF_W2T;
    const float* sact = sm + OFF_ACT26;
    for (int ci = 0; ci < 16; ci++) {
      const float* irow = sact + ci * 676;
#pragma unroll
      for (int kh = 0; kh < 5; kh++) {
        const float* ir = irow + (ih0 + kh) * 26 + iw0;
#pragma unroll
        for (int kw = 0; kw < 5; kw++) {
          ull xx = pack2(ir[kw]);
          const ulonglong2* wq =
              (const ulonglong2*)(w2t + (ci * 25 + kh * 5 + kw) * 16 + half * 8);
          ulonglong2 q0 = wq[0], q1 = wq[1];
          ffma2(acc[0], xx, q0.x); ffma2(acc[1], xx, q0.y);
          ffma2(acc[2], xx, q1.x); ffma2(acc[3], xx, q1.y);
        }
      }
    }
    float* act11 = sm + OFF_ACT11;
    const float* sb2 = sm + OFF_SB2;
#pragma unroll
    for (int q = 0; q < 4; q++) {
      float2 v = unpack2(acc[q]);
      int co = half * 8 + 2 * q;
      act11[co * 121 + p]       = lrelu(v.x + sb2[co]);
      act11[(co + 1) * 121 + p] = lrelu(v.y + sb2[co + 1]);
    }
  }
  __syncthreads();

  // ---- phase 4: gaze11 in-place (176) ----
  if (tid < 176) {
    int c = tid / 11, h = tid - c * 11;
    float* row = sm + OFF_ACT11 + c * 121 + h * 11;
    const float* K = sm + OFF_K11;
    float a[11];
#pragma unroll
    for (int w = 0; w < 11; w++) a[w] = row[w];
    ull acc[6];
#pragma unroll
    for (int q = 0; q < 6; q++) acc[q] = 0ULL;
#pragma unroll
    for (int w = 0; w < 11; w++) {
      ull xx = pack2(a[w]);
      const ulonglong2* kr = (const ulonglong2*)(K + w * 12);
#pragma unroll
      for (int q = 0; q < 3; q++) {
        ulonglong2 kv = kr[q];
        ffma2(acc[2 * q], xx, kv.x);
        ffma2(acc[2 * q + 1], xx, kv.y);
      }
    }
#pragma unroll
    for (int q = 0; q < 5; q++) {
      float2 v = unpack2(acc[q]);
      row[2 * q] = v.x; row[2 * q + 1] = v.y;
    }
    row[10] = unpack2(acc[5]).x;
  }
  __syncthreads();

  // ---- phase 5: conv3 3x3 16->16, leaky. px x co-half (162) ----
  if (tid < 162) {
    int half = tid & 1, p = tid >> 1;
    int oh = p / 9, ow = p - oh * 9;
    ull acc[4] = {0ULL, 0ULL, 0ULL, 0ULL};
    const float* w3t = sm + OFF_W3T;
    const float* act11 = sm + OFF_ACT11;
    for (int ci = 0; ci < 16; ci++) {
      const float* irow = act11 + ci * 121;
#pragma unroll
      for (int kh = 0; kh < 3; kh++) {
        const float* ir = irow + (oh + kh) * 11 + ow;
#pragma unroll
        for (int kw = 0; kw < 3; kw++) {
          ull xx = pack2(ir[kw]);
          const ulonglong2* wq =
              (const ulonglong2*)(w3t + (ci * 9 + kh * 3 + kw) * 16 + half * 8);
          ulonglong2 q0 = wq[0], q1 = wq[1];
          ffma2(acc[0], xx, q0.x); ffma2(acc[1], xx, q0.y);
          ffma2(acc[2], xx, q1.x); ffma2(acc[3], xx, q1.y);
        }
      }
    }
    float* act9 = sm + OFF_ACT9;
    const float* sb3 = sm + OFF_SB3;
#pragma unroll
    for (int q = 0; q < 4; q++) {
      float2 v = unpack2(acc[q]);
      int co = half * 8 + 2 * q;
      act9[co * 81 + p]       = lrelu(v.x + sb3[co]);
      act9[(co + 1) * 81 + p] = lrelu(v.y + sb3[co + 1]);
    }
  }
  __syncthreads();

  // ---- phase 6: conv4 3x3 16->16, leaky -> g_xf + cm. px x co-half (98) ----
  if (tid < 98) {
    int half = tid & 1, p = tid >> 1;
    int oh = p / 7, ow = p - oh * 7;
    ull acc[4] = {0ULL, 0ULL, 0ULL, 0ULL};
    const float* w4t = sm + OFF_W4T;
    const float* act9 = sm + OFF_ACT9;
    for (int ci = 0; ci < 16; ci++) {
      const float* irow = act9 + ci * 81;
#pragma unroll
      for (int kh = 0; kh < 3; kh++) {
        const float* ir = irow + (oh + kh) * 9 + ow;
#pragma unroll
        for (int kw = 0; kw < 3; kw++) {
          ull xx = pack2(ir[kw]);
          const ulonglong2* wq =
              (const ulonglong2*)(w4t + (ci * 9 + kh * 3 + kw) * 16 + half * 8);
          ulonglong2 q0 = wq[0], q1 = wq[1];
          ffma2(acc[0], xx, q0.x); ffma2(acc[1], xx, q0.y);
          ffma2(acc[2], xx, q1.x); ffma2(acc[3], xx, q1.y);
        }
      }
    }
    const float* sb4 = sm + OFF_SB4;
    float* xp = g_xf + (size_t)n * 784 + p;
    float cs = 0.f;
#pragma unroll
    for (int q = 0; q < 4; q++) {
      float2 v = unpack2(acc[q]);
      int co = half * 8 + 2 * q;
      float v0 = lrelu(v.x + sb4[co]);
      float v1 = lrelu(v.y + sb4[co + 1]);
      xp[co * 49] = v0;
      xp[(co + 1) * 49] = v1;
      cs += v0 + v1;
    }
    sm[OFF_SCM + tid] = cs;
  }
  __syncthreads();
  if (tid < 49)
    g_cm[(size_t)n * 49 + tid] = sm[OFF_SCM + 2 * tid] + sm[OFF_SCM + 2 * tid + 1];
}

// ---------------- fc ----------------
__global__ __launch_bounds__(256) void k_fc(const float* __restrict__ w1,
                                            const float* __restrict__ b1,
                                            const float* __restrict__ w2,
                                            const float* __restrict__ b2) {
  __shared__ float As[64][17];
  __shared__ float Bs[16][68];
  __shared__ float prs[16][64];
  int tid = threadIdx.x;
  int s0 = blockIdx.x * 64;
  int sg = tid >> 4, jg = tid & 15;
  float acc[4][4];
#pragma unroll
  for (int i = 0; i < 4; i++)
#pragma unroll
    for (int u = 0; u < 4; u++) acc[i][u] = 0.f;
  for (int k0 = 0; k0 < 784; k0 += 16) {
    for (int i = tid; i < 1024; i += 256) {
      int s = i >> 4, kk = i & 15;
      As[s][kk] = g_xf[(size_t)(s0 + s) * 784 + k0 + kk];
    }
    for (int i = tid; i < 1024; i += 256) {
      int j = i >> 4, kk = i & 15;
      Bs[kk][j] = w1[j * 784 + k0 + kk];
    }
    __syncthreads();
#pragma unroll
    for (int kk = 0; kk < 16; kk++) {
      float av[4], bv[4];
#pragma unroll
      for (int i = 0; i < 4; i++) av[i] = As[sg * 4 + i][kk];
#pragma unroll
      for (int u = 0; u < 4; u++) bv[u] = Bs[kk][jg * 4 + u];
#pragma unroll
      for (int i = 0; i < 4; i++)
#pragma unroll
        for (int u = 0; u < 4; u++) acc[i][u] += av[i] * bv[u];
    }
    __syncthreads();
  }
#pragma unroll
  for (int i = 0; i < 4; i++) {
    float pr = 0.f;
#pragma unroll
    for (int u = 0; u < 4; u++) {
      int j = jg * 4 + u;
      float h = acc[i][u] + b1[j];
      h = lrelu(h);
      pr += h * w2[j];
    }
    prs[jg][sg * 4 + i] = pr;
  }
  __syncthreads();
  if (tid < 64) {
    float s = 0.f;
#pragma unroll
    for (int j = 0; j < 16; j++) s += prs[j][tid];
    g_r[s0 + tid] = s + b2[0];
  }
}

__global__ void k_reduce_r(float* __restrict__ out) {
  __shared__ float sab[64];
  int tid = threadIdx.x;
  int traj = tid >> 5, b = tid & 31;
  float s = 0.f, sa = 0.f;
  for (int t = 0; t < 64; t++) {
    float r = g_r[traj * 2048 + t * 32 + b];
    s += r;
    sa += fabsf(r);
  }
  out[tid] = s;
  sab[tid] = sa;
  __syncthreads();
  if (tid < 32) out[64 + tid] = sab[tid] + sab[32 + tid];
}

__global__ __launch_bounds__(256) void k_cmnorm(float* __restrict__ out) {
  __shared__ float sv[1568];
  __shared__ float smn[8], smx[8];
  __shared__ float fmn, fmx;
  int idx = blockIdx.x;
  int traj = idx >> 6, t = idx & 63;
  int tid = threadIdx.x;
  const float* base = g_cm + ((size_t)(traj * 2048 + t * 32)) * 49;
  float mn = 1e30f, mx = -1e30f;
  for (int i = tid; i < 1568; i += 256) {
    float v = base[i];
    sv[i] = v;
    mn = fminf(mn, v);
    mx = fmaxf(mx, v);
  }
#pragma unroll
  for (int o = 16; o; o >>= 1) {
    mn = fminf(mn, __shfl_xor_sync(0xffffffffu, mn, o));
    mx = fmaxf(mx, __shfl_xor_sync(0xffffffffu, mx, o));
  }
  if ((tid & 31) == 0) { smn[tid >> 5] = mn; smx[tid >> 5] = mx; }
  __syncthreads();
  if (tid == 0) {
    float a = smn[0], bb = smx[0];
    for (int i = 1; i < 8; i++) { a = fminf(a, smn[i]); bb = fmaxf(bb, smx[i]); }
    fmn = a; fmx = bb;
  }
  __syncthreads();
  float m = fmn, inv = 1.f / (fmx - m);
  float* o = out + 96 + (size_t)traj * 100352 + (size_t)t * 1568;
  for (int i = tid; i < 1568; i += 256) o[i] = (sv[i] - m) * inv;
}

extern "C" void kernel_launch(void* const* d_in, const int* in_sizes, int n_in,
                              void* d_out, int out_size) {
  const float* ti   = (const float*)d_in[0];
  const float* tj   = (const float*)d_in[1];
  const float* g26i = (const float*)d_in[2];
  const float* g11i = (const float*)d_in[3];
  const float* g26j = (const float*)d_in[4];
  const float* g11j = (const float*)d_in[5];
  const float* w1 = (const float*)d_in[6];  const float* b1 = (const float*)d_in[7];
  const float* w2 = (const float*)d_in[8];  const float* b2 = (const float*)d_in[9];
  const float* w3 = (const float*)d_in[10]; const float* b3 = (const float*)d_in[11];
  const float* w4 = (const float*)d_in[12]; const float* b4 = (const float*)d_in[13];
  const float* f1w = (const float*)d_in[14]; const float* f1b = (const float*)d_in[15];
  const float* f2w = (const float*)d_in[16]; const float* f2b = (const float*)d_in[17];
  float* out = (float*)d_out;

  cudaFuncSetAttribute(k_net, cudaFuncAttributeMaxDynamicSharedMemorySize,
                       SMEM_FLOATS * 4);

  k_prep<<<4, 512>>>(w1, w2, w3, w4);
  k_net<<<NTOT, TPB, SMEM_FLOATS * 4>>>(ti, tj, g26i, g26j, g11i, g11j,
                                        b1, b2, b3, b4);
  k_fc<<<NTOT / 64, 256>>>(f1w, f1b, f2w, f2b);
  k_reduce_r<<<1, 64>>>(out);
  k_cmnorm<<<128, 256>>>(out);
}

// round 10
// speedup vs baseline: 1.3087x; 1.1232x over previous
#include <cuda_runtime.h>
#include <math.h>

#define NPT 2048
#define NTOT 4096
#define TPB 352
typedef unsigned long long ull;

__device__ float g_xf[(size_t)NTOT * 784];
__device__ float g_cm[(size_t)NTOT * 49];
__device__ float g_r[NTOT];
__device__ __align__(16) float g_w2t[6400];
__device__ __align__(16) float g_w3t[2304];
__device__ __align__(16) float g_w4t[2304];
// conv1 weights, bf16-split, mma-fragment-ready: [s(13)][nt(2)][lane(32)] -> {b0h,b1h,b0l,b1l}
__device__ uint4 g_w1frag[832];

__device__ __forceinline__ float lrelu(float v) { return v >= 0.f ? v : 0.01f * v; }
__device__ __forceinline__ ull pack2(float x) {
  ull r; asm("mov.b64 %0,{%1,%1};" : "=l"(r) : "f"(x)); return r;
}
__device__ __forceinline__ void ffma2(ull& d, ull a, ull b) {
  asm("fma.rn.f32x2 %0,%1,%2,%0;" : "+l"(d) : "l"(a), "l"(b));
}
__device__ __forceinline__ float2 unpack2(ull v) {
  float2 r; asm("mov.b64 {%0,%1},%2;" : "=f"(r.x), "=f"(r.y) : "l"(v)); return r;
}
// bf16x2 pack: low half = lo_elem, high half = hi_elem
__device__ __forceinline__ unsigned bf2pack(float hi_elem, float lo_elem) {
  unsigned u; asm("cvt.rn.bf16x2.f32 %0, %1, %2;" : "=r"(u) : "f"(hi_elem), "f"(lo_elem));
  return u;
}
#define MMA_BF16(d0,d1,d2,d3,a0,a1,a2,a3,b0,b1) \
  asm("mma.sync.aligned.m16n8k16.row.col.f32.bf16.bf16.f32 " \
      "{%0,%1,%2,%3},{%4,%5,%6,%7},{%8,%9},{%0,%1,%2,%3};" \
      : "+f"(d0),"+f"(d1),"+f"(d2),"+f"(d3) \
      : "r"(a0),"r"(a1),"r"(a2),"r"(a3),"r"(b0),"r"(b1))

// smem float offsets (total 26078 floats = 104312 B -> 2 blocks/SM)
#define OFF_ACT26 0
#define OFF_W2T   10816
#define OFF_W3T   17216
#define OFF_W4T   19520
#define OFF_K26   21824
#define OFF_K11   22552
#define OFF_ACT11 22684
#define OFF_ACT9  24620
#define OFF_SB1   25916
#define OFF_SB2   25932
#define OFF_SB3   25948
#define OFF_SB4   25964
#define OFF_SCM   25980
#define SMEM_FLOATS 26078

__device__ __forceinline__ int koff(int k) {
  int ci = k & 3, t = k >> 2;
  int kw = t % 7, kh = t / 7;
  return kh * 336 + kw * 4 + ci;  // float offset within 84x84x4 window
}

// ---------------- one-time weight prep ----------------
__global__ void k_prep(const float* __restrict__ w1, const float* __restrict__ w2,
                       const float* __restrict__ w3, const float* __restrict__ w4) {
  int tid = blockIdx.x * blockDim.x + threadIdx.x;
  for (int i = tid; i < 6400; i += 2048) g_w2t[i] = w2[(i & 15) * 400 + (i >> 4)];
  for (int i = tid; i < 2304; i += 2048) g_w3t[i] = w3[(i & 15) * 144 + (i >> 4)];
  for (int i = tid; i < 2304; i += 2048) g_w4t[i] = w4[(i & 15) * 144 + (i >> 4)];
  // conv1 fragment build
  for (int idx = tid; idx < 832; idx += 2048) {
    int lane = idx & 31, sn = idx >> 5;
    int s = sn >> 1, nt = sn & 1;
    int tig = lane & 3, gq = lane >> 2;
    int co = nt * 8 + gq;
    float wv[4]; // k0,k0+1,k8,k8+1
    int k0 = s * 16 + tig * 2;
#pragma unroll
    for (int e = 0; e < 4; e++) {
      int k = k0 + (e >> 1) * 8 + (e & 1);
      float w = 0.f;
      if (k < 196) {
        int ci = k & 3, t = k >> 2, kw = t % 7, kh = t / 7;
        w = w1[co * 196 + ci * 49 + kh * 7 + kw];
      }
      wv[e] = w;
    }
    unsigned hb[4], hi_pairs[2], lo_pairs[2];
    float lo[4];
#pragma unroll
    for (int e = 0; e < 4; e++) {
      hb[e] = __float_as_uint(wv[e]) & 0xffff0000u;
      lo[e] = wv[e] - __uint_as_float(hb[e]);
    }
    hi_pairs[0] = (hb[0] >> 16) | (hb[1] & 0xffff0000u);
    hi_pairs[1] = (hb[2] >> 16) | (hb[3] & 0xffff0000u);
    lo_pairs[0] = bf2pack(lo[1], lo[0]);
    lo_pairs[1] = bf2pack(lo[3], lo[2]);
    uint4 out;
    out.x = hi_pairs[0]; out.y = hi_pairs[1];
    out.z = lo_pairs[0]; out.w = lo_pairs[1];
    g_w1frag[idx] = out;
  }
}

__global__ __launch_bounds__(TPB, 2) void k_net(
    const float* __restrict__ ti, const float* __restrict__ tj,
    const float* __restrict__ g26i, const float* __restrict__ g26j,
    const float* __restrict__ g11i, const float* __restrict__ g11j,
    const float* __restrict__ b1, const float* __restrict__ b2,
    const float* __restrict__ b3, const float* __restrict__ b4) {
  extern __shared__ float sm[];
  int n = blockIdx.x, tid = threadIdx.x;
  const float sc = 1.0f / (0.7f * 0.3f);

  const float* x   = (n < NPT) ? ti   + (size_t)n * 28224 : tj   + (size_t)(n - NPT) * 28224;
  const float* g26 = (n < NPT) ? g26i + (size_t)n * 676   : g26j + (size_t)(n - NPT) * 676;
  const float* g11 = (n < NPT) ? g11i + (size_t)n * 121   : g11j + (size_t)(n - NPT) * 121;

  // ---- phase 0: weights + gaze kernels into smem ----
  for (int i = tid; i < 6400; i += TPB) sm[OFF_W2T + i] = g_w2t[i];
  for (int i = tid; i < 2304; i += TPB) sm[OFF_W3T + i] = g_w3t[i];
  for (int i = tid; i < 2304; i += TPB) sm[OFF_W4T + i] = g_w4t[i];
  for (int i = tid; i < 728; i += TPB) {
    int wdx = i / 28, k = i - wdx * 28;
    sm[OFF_K26 + i] = (k < 26) ? (g26[wdx * 26 + k] - 0.3f) * sc : 0.f;
  }
  for (int i = tid; i < 132; i += TPB) {
    int wdx = i / 12, k = i - wdx * 12;
    sm[OFF_K11 + i] = (k < 11) ? (g11[wdx * 11 + k] - 0.3f) * sc : 0.f;
  }
  if (tid < 16) {
    sm[OFF_SB1 + tid] = b1[tid]; sm[OFF_SB2 + tid] = b2[tid];
    sm[OFF_SB3 + tid] = b3[tid]; sm[OFF_SB4 + tid] = b4[tid];
  }
  __syncthreads();

  // ---- phase 1: conv1 via mma.sync bf16-split (M=676,N=16,K=196) ----
  {
    int warp = tid >> 5, lane = tid & 31;
    int g = lane >> 2, tig = lane & 3;
    const float* sb1 = sm + OFF_SB1;
    float* sact = sm + OFF_ACT26;
#pragma unroll
    for (int pass = 0; pass < 2; pass++) {
      int t0 = pass * 22 + 2 * warp;  // tiles t0, t0+1 (t may be >=43 -> fully guarded)
      float d[2][2][4];
#pragma unroll
      for (int t = 0; t < 2; t++)
#pragma unroll
        for (int nt = 0; nt < 2; nt++)
#pragma unroll
          for (int e = 0; e < 4; e++) d[t][nt][e] = 0.f;
      // row bases: px for rows g, g+8 of each tile
      int px[2][2], base[2][2];
      bool ok[2][2];
#pragma unroll
      for (int t = 0; t < 2; t++) {
        px[t][0] = (t0 + t) * 16 + g;
        px[t][1] = px[t][0] + 8;
#pragma unroll
        for (int r = 0; r < 2; r++) {
          int p = px[t][r];
          ok[t][r] = p < 676;
          int oh = p / 26, ow = p - oh * 26;
          base[t][r] = ok[t][r] ? (oh * 1008 + ow * 12) : 0;
        }
      }
      for (int s = 0; s < 13; s++) {
        int k0 = s * 16 + tig * 2;
        int k8 = k0 + 8;
        bool k01ok = k0 < 196, k89ok = k8 < 196;
        int off01 = koff(k0 < 196 ? k0 : 0);
        int off89 = koff(k8 < 196 ? k8 : 0);
        uint4 B0 = g_w1frag[(s * 2 + 0) * 32 + lane];
        uint4 B1 = g_w1frag[(s * 2 + 1) * 32 + lane];
#pragma unroll
        for (int t = 0; t < 2; t++) {
          float2 v[4];  // a0(r0,c01) a1(r1,c01) a2(r0,c89) a3(r1,c89)
          v[0] = (ok[t][0] && k01ok) ? *(const float2*)(x + base[t][0] + off01) : make_float2(0.f, 0.f);
          v[1] = (ok[t][1] && k01ok) ? *(const float2*)(x + base[t][1] + off01) : make_float2(0.f, 0.f);
          v[2] = (ok[t][0] && k89ok) ? *(const float2*)(x + base[t][0] + off89) : make_float2(0.f, 0.f);
          v[3] = (ok[t][1] && k89ok) ? *(const float2*)(x + base[t][1] + off89) : make_float2(0.f, 0.f);
          unsigned ah[4], al[4];
#pragma unroll
          for (int q = 0; q < 4; q++) {
            unsigned xb = __float_as_uint(v[q].x), yb = __float_as_uint(v[q].y);
            ah[q] = __byte_perm(xb, yb, 0x7632);  // {y.hi16, x.hi16} -> low half = x
            float lx = v[q].x - __uint_as_float(xb & 0xffff0000u);
            float ly = v[q].y - __uint_as_float(yb & 0xffff0000u);
            al[q] = bf2pack(ly, lx);
          }
          MMA_BF16(d[t][0][0], d[t][0][1], d[t][0][2], d[t][0][3],
                   ah[0], ah[1], ah[2], ah[3], B0.x, B0.y);
          MMA_BF16(d[t][0][0], d[t][0][1], d[t][0][2], d[t][0][3],
                   ah[0], ah[1], ah[2], ah[3], B0.z, B0.w);
          MMA_BF16(d[t][0][0], d[t][0][1], d[t][0][2], d[t][0][3],
                   al[0], al[1], al[2], al[3], B0.x, B0.y);
          MMA_BF16(d[t][1][0], d[t][1][1], d[t][1][2], d[t][1][3],
                   ah[0], ah[1], ah[2], ah[3], B1.x, B1.y);
          MMA_BF16(d[t][1][0], d[t][1][1], d[t][1][2], d[t][1][3],
                   ah[0], ah[1], ah[2], ah[3], B1.z, B1.w);
          MMA_BF16(d[t][1][0], d[t][1][1], d[t][1][2], d[t][1][3],
                   al[0], al[1], al[2], al[3], B1.x, B1.y);
        }
      }
      // epilogue: D(row, col): d0 (g, tig*2), d1 (g, tig*2+1), d2 (g+8, ...), d3
#pragma unroll
      for (int t = 0; t < 2; t++)
#pragma unroll
        for (int nt = 0; nt < 2; nt++) {
          int co0 = nt * 8 + tig * 2, co1 = co0 + 1;
          if (ok[t][0]) {
            sact[co0 * 676 + px[t][0]] = lrelu(d[t][nt][0] + sb1[co0]);
            sact[co1 * 676 + px[t][0]] = lrelu(d[t][nt][1] + sb1[co1]);
          }
          if (ok[t][1]) {
            sact[co0 * 676 + px[t][1]] = lrelu(d[t][nt][2] + sb1[co0]);
            sact[co1 * 676 + px[t][1]] = lrelu(d[t][nt][3] + sb1[co1]);
          }
        }
    }
  }
  __syncthreads();

  // ---- phase 2: gaze26 in-place (row per thread, 416 items) ----
  for (int i = tid; i < 416; i += TPB) {
    int c = i / 26, h = i - c * 26;
    float* row = sm + OFF_ACT26 + c * 676 + h * 26;
    const float* K = sm + OFF_K26;
    float a[26];
#pragma unroll
    for (int w = 0; w < 26; w++) a[w] = row[w];
    ull acc[14];
#pragma unroll
    for (int q = 0; q < 14; q++) acc[q] = 0ULL;
#pragma unroll
    for (int w = 0; w < 26; w++) {
      ull xx = pack2(a[w]);
      const ulonglong2* kr = (const ulonglong2*)(K + w * 28);
#pragma unroll
      for (int q = 0; q < 7; q++) {
        ulonglong2 kv = kr[q];
        ffma2(acc[2 * q], xx, kv.x);
        ffma2(acc[2 * q + 1], xx, kv.y);
      }
    }
#pragma unroll
    for (int q = 0; q < 13; q++) {
      float2 v = unpack2(acc[q]);
      row[2 * q] = v.x; row[2 * q + 1] = v.y;
    }
  }
  __syncthreads();

  // ---- phase 3: conv2 5x5 s2 16->16, leaky. px x co-half (242) ----
  if (tid < 242) {
    int half = tid & 1, p = tid >> 1;
    int oh = p / 11, ow = p - oh * 11;
    int ih0 = oh * 2, iw0 = ow * 2;
    ull acc[4] = {0ULL, 0ULL, 0ULL, 0ULL};
    const float* w2t = sm + OFF_W2T;
    const float* sact = sm + OFF_ACT26;
    for (int ci = 0; ci < 16; ci++) {
      const float* irow = sact + ci * 676;
#pragma unroll
      for (int kh = 0; kh < 5; kh++) {
        const float* ir = irow + (ih0 + kh) * 26 + iw0;
#pragma unroll
        for (int kw = 0; kw < 5; kw++) {
          ull xx = pack2(ir[kw]);
          const ulonglong2* wq =
              (const ulonglong2*)(w2t + (ci * 25 + kh * 5 + kw) * 16 + half * 8);
          ulonglong2 q0 = wq[0], q1 = wq[1];
          ffma2(acc[0], xx, q0.x); ffma2(acc[1], xx, q0.y);
          ffma2(acc[2], xx, q1.x); ffma2(acc[3], xx, q1.y);
        }
      }
    }
    float* act11 = sm + OFF_ACT11;
    const float* sb2 = sm + OFF_SB2;
#pragma unroll
    for (int q = 0; q < 4; q++) {
      float2 v = unpack2(acc[q]);
      int co = half * 8 + 2 * q;
      act11[co * 121 + p]       = lrelu(v.x + sb2[co]);
      act11[(co + 1) * 121 + p] = lrelu(v.y + sb2[co + 1]);
    }
  }
  __syncthreads();

  // ---- phase 4: gaze11 in-place (176) ----
  if (tid < 176) {
    int c = tid / 11, h = tid - c * 11;
    float* row = sm + OFF_ACT11 + c * 121 + h * 11;
    const float* K = sm + OFF_K11;
    float a[11];
#pragma unroll
    for (int w = 0; w < 11; w++) a[w] = row[w];
    ull acc[6];
#pragma unroll
    for (int q = 0; q < 6; q++) acc[q] = 0ULL;
#pragma unroll
    for (int w = 0; w < 11; w++) {
      ull xx = pack2(a[w]);
      const ulonglong2* kr = (const ulonglong2*)(K + w * 12);
#pragma unroll
      for (int q = 0; q < 3; q++) {
        ulonglong2 kv = kr[q];
        ffma2(acc[2 * q], xx, kv.x);
        ffma2(acc[2 * q + 1], xx, kv.y);
      }
    }
#pragma unroll
    for (int q = 0; q < 5; q++) {
      float2 v = unpack2(acc[q]);
      row[2 * q] = v.x; row[2 * q + 1] = v.y;
    }
    row[10] = unpack2(acc[5]).x;
  }
  __syncthreads();

  // ---- phase 5: conv3 3x3 16->16, leaky. px x co-half (162) ----
  if (tid < 162) {
    int half = tid & 1, p = tid >> 1;
    int oh = p / 9, ow = p - oh * 9;
    ull acc[4] = {0ULL, 0ULL, 0ULL, 0ULL};
    const float* w3t = sm + OFF_W3T;
    const float* act11 = sm + OFF_ACT11;
    for (int ci = 0; ci < 16; ci++) {
      const float* irow = act11 + ci * 121;
#pragma unroll
      for (int kh = 0; kh < 3; kh++) {
        const float* ir = irow + (oh + kh) * 11 + ow;
#pragma unroll
        for (int kw = 0; kw < 3; kw++) {
          ull xx = pack2(ir[kw]);
          const ulonglong2* wq =
              (const ulonglong2*)(w3t + (ci * 9 + kh * 3 + kw) * 16 + half * 8);
          ulonglong2 q0 = wq[0], q1 = wq[1];
          ffma2(acc[0], xx, q0.x); ffma2(acc[1], xx, q0.y);
          ffma2(acc[2], xx, q1.x); ffma2(acc[3], xx, q1.y);
        }
      }
    }
    float* act9 = sm + OFF_ACT9;
    const float* sb3 = sm + OFF_SB3;
#pragma unroll
    for (int q = 0; q < 4; q++) {
      float2 v = unpack2(acc[q]);
      int co = half * 8 + 2 * q;
      act9[co * 81 + p]       = lrelu(v.x + sb3[co]);
      act9[(co + 1) * 81 + p] = lrelu(v.y + sb3[co + 1]);
    }
  }
  __syncthreads();

  // ---- phase 6: conv4 3x3 16->16, leaky -> g_xf + cm. px x co-half (98) ----
  if (tid < 98) {
    int half = tid & 1, p = tid >> 1;
    int oh = p / 7, ow = p - oh * 7;
    ull acc[4] = {0ULL, 0ULL, 0ULL, 0ULL};
    const float* w4t = sm + OFF_W4T;
    const float* act9 = sm + OFF_ACT9;
    for (int ci = 0; ci < 16; ci++) {
      const float* irow = act9 + ci * 81;
#pragma unroll
      for (int kh = 0; kh < 3; kh++) {
        const float* ir = irow + (oh + kh) * 9 + ow;
#pragma unroll
        for (int kw = 0; kw < 3; kw++) {
          ull xx = pack2(ir[kw]);
          const ulonglong2* wq =
              (const ulonglong2*)(w4t + (ci * 9 + kh * 3 + kw) * 16 + half * 8);
          ulonglong2 q0 = wq[0], q1 = wq[1];
          ffma2(acc[0], xx, q0.x); ffma2(acc[1], xx, q0.y);
          ffma2(acc[2], xx, q1.x); ffma2(acc[3], xx, q1.y);
        }
      }
    }
    const float* sb4 = sm + OFF_SB4;
    float* xp = g_xf + (size_t)n * 784 + p;
    float cs = 0.f;
#pragma unroll
    for (int q = 0; q < 4; q++) {
      float2 v = unpack2(acc[q]);
      int co = half * 8 + 2 * q;
      float v0 = lrelu(v.x + sb4[co]);
      float v1 = lrelu(v.y + sb4[co + 1]);
      xp[co * 49] = v0;
      xp[(co + 1) * 49] = v1;
      cs += v0 + v1;
    }
    sm[OFF_SCM + tid] = cs;
  }
  __syncthreads();
  if (tid < 49)
    g_cm[(size_t)n * 49 + tid] = sm[OFF_SCM + 2 * tid] + sm[OFF_SCM + 2 * tid + 1];
}

// ---------------- fc ----------------
__global__ __launch_bounds__(256) void k_fc(const float* __restrict__ w1,
                                            const float* __restrict__ b1,
                                            const float* __restrict__ w2,
                                            const float* __restrict__ b2) {
  __shared__ float As[64][17];
  __shared__ float Bs[16][68];
  __shared__ float prs[16][64];
  int tid = threadIdx.x;
  int s0 = blockIdx.x * 64;
  int sg = tid >> 4, jg = tid & 15;
  float acc[4][4];
#pragma unroll
  for (int i = 0; i < 4; i++)
#pragma unroll
    for (int u = 0; u < 4; u++) acc[i][u] = 0.f;
  for (int k0 = 0; k0 < 784; k0 += 16) {
    for (int i = tid; i < 1024; i += 256) {
      int s = i >> 4, kk = i & 15;
      As[s][kk] = g_xf[(size_t)(s0 + s) * 784 + k0 + kk];
    }
    for (int i = tid; i < 1024; i += 256) {
      int j = i >> 4, kk = i & 15;
      Bs[kk][j] = w1[j * 784 + k0 + kk];
    }
    __syncthreads();
#pragma unroll
    for (int kk = 0; kk < 16; kk++) {
      float av[4], bv[4];
#pragma unroll
      for (int i = 0; i < 4; i++) av[i] = As[sg * 4 + i][kk];
#pragma unroll
      for (int u = 0; u < 4; u++) bv[u] = Bs[kk][jg * 4 + u];
#pragma unroll
      for (int i = 0; i < 4; i++)
#pragma unroll
        for (int u = 0; u < 4; u++) acc[i][u] += av[i] * bv[u];
    }
    __syncthreads();
  }
#pragma unroll
  for (int i = 0; i < 4; i++) {
    float pr = 0.f;
#pragma unroll
    for (int u = 0; u < 4; u++) {
      int j = jg * 4 + u;
      float h = acc[i][u] + b1[j];
      h = lrelu(h);
      pr += h * w2[j];
    }
    prs[jg][sg * 4 + i] = pr;
  }
  __syncthreads();
  if (tid < 64) {
    float s = 0.f;
#pragma unroll
    for (int j = 0; j < 16; j++) s += prs[j][tid];
    g_r[s0 + tid] = s + b2[0];
  }
}

__global__ void k_reduce_r(float* __restrict__ out) {
  __shared__ float sab[64];
  int tid = threadIdx.x;
  int traj = tid >> 5, b = tid & 31;
  float s = 0.f, sa = 0.f;
  for (int t = 0; t < 64; t++) {
    float r = g_r[traj * 2048 + t * 32 + b];
    s += r;
    sa += fabsf(r);
  }
  out[tid] = s;
  sab[tid] = sa;
  __syncthreads();
  if (tid < 32) out[64 + tid] = sab[tid] + sab[32 + tid];
}

__global__ __launch_bounds__(256) void k_cmnorm(float* __restrict__ out) {
  __shared__ float sv[1568];
  __shared__ float smn[8], smx[8];
  __shared__ float fmn, fmx;
  int idx = blockIdx.x;
  int traj = idx >> 6, t = idx & 63;
  int tid = threadIdx.x;
  const float* base = g_cm + ((size_t)(traj * 2048 + t * 32)) * 49;
  float mn = 1e30f, mx = -1e30f;
  for (int i = tid; i < 1568; i += 256) {
    float v = base[i];
    sv[i] = v;
    mn = fminf(mn, v);
    mx = fmaxf(mx, v);
  }
#pragma unroll
  for (int o = 16; o; o >>= 1) {
    mn = fminf(mn, __shfl_xor_sync(0xffffffffu, mn, o));
    mx = fmaxf(mx, __shfl_xor_sync(0xffffffffu, mx, o));
  }
  if ((tid & 31) == 0) { smn[tid >> 5] = mn; smx[tid >> 5] = mx; }
  __syncthreads();
  if (tid == 0) {
    float a = smn[0], bb = smx[0];
    for (int i = 1; i < 8; i++) { a = fminf(a, smn[i]); bb = fmaxf(bb, smx[i]); }
    fmn = a; fmx = bb;
  }
  __syncthreads();
  float m = fmn, inv = 1.f / (fmx - m);
  float* o = out + 96 + (size_t)traj * 100352 + (size_t)t * 1568;
  for (int i = tid; i < 1568; i += 256) o[i] = (sv[i] - m) * inv;
}

extern "C" void kernel_launch(void* const* d_in, const int* in_sizes, int n_in,
                              void* d_out, int out_size) {
  const float* ti   = (const float*)d_in[0];
  const float* tj   = (const float*)d_in[1];
  const float* g26i = (const float*)d_in[2];
  const float* g11i = (const float*)d_in[3];
  const float* g26j = (const float*)d_in[4];
  const float* g11j = (const float*)d_in[5];
  const float* w1 = (const float*)d_in[6];  const float* b1 = (const float*)d_in[7];
  const float* w2 = (const float*)d_in[8];  const float* b2 = (const float*)d_in[9];
  const float* w3 = (const float*)d_in[10]; const float* b3 = (const float*)d_in[11];
  const float* w4 = (const float*)d_in[12]; const float* b4 = (const float*)d_in[13];
  const float* f1w = (const float*)d_in[14]; const float* f1b = (const float*)d_in[15];
  const float* f2w = (const float*)d_in[16]; const float* f2b = (const float*)d_in[17];
  float* out = (float*)d_out;

  cudaFuncSetAttribute(k_net, cudaFuncAttributeMaxDynamicSharedMemorySize,
                       SMEM_FLOATS * 4);

  k_prep<<<4, 512>>>(w1, w2, w3, w4);
  k_net<<<NTOT, TPB, SMEM_FLOATS * 4>>>(ti, tj, g26i, g26j, g11i, g11j,
                                        b1, b2, b3, b4);
  k_fc<<<NTOT / 64, 256>>>(f1w, f1b, f2w, f2b);
  k_reduce_r<<<1, 64>>>(out);
  k_cmnorm<<<128, 256>>>(out);
}

// round 11
// speedup vs baseline: 1.3145x; 1.0045x over previous
#include <cuda_runtime.h>
#include <math.h>

#define NPT 2048
#define NTOT 4096
#define TPB 352
typedef unsigned long long ull;

__device__ float g_xf[(size_t)NTOT * 784];
__device__ float g_cm[(size_t)NTOT * 49];
__device__ float g_r[NTOT];
__device__ __align__(16) float g_w2t[6400];
__device__ __align__(16) float g_w3t[2304];
__device__ __align__(16) float g_w4t[2304];
// conv1 weights, bf16-split, mma-fragment-ready: [s(13)][nt(2)][lane(32)] -> {b0h,b1h,b0l,b1l}
__device__ uint4 g_w1frag[832];

__device__ __forceinline__ float lrelu(float v) { return v >= 0.f ? v : 0.01f * v; }
__device__ __forceinline__ ull pack2(float x) {
  ull r; asm("mov.b64 %0,{%1,%1};" : "=l"(r) : "f"(x)); return r;
}
__device__ __forceinline__ void ffma2(ull& d, ull a, ull b) {
  asm("fma.rn.f32x2 %0,%1,%2,%0;" : "+l"(d) : "l"(a), "l"(b));
}
__device__ __forceinline__ float2 unpack2(ull v) {
  float2 r; asm("mov.b64 {%0,%1},%2;" : "=f"(r.x), "=f"(r.y) : "l"(v)); return r;
}
// bf16x2 pack: low half = lo_elem, high half = hi_elem
__device__ __forceinline__ unsigned bf2pack(float hi_elem, float lo_elem) {
  unsigned u; asm("cvt.rn.bf16x2.f32 %0, %1, %2;" : "=r"(u) : "f"(hi_elem), "f"(lo_elem));
  return u;
}
#define MMA_BF16(d0,d1,d2,d3,a0,a1,a2,a3,b0,b1) \
  asm("mma.sync.aligned.m16n8k16.row.col.f32.bf16.bf16.f32 " \
      "{%0,%1,%2,%3},{%4,%5,%6,%7},{%8,%9},{%0,%1,%2,%3};" \
      : "+f"(d0),"+f"(d1),"+f"(d2),"+f"(d3) \
      : "r"(a0),"r"(a1),"r"(a2),"r"(a3),"r"(b0),"r"(b1))

// smem float offsets (total 26078 floats = 104312 B -> 2 blocks/SM)
#define OFF_ACT26 0
#define OFF_W2T   10816
#define OFF_W3T   17216
#define OFF_W4T   19520
#define OFF_K26   21824
#define OFF_K11   22552
#define OFF_ACT11 22684
#define OFF_ACT9  24620
#define OFF_SB1   25916
#define OFF_SB2   25932
#define OFF_SB3   25948
#define OFF_SB4   25964
#define OFF_SCM   25980
#define SMEM_FLOATS 26078

__device__ __forceinline__ int koff(int k) {
  int ci = k & 3, t = k >> 2;
  int kw = t % 7, kh = t / 7;
  return kh * 336 + kw * 4 + ci;  // float offset within 84x84x4 window
}

// ---------------- one-time weight prep ----------------
__global__ void k_prep(const float* __restrict__ w1, const float* __restrict__ w2,
                       const float* __restrict__ w3, const float* __restrict__ w4) {
  int tid = blockIdx.x * blockDim.x + threadIdx.x;
  for (int i = tid; i < 6400; i += 2048) g_w2t[i] = w2[(i & 15) * 400 + (i >> 4)];
  for (int i = tid; i < 2304; i += 2048) g_w3t[i] = w3[(i & 15) * 144 + (i >> 4)];
  for (int i = tid; i < 2304; i += 2048) g_w4t[i] = w4[(i & 15) * 144 + (i >> 4)];
  // conv1 fragment build
  for (int idx = tid; idx < 832; idx += 2048) {
    int lane = idx & 31, sn = idx >> 5;
    int s = sn >> 1, nt = sn & 1;
    int tig = lane & 3, gq = lane >> 2;
    int co = nt * 8 + gq;
    float wv[4]; // k0,k0+1,k8,k8+1
    int k0 = s * 16 + tig * 2;
#pragma unroll
    for (int e = 0; e < 4; e++) {
      int k = k0 + (e >> 1) * 8 + (e & 1);
      float w = 0.f;
      if (k < 196) {
        int ci = k & 3, t = k >> 2, kw = t % 7, kh = t / 7;
        w = w1[co * 196 + ci * 49 + kh * 7 + kw];
      }
      wv[e] = w;
    }
    unsigned hb[4], hi_pairs[2], lo_pairs[2];
    float lo[4];
#pragma unroll
    for (int e = 0; e < 4; e++) {
      hb[e] = __float_as_uint(wv[e]) & 0xffff0000u;
      lo[e] = wv[e] - __uint_as_float(hb[e]);
    }
    hi_pairs[0] = (hb[0] >> 16) | (hb[1] & 0xffff0000u);
    hi_pairs[1] = (hb[2] >> 16) | (hb[3] & 0xffff0000u);
    lo_pairs[0] = bf2pack(lo[1], lo[0]);
    lo_pairs[1] = bf2pack(lo[3], lo[2]);
    uint4 out;
    out.x = hi_pairs[0]; out.y = hi_pairs[1];
    out.z = lo_pairs[0]; out.w = lo_pairs[1];
    g_w1frag[idx] = out;
  }
}

__global__ __launch_bounds__(TPB, 2) void k_net(
    const float* __restrict__ ti, const float* __restrict__ tj,
    const float* __restrict__ g26i, const float* __restrict__ g26j,
    const float* __restrict__ g11i, const float* __restrict__ g11j,
    const float* __restrict__ b1, const float* __restrict__ b2,
    const float* __restrict__ b3, const float* __restrict__ b4) {
  extern __shared__ float sm[];
  int n = blockIdx.x, tid = threadIdx.x;
  const float sc = 1.0f / (0.7f * 0.3f);

  const float* x   = (n < NPT) ? ti   + (size_t)n * 28224 : tj   + (size_t)(n - NPT) * 28224;
  const float* g26 = (n < NPT) ? g26i + (size_t)n * 676   : g26j + (size_t)(n - NPT) * 676;
  const float* g11 = (n < NPT) ? g11i + (size_t)n * 121   : g11j + (size_t)(n - NPT) * 121;

  // ---- phase 0: weights + gaze kernels into smem ----
  for (int i = tid; i < 6400; i += TPB) sm[OFF_W2T + i] = g_w2t[i];
  for (int i = tid; i < 2304; i += TPB) sm[OFF_W3T + i] = g_w3t[i];
  for (int i = tid; i < 2304; i += TPB) sm[OFF_W4T + i] = g_w4t[i];
  for (int i = tid; i < 728; i += TPB) {
    int wdx = i / 28, k = i - wdx * 28;
    sm[OFF_K26 + i] = (k < 26) ? (g26[wdx * 26 + k] - 0.3f) * sc : 0.f;
  }
  for (int i = tid; i < 132; i += TPB) {
    int wdx = i / 12, k = i - wdx * 12;
    sm[OFF_K11 + i] = (k < 11) ? (g11[wdx * 11 + k] - 0.3f) * sc : 0.f;
  }
  if (tid < 16) {
    sm[OFF_SB1 + tid] = b1[tid]; sm[OFF_SB2 + tid] = b2[tid];
    sm[OFF_SB3 + tid] = b3[tid]; sm[OFF_SB4 + tid] = b4[tid];
  }
  __syncthreads();

  // ---- phase 1: conv1 via mma.sync bf16-split (M=676,N=16,K=196) ----
  {
    int warp = tid >> 5, lane = tid & 31;
    int g = lane >> 2, tig = lane & 3;
    const float* sb1 = sm + OFF_SB1;
    float* sact = sm + OFF_ACT26;
#pragma unroll
    for (int pass = 0; pass < 2; pass++) {
      int t0 = pass * 22 + 2 * warp;  // tiles t0, t0+1 (t may be >=43 -> fully guarded)
      float d[2][2][4];
#pragma unroll
      for (int t = 0; t < 2; t++)
#pragma unroll
        for (int nt = 0; nt < 2; nt++)
#pragma unroll
          for (int e = 0; e < 4; e++) d[t][nt][e] = 0.f;
      // row bases: px for rows g, g+8 of each tile
      int px[2][2], base[2][2];
      bool ok[2][2];
#pragma unroll
      for (int t = 0; t < 2; t++) {
        px[t][0] = (t0 + t) * 16 + g;
        px[t][1] = px[t][0] + 8;
#pragma unroll
        for (int r = 0; r < 2; r++) {
          int p = px[t][r];
          ok[t][r] = p < 676;
          int oh = p / 26, ow = p - oh * 26;
          base[t][r] = ok[t][r] ? (oh * 1008 + ow * 12) : 0;
        }
      }
      for (int s = 0; s < 13; s++) {
        int k0 = s * 16 + tig * 2;
        int k8 = k0 + 8;
        bool k01ok = k0 < 196, k89ok = k8 < 196;
        int off01 = koff(k0 < 196 ? k0 : 0);
        int off89 = koff(k8 < 196 ? k8 : 0);
        uint4 B0 = g_w1frag[(s * 2 + 0) * 32 + lane];
        uint4 B1 = g_w1frag[(s * 2 + 1) * 32 + lane];
#pragma unroll
        for (int t = 0; t < 2; t++) {
          float2 v[4];  // a0(r0,c01) a1(r1,c01) a2(r0,c89) a3(r1,c89)
          v[0] = (ok[t][0] && k01ok) ? *(const float2*)(x + base[t][0] + off01) : make_float2(0.f, 0.f);
          v[1] = (ok[t][1] && k01ok) ? *(const float2*)(x + base[t][1] + off01) : make_float2(0.f, 0.f);
          v[2] = (ok[t][0] && k89ok) ? *(const float2*)(x + base[t][0] + off89) : make_float2(0.f, 0.f);
          v[3] = (ok[t][1] && k89ok) ? *(const float2*)(x + base[t][1] + off89) : make_float2(0.f, 0.f);
          unsigned ah[4], al[4];
#pragma unroll
          for (int q = 0; q < 4; q++) {
            unsigned xb = __float_as_uint(v[q].x), yb = __float_as_uint(v[q].y);
            ah[q] = __byte_perm(xb, yb, 0x7632);  // {y.hi16, x.hi16} -> low half = x
            float lx = v[q].x - __uint_as_float(xb & 0xffff0000u);
            float ly = v[q].y - __uint_as_float(yb & 0xffff0000u);
            al[q] = bf2pack(ly, lx);
          }
          MMA_BF16(d[t][0][0], d[t][0][1], d[t][0][2], d[t][0][3],
                   ah[0], ah[1], ah[2], ah[3], B0.x, B0.y);
          MMA_BF16(d[t][0][0], d[t][0][1], d[t][0][2], d[t][0][3],
                   ah[0], ah[1], ah[2], ah[3], B0.z, B0.w);
          MMA_BF16(d[t][0][0], d[t][0][1], d[t][0][2], d[t][0][3],
                   al[0], al[1], al[2], al[3], B0.x, B0.y);
          MMA_BF16(d[t][1][0], d[t][1][1], d[t][1][2], d[t][1][3],
                   ah[0], ah[1], ah[2], ah[3], B1.x, B1.y);
          MMA_BF16(d[t][1][0], d[t][1][1], d[t][1][2], d[t][1][3],
                   ah[0], ah[1], ah[2], ah[3], B1.z, B1.w);
          MMA_BF16(d[t][1][0], d[t][1][1], d[t][1][2], d[t][1][3],
                   al[0], al[1], al[2], al[3], B1.x, B1.y);
        }
      }
      // epilogue: D(row, col): d0 (g, tig*2), d1 (g, tig*2+1), d2 (g+8, ...), d3
#pragma unroll
      for (int t = 0; t < 2; t++)
#pragma unroll
        for (int nt = 0; nt < 2; nt++) {
          int co0 = nt * 8 + tig * 2, co1 = co0 + 1;
          if (ok[t][0]) {
            sact[co0 * 676 + px[t][0]] = lrelu(d[t][nt][0] + sb1[co0]);
            sact[co1 * 676 + px[t][0]] = lrelu(d[t][nt][1] + sb1[co1]);
          }
          if (ok[t][1]) {
            sact[co0 * 676 + px[t][1]] = lrelu(d[t][nt][2] + sb1[co0]);
            sact[co1 * 676 + px[t][1]] = lrelu(d[t][nt][3] + sb1[co1]);
          }
        }
    }
  }
  __syncthreads();

  // ---- phase 2: gaze26 in-place (row per thread, 416 items) ----
  for (int i = tid; i < 416; i += TPB) {
    int c = i / 26, h = i - c * 26;
    float* row = sm + OFF_ACT26 + c * 676 + h * 26;
    const float* K = sm + OFF_K26;
    float a[26];
#pragma unroll
    for (int w = 0; w < 26; w++) a[w] = row[w];
    ull acc[14];
#pragma unroll
    for (int q = 0; q < 14; q++) acc[q] = 0ULL;
#pragma unroll
    for (int w = 0; w < 26; w++) {
      ull xx = pack2(a[w]);
      const ulonglong2* kr = (const ulonglong2*)(K + w * 28);
#pragma unroll
      for (int q = 0; q < 7; q++) {
        ulonglong2 kv = kr[q];
        ffma2(acc[2 * q], xx, kv.x);
        ffma2(acc[2 * q + 1], xx, kv.y);
      }
    }
#pragma unroll
    for (int q = 0; q < 13; q++) {
      float2 v = unpack2(acc[q]);
      row[2 * q] = v.x; row[2 * q + 1] = v.y;
    }
  }
  __syncthreads();

  // ---- phase 3: conv2 5x5 s2 16->16, leaky. px x co-half (242) ----
  if (tid < 242) {
    int half = tid & 1, p = tid >> 1;
    int oh = p / 11, ow = p - oh * 11;
    int ih0 = oh * 2, iw0 = ow * 2;
    ull acc[4] = {0ULL, 0ULL, 0ULL, 0ULL};
    const float* w2t = sm + OFF_W2T;
    const float* sact = sm + OFF_ACT26;
    for (int ci = 0; ci < 16; ci++) {
      const float* irow = sact + ci * 676;
#pragma unroll
      for (int kh = 0; kh < 5; kh++) {
        const float* ir = irow + (ih0 + kh) * 26 + iw0;
#pragma unroll
        for (int kw = 0; kw < 5; kw++) {
          ull xx = pack2(ir[kw]);
          const ulonglong2* wq =
              (const ulonglong2*)(w2t + (ci * 25 + kh * 5 + kw) * 16 + half * 8);
          ulonglong2 q0 = wq[0], q1 = wq[1];
          ffma2(acc[0], xx, q0.x); ffma2(acc[1], xx, q0.y);
          ffma2(acc[2], xx, q1.x); ffma2(acc[3], xx, q1.y);
        }
      }
    }
    float* act11 = sm + OFF_ACT11;
    const float* sb2 = sm + OFF_SB2;
#pragma unroll
    for (int q = 0; q < 4; q++) {
      float2 v = unpack2(acc[q]);
      int co = half * 8 + 2 * q;
      act11[co * 121 + p]       = lrelu(v.x + sb2[co]);
      act11[(co + 1) * 121 + p] = lrelu(v.y + sb2[co + 1]);
    }
  }
  __syncthreads();

  // ---- phase 4: gaze11 in-place (176) ----
  if (tid < 176) {
    int c = tid / 11, h = tid - c * 11;
    float* row = sm + OFF_ACT11 + c * 121 + h * 11;
    const float* K = sm + OFF_K11;
    float a[11];
#pragma unroll
    for (int w = 0; w < 11; w++) a[w] = row[w];
    ull acc[6];
#pragma unroll
    for (int q = 0; q < 6; q++) acc[q] = 0ULL;
#pragma unroll
    for (int w = 0; w < 11; w++) {
      ull xx = pack2(a[w]);
      const ulonglong2* kr = (const ulonglong2*)(K + w * 12);
#pragma unroll
      for (int q = 0; q < 3; q++) {
        ulonglong2 kv = kr[q];
        ffma2(acc[2 * q], xx, kv.x);
        ffma2(acc[2 * q + 1], xx, kv.y);
      }
    }
#pragma unroll
    for (int q = 0; q < 5; q++) {
      float2 v = unpack2(acc[q]);
      row[2 * q] = v.x; row[2 * q + 1] = v.y;
    }
    row[10] = unpack2(acc[5]).x;
  }
  __syncthreads();

  // ---- phase 5: conv3 3x3 16->16, leaky. px x co-half (162) ----
  if (tid < 162) {
    int half = tid & 1, p = tid >> 1;
    int oh = p / 9, ow = p - oh * 9;
    ull acc[4] = {0ULL, 0ULL, 0ULL, 0ULL};
    const float* w3t = sm + OFF_W3T;
    const float* act11 = sm + OFF_ACT11;
    for (int ci = 0; ci < 16; ci++) {
      const float* irow = act11 + ci * 121;
#pragma unroll
      for (int kh = 0; kh < 3; kh++) {
        const float* ir = irow + (oh + kh) * 11 + ow;
#pragma unroll
        for (int kw = 0; kw < 3; kw++) {
          ull xx = pack2(ir[kw]);
          const ulonglong2* wq =
              (const ulonglong2*)(w3t + (ci * 9 + kh * 3 + kw) * 16 + half * 8);
          ulonglong2 q0 = wq[0], q1 = wq[1];
          ffma2(acc[0], xx, q0.x); ffma2(acc[1], xx, q0.y);
          ffma2(acc[2], xx, q1.x); ffma2(acc[3], xx, q1.y);
        }
      }
    }
    float* act9 = sm + OFF_ACT9;
    const float* sb3 = sm + OFF_SB3;
#pragma unroll
    for (int q = 0; q < 4; q++) {
      float2 v = unpack2(acc[q]);
      int co = half * 8 + 2 * q;
      act9[co * 81 + p]       = lrelu(v.x + sb3[co]);
      act9[(co + 1) * 81 + p] = lrelu(v.y + sb3[co + 1]);
    }
  }
  __syncthreads();

  // ---- phase 6: conv4 3x3 16->16, leaky -> g_xf + cm. px x co-half (98) ----
  if (tid < 98) {
    int half = tid & 1, p = tid >> 1;
    int oh = p / 7, ow = p - oh * 7;
    ull acc[4] = {0ULL, 0ULL, 0ULL, 0ULL};
    const float* w4t = sm + OFF_W4T;
    const float* act9 = sm + OFF_ACT9;
    for (int ci = 0; ci < 16; ci++) {
      const float* irow = act9 + ci * 81;
#pragma unroll
      for (int kh = 0; kh < 3; kh++) {
        const float* ir = irow + (oh + kh) * 9 + ow;
#pragma unroll
        for (int kw = 0; kw < 3; kw++) {
          ull xx = pack2(ir[kw]);
          const ulonglong2* wq =
              (const ulonglong2*)(w4t + (ci * 9 + kh * 3 + kw) * 16 + half * 8);
          ulonglong2 q0 = wq[0], q1 = wq[1];
          ffma2(acc[0], xx, q0.x); ffma2(acc[1], xx, q0.y);
          ffma2(acc[2], xx, q1.x); ffma2(acc[3], xx, q1.y);
        }
      }
    }
    const float* sb4 = sm + OFF_SB4;
    float* xp = g_xf + (size_t)n * 784 + p;
    float cs = 0.f;
#pragma unroll
    for (int q = 0; q < 4; q++) {
      float2 v = unpack2(acc[q]);
      int co = half * 8 + 2 * q;
      float v0 = lrelu(v.x + sb4[co]);
      float v1 = lrelu(v.y + sb4[co + 1]);
      xp[co * 49] = v0;
      xp[(co + 1) * 49] = v1;
      cs += v0 + v1;
    }
    sm[OFF_SCM + tid] = cs;
  }
  __syncthreads();
  if (tid < 49)
    g_cm[(size_t)n * 49 + tid] = sm[OFF_SCM + 2 * tid] + sm[OFF_SCM + 2 * tid + 1];
}

// ---------------- fc ----------------
__global__ __launch_bounds__(256) void k_fc(const float* __restrict__ w1,
                                            const float* __restrict__ b1,
                                            const float* __restrict__ w2,
                                            const float* __restrict__ b2) {
  __shared__ float As[64][17];
  __shared__ float Bs[16][68];
  __shared__ float prs[16][64];
  int tid = threadIdx.x;
  int s0 = blockIdx.x * 64;
  int sg = tid >> 4, jg = tid & 15;
  float acc[4][4];
#pragma unroll
  for (int i = 0; i < 4; i++)
#pragma unroll
    for (int u = 0; u < 4; u++) acc[i][u] = 0.f;
  for (int k0 = 0; k0 < 784; k0 += 16) {
    for (int i = tid; i < 1024; i += 256) {
      int s = i >> 4, kk = i & 15;
      As[s][kk] = g_xf[(size_t)(s0 + s) * 784 + k0 + kk];
    }
    for (int i = tid; i < 1024; i += 256) {
      int j = i >> 4, kk = i & 15;
      Bs[kk][j] = w1[j * 784 + k0 + kk];
    }
    __syncthreads();
#pragma unroll
    for (int kk = 0; kk < 16; kk++) {
      float av[4], bv[4];
#pragma unroll
      for (int i = 0; i < 4; i++) av[i] = As[sg * 4 + i][kk];
#pragma unroll
      for (int u = 0; u < 4; u++) bv[u] = Bs[kk][jg * 4 + u];
#pragma unroll
      for (int i = 0; i < 4; i++)
#pragma unroll
        for (int u = 0; u < 4; u++) acc[i][u] += av[i] * bv[u];
    }
    __syncthreads();
  }
#pragma unroll
  for (int i = 0; i < 4; i++) {
    float pr = 0.f;
#pragma unroll
    for (int u = 0; u < 4; u++) {
      int j = jg * 4 + u;
      float h = acc[i][u] + b1[j];
      h = lrelu(h);
      pr += h * w2[j];
    }
    prs[jg][sg * 4 + i] = pr;
  }
  __syncthreads();
  if (tid < 64) {
    float s = 0.f;
#pragma unroll
    for (int j = 0; j < 16; j++) s += prs[j][tid];
    g_r[s0 + tid] = s + b2[0];
  }
}

__global__ void k_reduce_r(float* __restrict__ out) {
  __shared__ float sab[64];
  int tid = threadIdx.x;
  int traj = tid >> 5, b = tid & 31;
  float s = 0.f, sa = 0.f;
  for (int t = 0; t < 64; t++) {
    float r = g_r[traj * 2048 + t * 32 + b];
    s += r;
    sa += fabsf(r);
  }
  out[tid] = s;
  sab[tid] = sa;
  __syncthreads();
  if (tid < 32) out[64 + tid] = sab[tid] + sab[32 + tid];
}

__global__ __launch_bounds__(256) void k_cmnorm(float* __restrict__ out) {
  __shared__ float sv[1568];
  __shared__ float smn[8], smx[8];
  __shared__ float fmn, fmx;
  int idx = blockIdx.x;
  int traj = idx >> 6, t = idx & 63;
  int tid = threadIdx.x;
  const float* base = g_cm + ((size_t)(traj * 2048 + t * 32)) * 49;
  float mn = 1e30f, mx = -1e30f;
  for (int i = tid; i < 1568; i += 256) {
    float v = base[i];
    sv[i] = v;
    mn = fminf(mn, v);
    mx = fmaxf(mx, v);
  }
#pragma unroll
  for (int o = 16; o; o >>= 1) {
    mn = fminf(mn, __shfl_xor_sync(0xffffffffu, mn, o));
    mx = fmaxf(mx, __shfl_xor_sync(0xffffffffu, mx, o));
  }
  if ((tid & 31) == 0) { smn[tid >> 5] = mn; smx[tid >> 5] = mx; }
  __syncthreads();
  if (tid == 0) {
    float a = smn[0], bb = smx[0];
    for (int i = 1; i < 8; i++) { a = fminf(a, smn[i]); bb = fmaxf(bb, smx[i]); }
    fmn = a; fmx = bb;
  }
  __syncthreads();
  float m = fmn, inv = 1.f / (fmx - m);
  float* o = out + 96 + (size_t)traj * 100352 + (size_t)t * 1568;
  for (int i = tid; i < 1568; i += 256) o[i] = (sv[i] - m) * inv;
}

extern "C" void kernel_launch(void* const* d_in, const int* in_sizes, int n_in,
                              void* d_out, int out_size) {
  const float* ti   = (const float*)d_in[0];
  const float* tj   = (const float*)d_in[1];
  const float* g26i = (const float*)d_in[2];
  const float* g11i = (const float*)d_in[3];
  const float* g26j = (const float*)d_in[4];
  const float* g11j = (const float*)d_in[5];
  const float* w1 = (const float*)d_in[6];  const float* b1 = (const float*)d_in[7];
  const float* w2 = (const float*)d_in[8];  const float* b2 = (const float*)d_in[9];
  const float* w3 = (const float*)d_in[10]; const float* b3 = (const float*)d_in[11];
  const float* w4 = (const float*)d_in[12]; const float* b4 = (const float*)d_in[13];
  const float* f1w = (const float*)d_in[14]; const float* f1b = (const float*)d_in[15];
  const float* f2w = (const float*)d_in[16]; const float* f2b = (const float*)d_in[17];
  float* out = (float*)d_out;

  cudaFuncSetAttribute(k_net, cudaFuncAttributeMaxDynamicSharedMemorySize,
                       SMEM_FLOATS * 4);

  k_prep<<<4, 512>>>(w1, w2, w3, w4);
  k_net<<<NTOT, TPB, SMEM_FLOATS * 4>>>(ti, tj, g26i, g26j, g11i, g11j,
                                        b1, b2, b3, b4);
  k_fc<<<NTOT / 64, 256>>>(f1w, f1b, f2w, f2b);
  k_reduce_r<<<1, 64>>>(out);
  k_cmnorm<<<128, 256>>>(out);
}

// round 12
// speedup vs baseline: 1.3224x; 1.0060x over previous
#include <cuda_runtime.h>
#include <math.h>

#define NPT 2048
#define NTOT 4096
#define TPB 352
typedef unsigned long long ull;

__device__ float g_xf[(size_t)NTOT * 784];
__device__ float g_cm[(size_t)NTOT * 49];
__device__ float g_r[NTOT];
__device__ __align__(16) float g_w2t[6400];
__device__ __align__(16) float g_w3t[2304];
__device__ __align__(16) float g_w4t[2304];
// conv1 weights, bf16-split, mma-fragment-ready: [s(13)][nt(2)][lane(32)] -> {b0h,b1h,b0l,b1l}
__device__ uint4 g_w1frag[832];

__device__ __forceinline__ float lrelu(float v) { return v >= 0.f ? v : 0.01f * v; }
__device__ __forceinline__ ull pack2(float x) {
  ull r; asm("mov.b64 %0,{%1,%1};" : "=l"(r) : "f"(x)); return r;
}
__device__ __forceinline__ void ffma2(ull& d, ull a, ull b) {
  asm("fma.rn.f32x2 %0,%1,%2,%0;" : "+l"(d) : "l"(a), "l"(b));
}
__device__ __forceinline__ float2 unpack2(ull v) {
  float2 r; asm("mov.b64 {%0,%1},%2;" : "=f"(r.x), "=f"(r.y) : "l"(v)); return r;
}
// bf16x2 pack: low half = lo_elem, high half = hi_elem
__device__ __forceinline__ unsigned bf2pack(float hi_elem, float lo_elem) {
  unsigned u; asm("cvt.rn.bf16x2.f32 %0, %1, %2;" : "=r"(u) : "f"(hi_elem), "f"(lo_elem));
  return u;
}
#define MMA_BF16(d0,d1,d2,d3,a0,a1,a2,a3,b0,b1) \
  asm("mma.sync.aligned.m16n8k16.row.col.f32.bf16.bf16.f32 " \
      "{%0,%1,%2,%3},{%4,%5,%6,%7},{%8,%9},{%0,%1,%2,%3};" \
      : "+f"(d0),"+f"(d1),"+f"(d2),"+f"(d3) \
      : "r"(a0),"r"(a1),"r"(a2),"r"(a3),"r"(b0),"r"(b1))

// smem float offsets (total 26078 floats = 104312 B -> 2 blocks/SM)
#define OFF_ACT26 0
#define OFF_W2T   10816
#define OFF_W3T   17216
#define OFF_W4T   19520
#define OFF_K26   21824
#define OFF_K11   22552
#define OFF_ACT11 22684
#define OFF_ACT9  24620
#define OFF_SB1   25916
#define OFF_SB2   25932
#define OFF_SB3   25948
#define OFF_SB4   25964
#define OFF_SCM   25980
#define SMEM_FLOATS 26078

__device__ __forceinline__ int koff(int k) {
  int ci = k & 3, t = k >> 2;
  int kw = t % 7, kh = t / 7;
  return kh * 336 + kw * 4 + ci;  // float offset within 84x84x4 window
}

// ---------------- one-time weight prep ----------------
__global__ void k_prep(const float* __restrict__ w1, const float* __restrict__ w2,
                       const float* __restrict__ w3, const float* __restrict__ w4) {
  int tid = blockIdx.x * blockDim.x + threadIdx.x;
  for (int i = tid; i < 6400; i += 2048) g_w2t[i] = w2[(i & 15) * 400 + (i >> 4)];
  for (int i = tid; i < 2304; i += 2048) g_w3t[i] = w3[(i & 15) * 144 + (i >> 4)];
  for (int i = tid; i < 2304; i += 2048) g_w4t[i] = w4[(i & 15) * 144 + (i >> 4)];
  // conv1 fragment build
  for (int idx = tid; idx < 832; idx += 2048) {
    int lane = idx & 31, sn = idx >> 5;
    int s = sn >> 1, nt = sn & 1;
    int tig = lane & 3, gq = lane >> 2;
    int co = nt * 8 + gq;
    float wv[4]; // k0,k0+1,k8,k8+1
    int k0 = s * 16 + tig * 2;
#pragma unroll
    for (int e = 0; e < 4; e++) {
      int k = k0 + (e >> 1) * 8 + (e & 1);
      float w = 0.f;
      if (k < 196) {
        int ci = k & 3, t = k >> 2, kw = t % 7, kh = t / 7;
        w = w1[co * 196 + ci * 49 + kh * 7 + kw];
      }
      wv[e] = w;
    }
    unsigned hb[4], hi_pairs[2], lo_pairs[2];
    float lo[4];
#pragma unroll
    for (int e = 0; e < 4; e++) {
      hb[e] = __float_as_uint(wv[e]) & 0xffff0000u;
      lo[e] = wv[e] - __uint_as_float(hb[e]);
    }
    hi_pairs[0] = (hb[0] >> 16) | (hb[1] & 0xffff0000u);
    hi_pairs[1] = (hb[2] >> 16) | (hb[3] & 0xffff0000u);
    lo_pairs[0] = bf2pack(lo[1], lo[0]);
    lo_pairs[1] = bf2pack(lo[3], lo[2]);
    uint4 out;
    out.x = hi_pairs[0]; out.y = hi_pairs[1];
    out.z = lo_pairs[0]; out.w = lo_pairs[1];
    g_w1frag[idx] = out;
  }
}

__global__ __launch_bounds__(TPB, 2) void k_net(
    const float* __restrict__ ti, const float* __restrict__ tj,
    const float* __restrict__ g26i, const float* __restrict__ g26j,
    const float* __restrict__ g11i, const float* __restrict__ g11j,
    const float* __restrict__ b1, const float* __restrict__ b2,
    const float* __restrict__ b3, const float* __restrict__ b4) {
  extern __shared__ float sm[];
  int n = blockIdx.x, tid = threadIdx.x;
  const float sc = 1.0f / (0.7f * 0.3f);

  const float* x   = (n < NPT) ? ti   + (size_t)n * 28224 : tj   + (size_t)(n - NPT) * 28224;
  const float* g26 = (n < NPT) ? g26i + (size_t)n * 676   : g26j + (size_t)(n - NPT) * 676;
  const float* g11 = (n < NPT) ? g11i + (size_t)n * 121   : g11j + (size_t)(n - NPT) * 121;

  // ---- phase 0: weights + gaze kernels into smem ----
  for (int i = tid; i < 6400; i += TPB) sm[OFF_W2T + i] = g_w2t[i];
  for (int i = tid; i < 2304; i += TPB) sm[OFF_W3T + i] = g_w3t[i];
  for (int i = tid; i < 2304; i += TPB) sm[OFF_W4T + i] = g_w4t[i];
  for (int i = tid; i < 728; i += TPB) {
    int wdx = i / 28, k = i - wdx * 28;
    sm[OFF_K26 + i] = (k < 26) ? (g26[wdx * 26 + k] - 0.3f) * sc : 0.f;
  }
  for (int i = tid; i < 132; i += TPB) {
    int wdx = i / 12, k = i - wdx * 12;
    sm[OFF_K11 + i] = (k < 11) ? (g11[wdx * 11 + k] - 0.3f) * sc : 0.f;
  }
  if (tid < 16) {
    sm[OFF_SB1 + tid] = b1[tid]; sm[OFF_SB2 + tid] = b2[tid];
    sm[OFF_SB3 + tid] = b3[tid]; sm[OFF_SB4 + tid] = b4[tid];
  }
  __syncthreads();

  // ---- phase 1: conv1 via mma.sync bf16-split (M=676,N=16,K=196) ----
  {
    int warp = tid >> 5, lane = tid & 31;
    int g = lane >> 2, tig = lane & 3;
    const float* sb1 = sm + OFF_SB1;
    float* sact = sm + OFF_ACT26;
#pragma unroll
    for (int pass = 0; pass < 2; pass++) {
      int t0 = pass * 22 + 2 * warp;  // tiles t0, t0+1 (t may be >=43 -> fully guarded)
      float d[2][2][4];
#pragma unroll
      for (int t = 0; t < 2; t++)
#pragma unroll
        for (int nt = 0; nt < 2; nt++)
#pragma unroll
          for (int e = 0; e < 4; e++) d[t][nt][e] = 0.f;
      // row bases: px for rows g, g+8 of each tile
      int px[2][2], base[2][2];
      bool ok[2][2];
#pragma unroll
      for (int t = 0; t < 2; t++) {
        px[t][0] = (t0 + t) * 16 + g;
        px[t][1] = px[t][0] + 8;
#pragma unroll
        for (int r = 0; r < 2; r++) {
          int p = px[t][r];
          ok[t][r] = p < 676;
          int oh = p / 26, ow = p - oh * 26;
          base[t][r] = ok[t][r] ? (oh * 1008 + ow * 12) : 0;
        }
      }
      for (int s = 0; s < 13; s++) {
        int k0 = s * 16 + tig * 2;
        int k8 = k0 + 8;
        bool k01ok = k0 < 196, k89ok = k8 < 196;
        int off01 = koff(k0 < 196 ? k0 : 0);
        int off89 = koff(k8 < 196 ? k8 : 0);
        uint4 B0 = g_w1frag[(s * 2 + 0) * 32 + lane];
        uint4 B1 = g_w1frag[(s * 2 + 1) * 32 + lane];
#pragma unroll
        for (int t = 0; t < 2; t++) {
          float2 v[4];  // a0(r0,c01) a1(r1,c01) a2(r0,c89) a3(r1,c89)
          v[0] = (ok[t][0] && k01ok) ? *(const float2*)(x + base[t][0] + off01) : make_float2(0.f, 0.f);
          v[1] = (ok[t][1] && k01ok) ? *(const float2*)(x + base[t][1] + off01) : make_float2(0.f, 0.f);
          v[2] = (ok[t][0] && k89ok) ? *(const float2*)(x + base[t][0] + off89) : make_float2(0.f, 0.f);
          v[3] = (ok[t][1] && k89ok) ? *(const float2*)(x + base[t][1] + off89) : make_float2(0.f, 0.f);
          unsigned ah[4], al[4];
#pragma unroll
          for (int q = 0; q < 4; q++) {
            unsigned xb = __float_as_uint(v[q].x), yb = __float_as_uint(v[q].y);
            ah[q] = __byte_perm(xb, yb, 0x7632);  // {y.hi16, x.hi16} -> low half = x
            float lx = v[q].x - __uint_as_float(xb & 0xffff0000u);
            float ly = v[q].y - __uint_as_float(yb & 0xffff0000u);
            al[q] = bf2pack(ly, lx);
          }
          MMA_BF16(d[t][0][0], d[t][0][1], d[t][0][2], d[t][0][3],
                   ah[0], ah[1], ah[2], ah[3], B0.x, B0.y);
          MMA_BF16(d[t][0][0], d[t][0][1], d[t][0][2], d[t][0][3],
                   ah[0], ah[1], ah[2], ah[3], B0.z, B0.w);
          MMA_BF16(d[t][0][0], d[t][0][1], d[t][0][2], d[t][0][3],
                   al[0], al[1], al[2], al[3], B0.x, B0.y);
          MMA_BF16(d[t][1][0], d[t][1][1], d[t][1][2], d[t][1][3],
                   ah[0], ah[1], ah[2], ah[3], B1.x, B1.y);
          MMA_BF16(d[t][1][0], d[t][1][1], d[t][1][2], d[t][1][3],
                   ah[0], ah[1], ah[2], ah[3], B1.z, B1.w);
          MMA_BF16(d[t][1][0], d[t][1][1], d[t][1][2], d[t][1][3],
                   al[0], al[1], al[2], al[3], B1.x, B1.y);
        }
      }
      // epilogue: D(row, col): d0 (g, tig*2), d1 (g, tig*2+1), d2 (g+8, ...), d3
#pragma unroll
      for (int t = 0; t < 2; t++)
#pragma unroll
        for (int nt = 0; nt < 2; nt++) {
          int co0 = nt * 8 + tig * 2, co1 = co0 + 1;
          if (ok[t][0]) {
            sact[co0 * 676 + px[t][0]] = lrelu(d[t][nt][0] + sb1[co0]);
            sact[co1 * 676 + px[t][0]] = lrelu(d[t][nt][1] + sb1[co1]);
          }
          if (ok[t][1]) {
            sact[co0 * 676 + px[t][1]] = lrelu(d[t][nt][2] + sb1[co0]);
            sact[co1 * 676 + px[t][1]] = lrelu(d[t][nt][3] + sb1[co1]);
          }
        }
    }
  }
  __syncthreads();

  // ---- phase 2: gaze26 in-place (row per thread, 416 items) ----
  for (int i = tid; i < 416; i += TPB) {
    int c = i / 26, h = i - c * 26;
    float* row = sm + OFF_ACT26 + c * 676 + h * 26;
    const float* K = sm + OFF_K26;
    float a[26];
#pragma unroll
    for (int w = 0; w < 26; w++) a[w] = row[w];
    ull acc[14];
#pragma unroll
    for (int q = 0; q < 14; q++) acc[q] = 0ULL;
#pragma unroll
    for (int w = 0; w < 26; w++) {
      ull xx = pack2(a[w]);
      const ulonglong2* kr = (const ulonglong2*)(K + w * 28);
#pragma unroll
      for (int q = 0; q < 7; q++) {
        ulonglong2 kv = kr[q];
        ffma2(acc[2 * q], xx, kv.x);
        ffma2(acc[2 * q + 1], xx, kv.y);
      }
    }
#pragma unroll
    for (int q = 0; q < 13; q++) {
      float2 v = unpack2(acc[q]);
      row[2 * q] = v.x; row[2 * q + 1] = v.y;
    }
  }
  __syncthreads();

  // ---- phase 3: conv2 5x5 s2 16->16, leaky. px x co-half (242) ----
  if (tid < 242) {
    int half = tid & 1, p = tid >> 1;
    int oh = p / 11, ow = p - oh * 11;
    int ih0 = oh * 2, iw0 = ow * 2;
    ull acc[4] = {0ULL, 0ULL, 0ULL, 0ULL};
    const float* w2t = sm + OFF_W2T;
    const float* sact = sm + OFF_ACT26;
    for (int ci = 0; ci < 16; ci++) {
      const float* irow = sact + ci * 676;
#pragma unroll
      for (int kh = 0; kh < 5; kh++) {
        const float* ir = irow + (ih0 + kh) * 26 + iw0;
#pragma unroll
        for (int kw = 0; kw < 5; kw++) {
          ull xx = pack2(ir[kw]);
          const ulonglong2* wq =
              (const ulonglong2*)(w2t + (ci * 25 + kh * 5 + kw) * 16 + half * 8);
          ulonglong2 q0 = wq[0], q1 = wq[1];
          ffma2(acc[0], xx, q0.x); ffma2(acc[1], xx, q0.y);
          ffma2(acc[2], xx, q1.x); ffma2(acc[3], xx, q1.y);
        }
      }
    }
    float* act11 = sm + OFF_ACT11;
    const float* sb2 = sm + OFF_SB2;
#pragma unroll
    for (int q = 0; q < 4; q++) {
      float2 v = unpack2(acc[q]);
      int co = half * 8 + 2 * q;
      act11[co * 121 + p]       = lrelu(v.x + sb2[co]);
      act11[(co + 1) * 121 + p] = lrelu(v.y + sb2[co + 1]);
    }
  }
  __syncthreads();

  // ---- phase 4: gaze11 in-place (176) ----
  if (tid < 176) {
    int c = tid / 11, h = tid - c * 11;
    float* row = sm + OFF_ACT11 + c * 121 + h * 11;
    const float* K = sm + OFF_K11;
    float a[11];
#pragma unroll
    for (int w = 0; w < 11; w++) a[w] = row[w];
    ull acc[6];
#pragma unroll
    for (int q = 0; q < 6; q++) acc[q] = 0ULL;
#pragma unroll
    for (int w = 0; w < 11; w++) {
      ull xx = pack2(a[w]);
      const ulonglong2* kr = (const ulonglong2*)(K + w * 12);
#pragma unroll
      for (int q = 0; q < 3; q++) {
        ulonglong2 kv = kr[q];
        ffma2(acc[2 * q], xx, kv.x);
        ffma2(acc[2 * q + 1], xx, kv.y);
      }
    }
#pragma unroll
    for (int q = 0; q < 5; q++) {
      float2 v = unpack2(acc[q]);
      row[2 * q] = v.x; row[2 * q + 1] = v.y;
    }
    row[10] = unpack2(acc[5]).x;
  }
  __syncthreads();

  // ---- phase 5: conv3 3x3 16->16, leaky. px x co-half (162) ----
  if (tid < 162) {
    int half = tid & 1, p = tid >> 1;
    int oh = p / 9, ow = p - oh * 9;
    ull acc[4] = {0ULL, 0ULL, 0ULL, 0ULL};
    const float* w3t = sm + OFF_W3T;
    const float* act11 = sm + OFF_ACT11;
    for (int ci = 0; ci < 16; ci++) {
      const float* irow = act11 + ci * 121;
#pragma unroll
      for (int kh = 0; kh < 3; kh++) {
        const float* ir = irow + (oh + kh) * 11 + ow;
#pragma unroll
        for (int kw = 0; kw < 3; kw++) {
          ull xx = pack2(ir[kw]);
          const ulonglong2* wq =
              (const ulonglong2*)(w3t + (ci * 9 + kh * 3 + kw) * 16 + half * 8);
          ulonglong2 q0 = wq[0], q1 = wq[1];
          ffma2(acc[0], xx, q0.x); ffma2(acc[1], xx, q0.y);
          ffma2(acc[2], xx, q1.x); ffma2(acc[3], xx, q1.y);
        }
      }
    }
    float* act9 = sm + OFF_ACT9;
    const float* sb3 = sm + OFF_SB3;
#pragma unroll
    for (int q = 0; q < 4; q++) {
      float2 v = unpack2(acc[q]);
      int co = half * 8 + 2 * q;
      act9[co * 81 + p]       = lrelu(v.x + sb3[co]);
      act9[(co + 1) * 81 + p] = lrelu(v.y + sb3[co + 1]);
    }
  }
  __syncthreads();

  // ---- phase 6: conv4 3x3 16->16, leaky -> g_xf + cm. px x co-half (98) ----
  if (tid < 98) {
    int half = tid & 1, p = tid >> 1;
    int oh = p / 7, ow = p - oh * 7;
    ull acc[4] = {0ULL, 0ULL, 0ULL, 0ULL};
    const float* w4t = sm + OFF_W4T;
    const float* act9 = sm + OFF_ACT9;
    for (int ci = 0; ci < 16; ci++) {
      const float* irow = act9 + ci * 81;
#pragma unroll
      for (int kh = 0; kh < 3; kh++) {
        const float* ir = irow + (oh + kh) * 9 + ow;
#pragma unroll
        for (int kw = 0; kw < 3; kw++) {
          ull xx = pack2(ir[kw]);
          const ulonglong2* wq =
              (const ulonglong2*)(w4t + (ci * 9 + kh * 3 + kw) * 16 + half * 8);
          ulonglong2 q0 = wq[0], q1 = wq[1];
          ffma2(acc[0], xx, q0.x); ffma2(acc[1], xx, q0.y);
          ffma2(acc[2], xx, q1.x); ffma2(acc[3], xx, q1.y);
        }
      }
    }
    const float* sb4 = sm + OFF_SB4;
    float* xp = g_xf + (size_t)n * 784 + p;
    float cs = 0.f;
#pragma unroll
    for (int q = 0; q < 4; q++) {
      float2 v = unpack2(acc[q]);
      int co = half * 8 + 2 * q;
      float v0 = lrelu(v.x + sb4[co]);
      float v1 = lrelu(v.y + sb4[co + 1]);
      xp[co * 49] = v0;
      xp[(co + 1) * 49] = v1;
      cs += v0 + v1;
    }
    sm[OFF_SCM + tid] = cs;
  }
  __syncthreads();
  if (tid < 49)
    g_cm[(size_t)n * 49 + tid] = sm[OFF_SCM + 2 * tid] + sm[OFF_SCM + 2 * tid + 1];
}

// ---------------- fc ----------------
__global__ __launch_bounds__(256) void k_fc(const float* __restrict__ w1,
                                            const float* __restrict__ b1,
                                            const float* __restrict__ w2,
                                            const float* __restrict__ b2) {
  __shared__ float As[64][17];
  __shared__ float Bs[16][68];
  __shared__ float prs[16][64];
  int tid = threadIdx.x;
  int s0 = blockIdx.x * 64;
  int sg = tid >> 4, jg = tid & 15;
  float acc[4][4];
#pragma unroll
  for (int i = 0; i < 4; i++)
#pragma unroll
    for (int u = 0; u < 4; u++) acc[i][u] = 0.f;
  for (int k0 = 0; k0 < 784; k0 += 16) {
    for (int i = tid; i < 1024; i += 256) {
      int s = i >> 4, kk = i & 15;
      As[s][kk] = g_xf[(size_t)(s0 + s) * 784 + k0 + kk];
    }
    for (int i = tid; i < 1024; i += 256) {
      int j = i >> 4, kk = i & 15;
      Bs[kk][j] = w1[j * 784 + k0 + kk];
    }
    __syncthreads();
#pragma unroll
    for (int kk = 0; kk < 16; kk++) {
      float av[4], bv[4];
#pragma unroll
      for (int i = 0; i < 4; i++) av[i] = As[sg * 4 + i][kk];
#pragma unroll
      for (int u = 0; u < 4; u++) bv[u] = Bs[kk][jg * 4 + u];
#pragma unroll
      for (int i = 0; i < 4; i++)
#pragma unroll
        for (int u = 0; u < 4; u++) acc[i][u] += av[i] * bv[u];
    }
    __syncthreads();
  }
#pragma unroll
  for (int i = 0; i < 4; i++) {
    float pr = 0.f;
#pragma unroll
    for (int u = 0; u < 4; u++) {
      int j = jg * 4 + u;
      float h = acc[i][u] + b1[j];
      h = lrelu(h);
      pr += h * w2[j];
    }
    prs[jg][sg * 4 + i] = pr;
  }
  __syncthreads();
  if (tid < 64) {
    float s = 0.f;
#pragma unroll
    for (int j = 0; j < 16; j++) s += prs[j][tid];
    g_r[s0 + tid] = s + b2[0];
  }
}

__global__ void k_reduce_r(float* __restrict__ out) {
  __shared__ float sab[64];
  int tid = threadIdx.x;
  int traj = tid >> 5, b = tid & 31;
  float s = 0.f, sa = 0.f;
  for (int t = 0; t < 64; t++) {
    float r = g_r[traj * 2048 + t * 32 + b];
    s += r;
    sa += fabsf(r);
  }
  out[tid] = s;
  sab[tid] = sa;
  __syncthreads();
  if (tid < 32) out[64 + tid] = sab[tid] + sab[32 + tid];
}

__global__ __launch_bounds__(256) void k_cmnorm(float* __restrict__ out) {
  __shared__ float sv[1568];
  __shared__ float smn[8], smx[8];
  __shared__ float fmn, fmx;
  int idx = blockIdx.x;
  int traj = idx >> 6, t = idx & 63;
  int tid = threadIdx.x;
  const float* base = g_cm + ((size_t)(traj * 2048 + t * 32)) * 49;
  float mn = 1e30f, mx = -1e30f;
  for (int i = tid; i < 1568; i += 256) {
    float v = base[i];
    sv[i] = v;
    mn = fminf(mn, v);
    mx = fmaxf(mx, v);
  }
#pragma unroll
  for (int o = 16; o; o >>= 1) {
    mn = fminf(mn, __shfl_xor_sync(0xffffffffu, mn, o));
    mx = fmaxf(mx, __shfl_xor_sync(0xffffffffu, mx, o));
  }
  if ((tid & 31) == 0) { smn[tid >> 5] = mn; smx[tid >> 5] = mx; }
  __syncthreads();
  if (tid == 0) {
    float a = smn[0], bb = smx[0];
    for (int i = 1; i < 8; i++) { a = fminf(a, smn[i]); bb = fmaxf(bb, smx[i]); }
    fmn = a; fmx = bb;
  }
  __syncthreads();
  float m = fmn, inv = 1.f / (fmx - m);
  float* o = out + 96 + (size_t)traj * 100352 + (size_t)t * 1568;
  for (int i = tid; i < 1568; i += 256) o[i] = (sv[i] - m) * inv;
}

extern "C" void kernel_launch(void* const* d_in, const int* in_sizes, int n_in,
                              void* d_out, int out_size) {
  const float* ti   = (const float*)d_in[0];
  const float* tj   = (const float*)d_in[1];
  const float* g26i = (const float*)d_in[2];
  const float* g11i = (const float*)d_in[3];
  const float* g26j = (const float*)d_in[4];
  const float* g11j = (const float*)d_in[5];
  const float* w1 = (const float*)d_in[6];  const float* b1 = (const float*)d_in[7];
  const float* w2 = (const float*)d_in[8];  const float* b2 = (const float*)d_in[9];
  const float* w3 = (const float*)d_in[10]; const float* b3 = (const float*)d_in[11];
  const float* w4 = (const float*)d_in[12]; const float* b4 = (const float*)d_in[13];
  const float* f1w = (const float*)d_in[14]; const float* f1b = (const float*)d_in[15];
  const float* f2w = (const float*)d_in[16]; const float* f2b = (const float*)d_in[17];
  float* out = (float*)d_out;

  cudaFuncSetAttribute(k_net, cudaFuncAttributeMaxDynamicSharedMemorySize,
                       SMEM_FLOATS * 4);

  k_prep<<<4, 512>>>(w1, w2, w3, w4);
  k_net<<<NTOT, TPB, SMEM_FLOATS * 4>>>(ti, tj, g26i, g26j, g11i, g11j,
                                        b1, b2, b3, b4);
  k_fc<<<NTOT / 64, 256>>>(f1w, f1b, f2w, f2b);
  k_reduce_r<<<1, 64>>>(out);
  k_cmnorm<<<128, 256>>>(out);
}

// round 13
// speedup vs baseline: 1.4045x; 1.0621x over previous
#include <cuda_runtime.h>
#include <math.h>

#define NPT 2048
#define NTOT 4096
#define TPB 416
typedef unsigned long long ull;

__device__ float g_xf[(size_t)NTOT * 784];
__device__ float g_cm[(size_t)NTOT * 49];
__device__ float g_r[NTOT];
__device__ __align__(16) float g_w3t[2304];
__device__ __align__(16) float g_w4t[2304];
// conv1 weights, bf16-split, fragment-ready: [s(13)][nt(2)][lane(32)] -> {b0h,b1h,b0l,b1l}
__device__ uint4 g_w1frag[832];
// conv2 weights, bf16-split, fragment-ready: [s(25)][nt(2)][lane(32)]
__device__ uint4 g_w2frag[1600];

__device__ __forceinline__ float lrelu(float v) { return v >= 0.f ? v : 0.01f * v; }
__device__ __forceinline__ ull pack2(float x) {
  ull r; asm("mov.b64 %0,{%1,%1};" : "=l"(r) : "f"(x)); return r;
}
__device__ __forceinline__ void ffma2(ull& d, ull a, ull b) {
  asm("fma.rn.f32x2 %0,%1,%2,%0;" : "+l"(d) : "l"(a), "l"(b));
}
__device__ __forceinline__ float2 unpack2(ull v) {
  float2 r; asm("mov.b64 {%0,%1},%2;" : "=f"(r.x), "=f"(r.y) : "l"(v)); return r;
}
// bf16x2 pack: low half = lo_elem, high half = hi_elem
__device__ __forceinline__ unsigned bf2pack(float hi_elem, float lo_elem) {
  unsigned u; asm("cvt.rn.bf16x2.f32 %0, %1, %2;" : "=r"(u) : "f"(hi_elem), "f"(lo_elem));
  return u;
}
#define MMA_BF16(d0,d1,d2,d3,a0,a1,a2,a3,b0,b1) \
  asm("mma.sync.aligned.m16n8k16.row.col.f32.bf16.bf16.f32 " \
      "{%0,%1,%2,%3},{%4,%5,%6,%7},{%8,%9},{%0,%1,%2,%3};" \
      : "+f"(d0),"+f"(d1),"+f"(d2),"+f"(d3) \
      : "r"(a0),"r"(a1),"r"(a2),"r"(a3),"r"(b0),"r"(b1))

// smem float offsets (26478 floats = 105912 B -> 2 blocks/SM)
#define OFF_ACT26 0        // 10816
#define OFF_W2F   10816    // 6400 floats = 1600 uint4 (conv2 fragments)
#define OFF_W3T   17216    // 2304
#define OFF_W4T   19520    // 2304
#define OFF_K26   21824    // 728
#define OFF_K11   22552    // 132
#define OFF_ACT11 22684    // 1936
#define OFF_ACT9  24620    // 1296
#define OFF_SB1   25916
#define OFF_SB2   25932
#define OFF_SB3   25948
#define OFF_SB4   25964
#define OFF_SCM   25980    // 98
#define OFF_KOFF  26078    // 400 ints (conv2 k -> act26 offset)
#define SMEM_FLOATS 26478

__device__ __forceinline__ int koff(int k) {
  int ci = k & 3, t = k >> 2;
  int kw = t % 7, kh = t / 7;
  return kh * 336 + kw * 4 + ci;  // float offset within 84x84x4 window
}

// ---------------- one-time weight prep ----------------
__global__ void k_prep(const float* __restrict__ w1, const float* __restrict__ w2,
                       const float* __restrict__ w3, const float* __restrict__ w4) {
  int tid = blockIdx.x * blockDim.x + threadIdx.x;
  for (int i = tid; i < 2304; i += 2048) g_w3t[i] = w3[(i & 15) * 144 + (i >> 4)];
  for (int i = tid; i < 2304; i += 2048) g_w4t[i] = w4[(i & 15) * 144 + (i >> 4)];
  // conv1 fragments
  for (int idx = tid; idx < 832; idx += 2048) {
    int lane = idx & 31, sn = idx >> 5;
    int s = sn >> 1, nt = sn & 1;
    int tig = lane & 3, gq = lane >> 2;
    int co = nt * 8 + gq;
    float wv[4];
    int k0 = s * 16 + tig * 2;
#pragma unroll
    for (int e = 0; e < 4; e++) {
      int k = k0 + (e >> 1) * 8 + (e & 1);
      float w = 0.f;
      if (k < 196) {
        int ci = k & 3, t = k >> 2, kw = t % 7, kh = t / 7;
        w = w1[co * 196 + ci * 49 + kh * 7 + kw];
      }
      wv[e] = w;
    }
    unsigned hb[4]; float lo[4];
#pragma unroll
    for (int e = 0; e < 4; e++) {
      hb[e] = __float_as_uint(wv[e]) & 0xffff0000u;
      lo[e] = wv[e] - __uint_as_float(hb[e]);
    }
    uint4 out;
    out.x = (hb[0] >> 16) | (hb[1] & 0xffff0000u);
    out.y = (hb[2] >> 16) | (hb[3] & 0xffff0000u);
    out.z = bf2pack(lo[1], lo[0]);
    out.w = bf2pack(lo[3], lo[2]);
    g_w1frag[idx] = out;
  }
  // conv2 fragments: w2 element (k, co) = w2[co*400 + k], k = ci*25+kh*5+kw
  for (int idx = tid; idx < 1600; idx += 2048) {
    int lane = idx & 31, sn = idx >> 5;
    int s = sn >> 1, nt = sn & 1;
    int tig = lane & 3, gq = lane >> 2;
    int co = nt * 8 + gq;
    float wv[4];
    int k0 = s * 16 + tig * 2;
#pragma unroll
    for (int e = 0; e < 4; e++) {
      int k = k0 + (e >> 1) * 8 + (e & 1);
      wv[e] = w2[co * 400 + k];
    }
    unsigned hb[4]; float lo[4];
#pragma unroll
    for (int e = 0; e < 4; e++) {
      hb[e] = __float_as_uint(wv[e]) & 0xffff0000u;
      lo[e] = wv[e] - __uint_as_float(hb[e]);
    }
    uint4 out;
    out.x = (hb[0] >> 16) | (hb[1] & 0xffff0000u);
    out.y = (hb[2] >> 16) | (hb[3] & 0xffff0000u);
    out.z = bf2pack(lo[1], lo[0]);
    out.w = bf2pack(lo[3], lo[2]);
    g_w2frag[idx] = out;
  }
}

__global__ __launch_bounds__(TPB, 2) void k_net(
    const float* __restrict__ ti, const float* __restrict__ tj,
    const float* __restrict__ g26i, const float* __restrict__ g26j,
    const float* __restrict__ g11i, const float* __restrict__ g11j,
    const float* __restrict__ b1, const float* __restrict__ b2,
    const float* __restrict__ b3, const float* __restrict__ b4) {
  extern __shared__ float sm[];
  int n = blockIdx.x, tid = threadIdx.x;
  const float sc = 1.0f / (0.7f * 0.3f);

  const float* x   = (n < NPT) ? ti   + (size_t)n * 28224 : tj   + (size_t)(n - NPT) * 28224;
  const float* g26 = (n < NPT) ? g26i + (size_t)n * 676   : g26j + (size_t)(n - NPT) * 676;
  const float* g11 = (n < NPT) ? g11i + (size_t)n * 121   : g11j + (size_t)(n - NPT) * 121;

  // ---- phase 0: weights/fragments/tables into smem ----
  {
    uint4* dst = (uint4*)(sm + OFF_W2F);
    for (int i = tid; i < 1600; i += TPB) dst[i] = g_w2frag[i];
  }
  for (int i = tid; i < 2304; i += TPB) sm[OFF_W3T + i] = g_w3t[i];
  for (int i = tid; i < 2304; i += TPB) sm[OFF_W4T + i] = g_w4t[i];
  for (int i = tid; i < 728; i += TPB) {
    int wdx = i / 28, k = i - wdx * 28;
    sm[OFF_K26 + i] = (k < 26) ? (g26[wdx * 26 + k] - 0.3f) * sc : 0.f;
  }
  for (int i = tid; i < 132; i += TPB) {
    int wdx = i / 12, k = i - wdx * 12;
    sm[OFF_K11 + i] = (k < 11) ? (g11[wdx * 11 + k] - 0.3f) * sc : 0.f;
  }
  {
    int* kt = (int*)(sm + OFF_KOFF);
    for (int k = tid; k < 400; k += TPB) {
      int ci = k / 25, t = k - ci * 25, kh = t / 5, kw = t - kh * 5;
      kt[k] = ci * 676 + kh * 26 + kw;
    }
  }
  if (tid < 16) {
    sm[OFF_SB1 + tid] = b1[tid]; sm[OFF_SB2 + tid] = b2[tid];
    sm[OFF_SB3 + tid] = b3[tid]; sm[OFF_SB4 + tid] = b4[tid];
  }
  __syncthreads();

  // ---- phase 1: conv1 via mma.sync bf16-split (M=676,N=16,K=196), 1 tile/pass ----
  {
    int warp = tid >> 5, lane = tid & 31;
    int g = lane >> 2, tig = lane & 3;
    const float* sb1 = sm + OFF_SB1;
    float* sact = sm + OFF_ACT26;
    for (int pass = 0; pass < 4; pass++) {
      int tile = pass * 13 + warp;
      if (tile >= 43) break;
      float dA[4] = {0.f, 0.f, 0.f, 0.f};
      float dB[4] = {0.f, 0.f, 0.f, 0.f};
      int p0 = tile * 16 + g, p1 = p0 + 8;
      bool ok0 = p0 < 676, ok1 = p1 < 676;
      int oh0 = p0 / 26, ow0 = p0 - oh0 * 26;
      int oh1 = p1 / 26, ow1 = p1 - oh1 * 26;
      int base0 = ok0 ? (oh0 * 1008 + ow0 * 12) : 0;
      int base1 = ok1 ? (oh1 * 1008 + ow1 * 12) : 0;
      for (int s = 0; s < 13; s++) {
        int k0 = s * 16 + tig * 2;
        int k8 = k0 + 8;
        bool k01ok = k0 < 196, k89ok = k8 < 196;
        int off01 = koff(k01ok ? k0 : 0);
        int off89 = koff(k89ok ? k8 : 0);
        uint4 B0 = g_w1frag[(s * 2 + 0) * 32 + lane];
        uint4 B1 = g_w1frag[(s * 2 + 1) * 32 + lane];
        float2 v[4];
        v[0] = (ok0 && k01ok) ? *(const float2*)(x + base0 + off01) : make_float2(0.f, 0.f);
        v[1] = (ok1 && k01ok) ? *(const float2*)(x + base1 + off01) : make_float2(0.f, 0.f);
        v[2] = (ok0 && k89ok) ? *(const float2*)(x + base0 + off89) : make_float2(0.f, 0.f);
        v[3] = (ok1 && k89ok) ? *(const float2*)(x + base1 + off89) : make_float2(0.f, 0.f);
        unsigned ah[4], al[4];
#pragma unroll
        for (int q = 0; q < 4; q++) {
          unsigned xb = __float_as_uint(v[q].x), yb = __float_as_uint(v[q].y);
          ah[q] = __byte_perm(xb, yb, 0x7632);
          float lx = v[q].x - __uint_as_float(xb & 0xffff0000u);
          float ly = v[q].y - __uint_as_float(yb & 0xffff0000u);
          al[q] = bf2pack(ly, lx);
        }
        MMA_BF16(dA[0], dA[1], dA[2], dA[3], ah[0], ah[1], ah[2], ah[3], B0.x, B0.y);
        MMA_BF16(dA[0], dA[1], dA[2], dA[3], ah[0], ah[1], ah[2], ah[3], B0.z, B0.w);
        MMA_BF16(dA[0], dA[1], dA[2], dA[3], al[0], al[1], al[2], al[3], B0.x, B0.y);
        MMA_BF16(dB[0], dB[1], dB[2], dB[3], ah[0], ah[1], ah[2], ah[3], B1.x, B1.y);
        MMA_BF16(dB[0], dB[1], dB[2], dB[3], ah[0], ah[1], ah[2], ah[3], B1.z, B1.w);
        MMA_BF16(dB[0], dB[1], dB[2], dB[3], al[0], al[1], al[2], al[3], B1.x, B1.y);
      }
      int co0 = tig * 2, co1 = co0 + 1;
      if (ok0) {
        sact[co0 * 676 + p0] = lrelu(dA[0] + sb1[co0]);
        sact[co1 * 676 + p0] = lrelu(dA[1] + sb1[co1]);
        sact[(co0 + 8) * 676 + p0] = lrelu(dB[0] + sb1[co0 + 8]);
        sact[(co1 + 8) * 676 + p0] = lrelu(dB[1] + sb1[co1 + 8]);
      }
      if (ok1) {
        sact[co0 * 676 + p1] = lrelu(dA[2] + sb1[co0]);
        sact[co1 * 676 + p1] = lrelu(dA[3] + sb1[co1]);
        sact[(co0 + 8) * 676 + p1] = lrelu(dB[2] + sb1[co0 + 8]);
        sact[(co1 + 8) * 676 + p1] = lrelu(dB[3] + sb1[co1 + 8]);
      }
    }
  }
  __syncthreads();

  // ---- phase 2: gaze26 in-place (row per thread, 416 items = 1/thread) ----
  for (int i = tid; i < 416; i += TPB) {
    int c = i / 26, h = i - c * 26;
    float* row = sm + OFF_ACT26 + c * 676 + h * 26;
    const float* K = sm + OFF_K26;
    float a[26];
#pragma unroll
    for (int w = 0; w < 26; w++) a[w] = row[w];
    ull acc[14];
#pragma unroll
    for (int q = 0; q < 14; q++) acc[q] = 0ULL;
#pragma unroll
    for (int w = 0; w < 26; w++) {
      ull xx = pack2(a[w]);
      const ulonglong2* kr = (const ulonglong2*)(K + w * 28);
#pragma unroll
      for (int q = 0; q < 7; q++) {
        ulonglong2 kv = kr[q];
        ffma2(acc[2 * q], xx, kv.x);
        ffma2(acc[2 * q + 1], xx, kv.y);
      }
    }
#pragma unroll
    for (int q = 0; q < 13; q++) {
      float2 v = unpack2(acc[q]);
      row[2 * q] = v.x; row[2 * q + 1] = v.y;
    }
  }
  __syncthreads();

  // ---- phase 3: conv2 via mma.sync bf16-split (M=121,N=16,K=400), warp=tile ----
  {
    int warp = tid >> 5, lane = tid & 31;
    if (warp < 8) {
      int g = lane >> 2, tig = lane & 3;
      const float* sact = sm + OFF_ACT26;
      const int* kt = (const int*)(sm + OFF_KOFF);
      const uint4* wfrag = (const uint4*)(sm + OFF_W2F);
      int p0 = warp * 16 + g, p1 = p0 + 8;
      bool ok0 = p0 < 121, ok1 = p1 < 121;
      int oh0 = p0 / 11, ow0 = p0 - oh0 * 11;
      int oh1 = p1 / 11, ow1 = p1 - oh1 * 11;
      int pb0 = ok0 ? (oh0 * 52 + ow0 * 2) : 0;
      int pb1 = ok1 ? (oh1 * 52 + ow1 * 2) : 0;
      float dA[4] = {0.f, 0.f, 0.f, 0.f};
      float dB[4] = {0.f, 0.f, 0.f, 0.f};
      int k0 = tig * 2;
      for (int s = 0; s < 25; s++, k0 += 16) {
        uint4 B0 = wfrag[(s * 2 + 0) * 32 + lane];
        uint4 B1 = wfrag[(s * 2 + 1) * 32 + lane];
        int o0 = kt[k0], o1 = kt[k0 + 1], o2 = kt[k0 + 8], o3 = kt[k0 + 9];
        float e00 = ok0 ? sact[o0 + pb0] : 0.f, e01 = ok0 ? sact[o1 + pb0] : 0.f;
        float e02 = ok0 ? sact[o2 + pb0] : 0.f, e03 = ok0 ? sact[o3 + pb0] : 0.f;
        float e10 = ok1 ? sact[o0 + pb1] : 0.f, e11 = ok1 ? sact[o1 + pb1] : 0.f;
        float e12 = ok1 ? sact[o2 + pb1] : 0.f, e13 = ok1 ? sact[o3 + pb1] : 0.f;
        float fx[4] = {e00, e10, e02, e12};
        float fy[4] = {e01, e11, e03, e13};
        unsigned ah[4], al[4];
#pragma unroll
        for (int q = 0; q < 4; q++) {
          unsigned xb = __float_as_uint(fx[q]), yb = __float_as_uint(fy[q]);
          ah[q] = __byte_perm(xb, yb, 0x7632);
          float lx = fx[q] - __uint_as_float(xb & 0xffff0000u);
          float ly = fy[q] - __uint_as_float(yb & 0xffff0000u);
          al[q] = bf2pack(ly, lx);
        }
        MMA_BF16(dA[0], dA[1], dA[2], dA[3], ah[0], ah[1], ah[2], ah[3], B0.x, B0.y);
        MMA_BF16(dA[0], dA[1], dA[2], dA[3], ah[0], ah[1], ah[2], ah[3], B0.z, B0.w);
        MMA_BF16(dA[0], dA[1], dA[2], dA[3], al[0], al[1], al[2], al[3], B0.x, B0.y);
        MMA_BF16(dB[0], dB[1], dB[2], dB[3], ah[0], ah[1], ah[2], ah[3], B1.x, B1.y);
        MMA_BF16(dB[0], dB[1], dB[2], dB[3], ah[0], ah[1], ah[2], ah[3], B1.z, B1.w);
        MMA_BF16(dB[0], dB[1], dB[2], dB[3], al[0], al[1], al[2], al[3], B1.x, B1.y);
      }
      float* act11 = sm + OFF_ACT11;
      const float* sb2 = sm + OFF_SB2;
      int co0 = tig * 2, co1 = co0 + 1;
      if (ok0) {
        act11[co0 * 121 + p0] = lrelu(dA[0] + sb2[co0]);
        act11[co1 * 121 + p0] = lrelu(dA[1] + sb2[co1]);
        act11[(co0 + 8) * 121 + p0] = lrelu(dB[0] + sb2[co0 + 8]);
        act11[(co1 + 8) * 121 + p0] = lrelu(dB[1] + sb2[co1 + 8]);
      }
      if (ok1) {
        act11[co0 * 121 + p1] = lrelu(dA[2] + sb2[co0]);
        act11[co1 * 121 + p1] = lrelu(dA[3] + sb2[co1]);
        act11[(co0 + 8) * 121 + p1] = lrelu(dB[2] + sb2[co0 + 8]);
        act11[(co1 + 8) * 121 + p1] = lrelu(dB[3] + sb2[co1 + 8]);
      }
    }
  }
  __syncthreads();

  // ---- phase 4: gaze11 in-place (176) ----
  if (tid < 176) {
    int c = tid / 11, h = tid - c * 11;
    float* row = sm + OFF_ACT11 + c * 121 + h * 11;
    const float* K = sm + OFF_K11;
    float a[11];
#pragma unroll
    for (int w = 0; w < 11; w++) a[w] = row[w];
    ull acc[6];
#pragma unroll
    for (int q = 0; q < 6; q++) acc[q] = 0ULL;
#pragma unroll
    for (int w = 0; w < 11; w++) {
      ull xx = pack2(a[w]);
      const ulonglong2* kr = (const ulonglong2*)(K + w * 12);
#pragma unroll
      for (int q = 0; q < 3; q++) {
        ulonglong2 kv = kr[q];
        ffma2(acc[2 * q], xx, kv.x);
        ffma2(acc[2 * q + 1], xx, kv.y);
      }
    }
#pragma unroll
    for (int q = 0; q < 5; q++) {
      float2 v = unpack2(acc[q]);
      row[2 * q] = v.x; row[2 * q + 1] = v.y;
    }
    row[10] = unpack2(acc[5]).x;
  }
  __syncthreads();

  // ---- phase 5: conv3 3x3 16->16, leaky. px x co-half (162) ----
  if (tid < 162) {
    int half = tid & 1, p = tid >> 1;
    int oh = p / 9, ow = p - oh * 9;
    ull acc[4] = {0ULL, 0ULL, 0ULL, 0ULL};
    const float* w3t = sm + OFF_W3T;
    const float* act11 = sm + OFF_ACT11;
    for (int ci = 0; ci < 16; ci++) {
      const float* irow = act11 + ci * 121;
#pragma unroll
      for (int kh = 0; kh < 3; kh++) {
        const float* ir = irow + (oh + kh) * 11 + ow;
#pragma unroll
        for (int kw = 0; kw < 3; kw++) {
          ull xx = pack2(ir[kw]);
          const ulonglong2* wq =
              (const ulonglong2*)(w3t + (ci * 9 + kh * 3 + kw) * 16 + half * 8);
          ulonglong2 q0 = wq[0], q1 = wq[1];
          ffma2(acc[0], xx, q0.x); ffma2(acc[1], xx, q0.y);
          ffma2(acc[2], xx, q1.x); ffma2(acc[3], xx, q1.y);
        }
      }
    }
    float* act9 = sm + OFF_ACT9;
    const float* sb3 = sm + OFF_SB3;
#pragma unroll
    for (int q = 0; q < 4; q++) {
      float2 v = unpack2(acc[q]);
      int co = half * 8 + 2 * q;
      act9[co * 81 + p]       = lrelu(v.x + sb3[co]);
      act9[(co + 1) * 81 + p] = lrelu(v.y + sb3[co + 1]);
    }
  }
  __syncthreads();

  // ---- phase 6: conv4 3x3 16->16, leaky -> g_xf + cm. px x co-half (98) ----
  if (tid < 98) {
    int half = tid & 1, p = tid >> 1;
    int oh = p / 7, ow = p - oh * 7;
    ull acc[4] = {0ULL, 0ULL, 0ULL, 0ULL};
    const float* w4t = sm + OFF_W4T;
    const float* act9 = sm + OFF_ACT9;
    for (int ci = 0; ci < 16; ci++) {
      const float* irow = act9 + ci * 81;
#pragma unroll
      for (int kh = 0; kh < 3; kh++) {
        const float* ir = irow + (oh + kh) * 9 + ow;
#pragma unroll
        for (int kw = 0; kw < 3; kw++) {
          ull xx = pack2(ir[kw]);
          const ulonglong2* wq =
              (const ulonglong2*)(w4t + (ci * 9 + kh * 3 + kw) * 16 + half * 8);
          ulonglong2 q0 = wq[0], q1 = wq[1];
          ffma2(acc[0], xx, q0.x); ffma2(acc[1], xx, q0.y);
          ffma2(acc[2], xx, q1.x); ffma2(acc[3], xx, q1.y);
        }
      }
    }
    const float* sb4 = sm + OFF_SB4;
    float* xp = g_xf + (size_t)n * 784 + p;
    float cs = 0.f;
#pragma unroll
    for (int q = 0; q < 4; q++) {
      float2 v = unpack2(acc[q]);
      int co = half * 8 + 2 * q;
      float v0 = lrelu(v.x + sb4[co]);
      float v1 = lrelu(v.y + sb4[co + 1]);
      xp[co * 49] = v0;
      xp[(co + 1) * 49] = v1;
      cs += v0 + v1;
    }
    sm[OFF_SCM + tid] = cs;
  }
  __syncthreads();
  if (tid < 49)
    g_cm[(size_t)n * 49 + tid] = sm[OFF_SCM + 2 * tid] + sm[OFF_SCM + 2 * tid + 1];
}

// ---------------- fc ----------------
__global__ __launch_bounds__(256) void k_fc(const float* __restrict__ w1,
                                            const float* __restrict__ b1,
                                            const float* __restrict__ w2,
                                            const float* __restrict__ b2) {
  __shared__ float As[64][17];
  __shared__ float Bs[16][68];
  __shared__ float prs[16][64];
  int tid = threadIdx.x;
  int s0 = blockIdx.x * 64;
  int sg = tid >> 4, jg = tid & 15;
  float acc[4][4];
#pragma unroll
  for (int i = 0; i < 4; i++)
#pragma unroll
    for (int u = 0; u < 4; u++) acc[i][u] = 0.f;
  for (int k0 = 0; k0 < 784; k0 += 16) {
    for (int i = tid; i < 1024; i += 256) {
      int s = i >> 4, kk = i & 15;
      As[s][kk] = g_xf[(size_t)(s0 + s) * 784 + k0 + kk];
    }
    for (int i = tid; i < 1024; i += 256) {
      int j = i >> 4, kk = i & 15;
      Bs[kk][j] = w1[j * 784 + k0 + kk];
    }
    __syncthreads();
#pragma unroll
    for (int kk = 0; kk < 16; kk++) {
      float av[4], bv[4];
#pragma unroll
      for (int i = 0; i < 4; i++) av[i] = As[sg * 4 + i][kk];
#pragma unroll
      for (int u = 0; u < 4; u++) bv[u] = Bs[kk][jg * 4 + u];
#pragma unroll
      for (int i = 0; i < 4; i++)
#pragma unroll
        for (int u = 0; u < 4; u++) acc[i][u] += av[i] * bv[u];
    }
    __syncthreads();
  }
#pragma unroll
  for (int i = 0; i < 4; i++) {
    float pr = 0.f;
#pragma unroll
    for (int u = 0; u < 4; u++) {
      int j = jg * 4 + u;
      float h = acc[i][u] + b1[j];
      h = lrelu(h);
      pr += h * w2[j];
    }
    prs[jg][sg * 4 + i] = pr;
  }
  __syncthreads();
  if (tid < 64) {
    float s = 0.f;
#pragma unroll
    for (int j = 0; j < 16; j++) s += prs[j][tid];
    g_r[s0 + tid] = s + b2[0];
  }
}

__global__ void k_reduce_r(float* __restrict__ out) {
  __shared__ float sab[64];
  int tid = threadIdx.x;
  int traj = tid >> 5, b = tid & 31;
  float s = 0.f, sa = 0.f;
  for (int t = 0; t < 64; t++) {
    float r = g_r[traj * 2048 + t * 32 + b];
    s += r;
    sa += fabsf(r);
  }
  out[tid] = s;
  sab[tid] = sa;
  __syncthreads();
  if (tid < 32) out[64 + tid] = sab[tid] + sab[32 + tid];
}

__global__ __launch_bounds__(256) void k_cmnorm(float* __restrict__ out) {
  __shared__ float sv[1568];
  __shared__ float smn[8], smx[8];
  __shared__ float fmn, fmx;
  int idx = blockIdx.x;
  int traj = idx >> 6, t = idx & 63;
  int tid = threadIdx.x;
  const float* base = g_cm + ((size_t)(traj * 2048 + t * 32)) * 49;
  float mn = 1e30f, mx = -1e30f;
  for (int i = tid; i < 1568; i += 256) {
    float v = base[i];
    sv[i] = v;
    mn = fminf(mn, v);
    mx = fmaxf(mx, v);
  }
#pragma unroll
  for (int o = 16; o; o >>= 1) {
    mn = fminf(mn, __shfl_xor_sync(0xffffffffu, mn, o));
    mx = fmaxf(mx, __shfl_xor_sync(0xffffffffu, mx, o));
  }
  if ((tid & 31) == 0) { smn[tid >> 5] = mn; smx[tid >> 5] = mx; }
  __syncthreads();
  if (tid == 0) {
    float a = smn[0], bb = smx[0];
    for (int i = 1; i < 8; i++) { a = fminf(a, smn[i]); bb = fmaxf(bb, smx[i]); }
    fmn = a; fmx = bb;
  }
  __syncthreads();
  float m = fmn, inv = 1.f / (fmx - m);
  float* o = out + 96 + (size_t)traj * 100352 + (size_t)t * 1568;
  for (int i = tid; i < 1568; i += 256) o[i] = (sv[i] - m) * inv;
}

extern "C" void kernel_launch(void* const* d_in, const int* in_sizes, int n_in,
                              void* d_out, int out_size) {
  const float* ti   = (const float*)d_in[0];
  const float* tj   = (const float*)d_in[1];
  const float* g26i = (const float*)d_in[2];
  const float* g11i = (const float*)d_in[3];
  const float* g26j = (const float*)d_in[4];
  const float* g11j = (const float*)d_in[5];
  const float* w1 = (const float*)d_in[6];  const float* b1 = (const float*)d_in[7];
  const float* w2 = (const float*)d_in[8];  const float* b2 = (const float*)d_in[9];
  const float* w3 = (const float*)d_in[10]; const float* b3 = (const float*)d_in[11];
  const float* w4 = (const float*)d_in[12]; const float* b4 = (const float*)d_in[13];
  const float* f1w = (const float*)d_in[14]; const float* f1b = (const float*)d_in[15];
  const float* f2w = (const float*)d_in[16]; const float* f2b = (const float*)d_in[17];
  float* out = (float*)d_out;

  cudaFuncSetAttribute(k_net, cudaFuncAttributeMaxDynamicSharedMemorySize,
                       SMEM_FLOATS * 4);

  k_prep<<<4, 512>>>(w1, w2, w3, w4);
  k_net<<<NTOT, TPB, SMEM_FLOATS * 4>>>(ti, tj, g26i, g26j, g11i, g11j,
                                        b1, b2, b3, b4);
  k_fc<<<NTOT / 64, 256>>>(f1w, f1b, f2w, f2b);
  k_reduce_r<<<1, 64>>>(out);
  k_cmnorm<<<128, 256>>>(out);
}

// round 14
// speedup vs baseline: 1.4944x; 1.0640x over previous
#include <cuda_runtime.h>
#include <math.h>

#define NPT 2048
#define NTOT 4096
#define TPB 416
typedef unsigned long long ull;

__device__ float g_xf[(size_t)NTOT * 784];
__device__ float g_cm[(size_t)NTOT * 49];
__device__ float g_r[NTOT];
// bf16-split fragment-ready weights (built once by k_prep)
__device__ uint4 g_w1frag[832];   // conv1 [s13][nt2][lane32]
__device__ uint4 g_w2frag[1600];  // conv2 [s25][nt2][lane32]
__device__ uint4 g_w3frag[576];   // conv3 [s9][nt2][lane32]
__device__ uint4 g_w4frag[576];   // conv4 [s9][nt2][lane32]

__device__ __forceinline__ float lrelu(float v) { return v >= 0.f ? v : 0.01f * v; }
__device__ __forceinline__ ull pack2(float x) {
  ull r; asm("mov.b64 %0,{%1,%1};" : "=l"(r) : "f"(x)); return r;
}
__device__ __forceinline__ void ffma2(ull& d, ull a, ull b) {
  asm("fma.rn.f32x2 %0,%1,%2,%0;" : "+l"(d) : "l"(a), "l"(b));
}
__device__ __forceinline__ float2 unpack2(ull v) {
  float2 r; asm("mov.b64 {%0,%1},%2;" : "=f"(r.x), "=f"(r.y) : "l"(v)); return r;
}
__device__ __forceinline__ unsigned bf2pack(float hi_elem, float lo_elem) {
  unsigned u; asm("cvt.rn.bf16x2.f32 %0, %1, %2;" : "=r"(u) : "f"(hi_elem), "f"(lo_elem));
  return u;
}
#define MMA_BF16(d0,d1,d2,d3,a0,a1,a2,a3,b0,b1) \
  asm("mma.sync.aligned.m16n8k16.row.col.f32.bf16.bf16.f32 " \
      "{%0,%1,%2,%3},{%4,%5,%6,%7},{%8,%9},{%0,%1,%2,%3};" \
      : "+f"(d0),"+f"(d1),"+f"(d2),"+f"(d3) \
      : "r"(a0),"r"(a1),"r"(a2),"r"(a3),"r"(b0),"r"(b1))

// split one fp32 pair (fx,fy) into hi-bf16x2 / lo-bf16x2
#define SPLIT_PAIR(fx, fy, hi, lo_) do { \
  unsigned xb = __float_as_uint(fx), yb = __float_as_uint(fy); \
  hi = __byte_perm(xb, yb, 0x7632); \
  float lx = (fx) - __uint_as_float(xb & 0xffff0000u); \
  float ly = (fy) - __uint_as_float(yb & 0xffff0000u); \
  lo_ = bf2pack(ly, lx); \
} while (0)

// smem float offsets (26864 floats = 107456 B -> 2 blocks/SM)
#define OFF_ACT26 0        // 10816
#define OFF_W2F   10816    // 6400 (1600 uint4)
#define OFF_W3F   17216    // 2304 (576 uint4)
#define OFF_W4F   19520    // 2304 (576 uint4)
#define OFF_K26   21824    // 728
#define OFF_K11   22552    // 132
#define OFF_ACT11 22684    // 1936
#define OFF_ACT9  24620    // 1296
#define OFF_SB1   25916
#define OFF_SB2   25932
#define OFF_SB3   25948
#define OFF_SB4   25964
#define OFF_SCM   25980    // 196 (49 px * 4 partials)
#define OFF_KOFF  26176    // 400 ints (conv2)
#define OFF_KT3   26576    // 144 ints
#define OFF_KT4   26720    // 144 ints
#define SMEM_FLOATS 26864

__device__ __forceinline__ int koff(int k) {
  int ci = k & 3, t = k >> 2;
  int kw = t % 7, kh = t / 7;
  return kh * 336 + kw * 4 + ci;
}

// ---------------- one-time weight prep ----------------
__global__ void k_prep(const float* __restrict__ w1, const float* __restrict__ w2,
                       const float* __restrict__ w3, const float* __restrict__ w4) {
  int tid = blockIdx.x * blockDim.x + threadIdx.x;
  // conv1 fragments (K=196, zero-padded to 208)
  for (int idx = tid; idx < 832; idx += 2048) {
    int lane = idx & 31, sn = idx >> 5;
    int s = sn >> 1, nt = sn & 1;
    int tig = lane & 3, gq = lane >> 2;
    int co = nt * 8 + gq;
    float wv[4];
    int k0 = s * 16 + tig * 2;
#pragma unroll
    for (int e = 0; e < 4; e++) {
      int k = k0 + (e >> 1) * 8 + (e & 1);
      float w = 0.f;
      if (k < 196) {
        int ci = k & 3, t = k >> 2, kw = t % 7, kh = t / 7;
        w = w1[co * 196 + ci * 49 + kh * 7 + kw];
      }
      wv[e] = w;
    }
    unsigned hb[4]; float lo[4];
#pragma unroll
    for (int e = 0; e < 4; e++) {
      hb[e] = __float_as_uint(wv[e]) & 0xffff0000u;
      lo[e] = wv[e] - __uint_as_float(hb[e]);
    }
    uint4 out;
    out.x = (hb[0] >> 16) | (hb[1] & 0xffff0000u);
    out.y = (hb[2] >> 16) | (hb[3] & 0xffff0000u);
    out.z = bf2pack(lo[1], lo[0]);
    out.w = bf2pack(lo[3], lo[2]);
    g_w1frag[idx] = out;
  }
  // conv2 fragments (K=400 exact)
  for (int idx = tid; idx < 1600; idx += 2048) {
    int lane = idx & 31, sn = idx >> 5;
    int s = sn >> 1, nt = sn & 1;
    int tig = lane & 3, gq = lane >> 2;
    int co = nt * 8 + gq;
    float wv[4];
    int k0 = s * 16 + tig * 2;
#pragma unroll
    for (int e = 0; e < 4; e++) {
      int k = k0 + (e >> 1) * 8 + (e & 1);
      wv[e] = w2[co * 400 + k];
    }
    unsigned hb[4]; float lo[4];
#pragma unroll
    for (int e = 0; e < 4; e++) {
      hb[e] = __float_as_uint(wv[e]) & 0xffff0000u;
      lo[e] = wv[e] - __uint_as_float(hb[e]);
    }
    uint4 out;
    out.x = (hb[0] >> 16) | (hb[1] & 0xffff0000u);
    out.y = (hb[2] >> 16) | (hb[3] & 0xffff0000u);
    out.z = bf2pack(lo[1], lo[0]);
    out.w = bf2pack(lo[3], lo[2]);
    g_w2frag[idx] = out;
  }
  // conv3/conv4 fragments (K=144 exact; k = ci*9+kh*3+kw -> w[co*144+k])
  for (int idx = tid; idx < 1152; idx += 2048) {
    int which = idx >= 576;
    int id2 = idx - which * 576;
    const float* w = which ? w4 : w3;
    int lane = id2 & 31, sn = id2 >> 5;
    int s = sn >> 1, nt = sn & 1;
    int tig = lane & 3, gq = lane >> 2;
    int co = nt * 8 + gq;
    float wv[4];
    int k0 = s * 16 + tig * 2;
#pragma unroll
    for (int e = 0; e < 4; e++) {
      int k = k0 + (e >> 1) * 8 + (e & 1);
      wv[e] = w[co * 144 + k];
    }
    unsigned hb[4]; float lo[4];
#pragma unroll
    for (int e = 0; e < 4; e++) {
      hb[e] = __float_as_uint(wv[e]) & 0xffff0000u;
      lo[e] = wv[e] - __uint_as_float(hb[e]);
    }
    uint4 out;
    out.x = (hb[0] >> 16) | (hb[1] & 0xffff0000u);
    out.y = (hb[2] >> 16) | (hb[3] & 0xffff0000u);
    out.z = bf2pack(lo[1], lo[0]);
    out.w = bf2pack(lo[3], lo[2]);
    if (which) g_w4frag[id2] = out; else g_w3frag[id2] = out;
  }
}

__global__ __launch_bounds__(TPB, 2) void k_net(
    const float* __restrict__ ti, const float* __restrict__ tj,
    const float* __restrict__ g26i, const float* __restrict__ g26j,
    const float* __restrict__ g11i, const float* __restrict__ g11j,
    const float* __restrict__ b1, const float* __restrict__ b2,
    const float* __restrict__ b3, const float* __restrict__ b4) {
  extern __shared__ float sm[];
  int n = blockIdx.x, tid = threadIdx.x;
  const float sc = 1.0f / (0.7f * 0.3f);

  const float* x   = (n < NPT) ? ti   + (size_t)n * 28224 : tj   + (size_t)(n - NPT) * 28224;
  const float* g26 = (n < NPT) ? g26i + (size_t)n * 676   : g26j + (size_t)(n - NPT) * 676;
  const float* g11 = (n < NPT) ? g11i + (size_t)n * 121   : g11j + (size_t)(n - NPT) * 121;

  // ---- phase 0: fragments / tables / gaze kernels ----
  {
    uint4* w2f = (uint4*)(sm + OFF_W2F);
    for (int i = tid; i < 1600; i += TPB) w2f[i] = g_w2frag[i];
    uint4* w3f = (uint4*)(sm + OFF_W3F);
    for (int i = tid; i < 576; i += TPB) w3f[i] = g_w3frag[i];
    uint4* w4f = (uint4*)(sm + OFF_W4F);
    for (int i = tid; i < 576; i += TPB) w4f[i] = g_w4frag[i];
  }
  for (int i = tid; i < 728; i += TPB) {
    int wdx = i / 28, k = i - wdx * 28;
    sm[OFF_K26 + i] = (k < 26) ? (g26[wdx * 26 + k] - 0.3f) * sc : 0.f;
  }
  for (int i = tid; i < 132; i += TPB) {
    int wdx = i / 12, k = i - wdx * 12;
    sm[OFF_K11 + i] = (k < 11) ? (g11[wdx * 11 + k] - 0.3f) * sc : 0.f;
  }
  {
    int* kt = (int*)(sm + OFF_KOFF);
    for (int k = tid; k < 400; k += TPB) {
      int ci = k / 25, t = k - ci * 25, kh = t / 5, kw = t - kh * 5;
      kt[k] = ci * 676 + kh * 26 + kw;
    }
    int* kt3 = (int*)(sm + OFF_KT3);
    int* kt4 = (int*)(sm + OFF_KT4);
    for (int k = tid; k < 144; k += TPB) {
      int ci = k / 9, t = k - ci * 9, kh = t / 3, kw = t - kh * 3;
      kt3[k] = ci * 121 + kh * 11 + kw;
      kt4[k] = ci * 81 + kh * 9 + kw;
    }
  }
  if (tid < 16) {
    sm[OFF_SB1 + tid] = b1[tid]; sm[OFF_SB2 + tid] = b2[tid];
    sm[OFF_SB3 + tid] = b3[tid]; sm[OFF_SB4 + tid] = b4[tid];
  }
  __syncthreads();

  int warp = tid >> 5, lane = tid & 31;
  int g = lane >> 2, tig = lane & 3;

  // ---- phase 1: conv1 MMA (M=676, N=16, K=196) ----
  {
    const float* sb1 = sm + OFF_SB1;
    float* sact = sm + OFF_ACT26;
    for (int pass = 0; pass < 4; pass++) {
      int tile = pass * 13 + warp;
      if (tile >= 43) break;
      float dA[4] = {0.f, 0.f, 0.f, 0.f};
      float dB[4] = {0.f, 0.f, 0.f, 0.f};
      int p0 = tile * 16 + g, p1 = p0 + 8;
      bool ok0 = p0 < 676, ok1 = p1 < 676;
      int oh0 = p0 / 26, ow0 = p0 - oh0 * 26;
      int oh1 = p1 / 26, ow1 = p1 - oh1 * 26;
      int base0 = ok0 ? (oh0 * 1008 + ow0 * 12) : 0;
      int base1 = ok1 ? (oh1 * 1008 + ow1 * 12) : 0;
      for (int s = 0; s < 13; s++) {
        int k0 = s * 16 + tig * 2;
        int k8 = k0 + 8;
        bool k01ok = k0 < 196, k89ok = k8 < 196;
        int off01 = koff(k01ok ? k0 : 0);
        int off89 = koff(k89ok ? k8 : 0);
        uint4 B0 = g_w1frag[(s * 2 + 0) * 32 + lane];
        uint4 B1 = g_w1frag[(s * 2 + 1) * 32 + lane];
        float2 v[4];
        v[0] = (ok0 && k01ok) ? *(const float2*)(x + base0 + off01) : make_float2(0.f, 0.f);
        v[1] = (ok1 && k01ok) ? *(const float2*)(x + base1 + off01) : make_float2(0.f, 0.f);
        v[2] = (ok0 && k89ok) ? *(const float2*)(x + base0 + off89) : make_float2(0.f, 0.f);
        v[3] = (ok1 && k89ok) ? *(const float2*)(x + base1 + off89) : make_float2(0.f, 0.f);
        unsigned ah[4], al[4];
#pragma unroll
        for (int q = 0; q < 4; q++) SPLIT_PAIR(v[q].x, v[q].y, ah[q], al[q]);
        MMA_BF16(dA[0], dA[1], dA[2], dA[3], ah[0], ah[1], ah[2], ah[3], B0.x, B0.y);
        MMA_BF16(dA[0], dA[1], dA[2], dA[3], ah[0], ah[1], ah[2], ah[3], B0.z, B0.w);
        MMA_BF16(dA[0], dA[1], dA[2], dA[3], al[0], al[1], al[2], al[3], B0.x, B0.y);
        MMA_BF16(dB[0], dB[1], dB[2], dB[3], ah[0], ah[1], ah[2], ah[3], B1.x, B1.y);
        MMA_BF16(dB[0], dB[1], dB[2], dB[3], ah[0], ah[1], ah[2], ah[3], B1.z, B1.w);
        MMA_BF16(dB[0], dB[1], dB[2], dB[3], al[0], al[1], al[2], al[3], B1.x, B1.y);
      }
      int co0 = tig * 2, co1 = co0 + 1;
      if (ok0) {
        sact[co0 * 676 + p0] = lrelu(dA[0] + sb1[co0]);
        sact[co1 * 676 + p0] = lrelu(dA[1] + sb1[co1]);
        sact[(co0 + 8) * 676 + p0] = lrelu(dB[0] + sb1[co0 + 8]);
        sact[(co1 + 8) * 676 + p0] = lrelu(dB[1] + sb1[co1 + 8]);
      }
      if (ok1) {
        sact[co0 * 676 + p1] = lrelu(dA[2] + sb1[co0]);
        sact[co1 * 676 + p1] = lrelu(dA[3] + sb1[co1]);
        sact[(co0 + 8) * 676 + p1] = lrelu(dB[2] + sb1[co0 + 8]);
        sact[(co1 + 8) * 676 + p1] = lrelu(dB[3] + sb1[co1 + 8]);
      }
    }
  }
  __syncthreads();

  // ---- phase 2: gaze26 in-place (416 rows = 1/thread) ----
  for (int i = tid; i < 416; i += TPB) {
    int c = i / 26, h = i - c * 26;
    float* row = sm + OFF_ACT26 + c * 676 + h * 26;
    const float* K = sm + OFF_K26;
    float a[26];
#pragma unroll
    for (int w = 0; w < 26; w++) a[w] = row[w];
    ull acc[14];
#pragma unroll
    for (int q = 0; q < 14; q++) acc[q] = 0ULL;
#pragma unroll
    for (int w = 0; w < 26; w++) {
      ull xx = pack2(a[w]);
      const ulonglong2* kr = (const ulonglong2*)(K + w * 28);
#pragma unroll
      for (int q = 0; q < 7; q++) {
        ulonglong2 kv = kr[q];
        ffma2(acc[2 * q], xx, kv.x);
        ffma2(acc[2 * q + 1], xx, kv.y);
      }
    }
#pragma unroll
    for (int q = 0; q < 13; q++) {
      float2 v = unpack2(acc[q]);
      row[2 * q] = v.x; row[2 * q + 1] = v.y;
    }
  }
  __syncthreads();

  // ---- phase 3: conv2 MMA (M=121, N=16, K=400), warps 0-7 ----
  if (warp < 8) {
    const float* sact = sm + OFF_ACT26;
    const int* kt = (const int*)(sm + OFF_KOFF);
    const uint4* wfrag = (const uint4*)(sm + OFF_W2F);
    int p0 = warp * 16 + g, p1 = p0 + 8;
    bool ok0 = p0 < 121, ok1 = p1 < 121;
    int oh0 = p0 / 11, ow0 = p0 - oh0 * 11;
    int oh1 = p1 / 11, ow1 = p1 - oh1 * 11;
    int pb0 = ok0 ? (oh0 * 52 + ow0 * 2) : 0;
    int pb1 = ok1 ? (oh1 * 52 + ow1 * 2) : 0;
    float dA[4] = {0.f, 0.f, 0.f, 0.f};
    float dB[4] = {0.f, 0.f, 0.f, 0.f};
    int k0 = tig * 2;
    for (int s = 0; s < 25; s++, k0 += 16) {
      uint4 B0 = wfrag[(s * 2 + 0) * 32 + lane];
      uint4 B1 = wfrag[(s * 2 + 1) * 32 + lane];
      int o0 = kt[k0], o1 = kt[k0 + 1], o2 = kt[k0 + 8], o3 = kt[k0 + 9];
      float e00 = ok0 ? sact[o0 + pb0] : 0.f, e01 = ok0 ? sact[o1 + pb0] : 0.f;
      float e02 = ok0 ? sact[o2 + pb0] : 0.f, e03 = ok0 ? sact[o3 + pb0] : 0.f;
      float e10 = ok1 ? sact[o0 + pb1] : 0.f, e11 = ok1 ? sact[o1 + pb1] : 0.f;
      float e12 = ok1 ? sact[o2 + pb1] : 0.f, e13 = ok1 ? sact[o3 + pb1] : 0.f;
      unsigned ah[4], al[4];
      SPLIT_PAIR(e00, e01, ah[0], al[0]);
      SPLIT_PAIR(e10, e11, ah[1], al[1]);
      SPLIT_PAIR(e02, e03, ah[2], al[2]);
      SPLIT_PAIR(e12, e13, ah[3], al[3]);
      MMA_BF16(dA[0], dA[1], dA[2], dA[3], ah[0], ah[1], ah[2], ah[3], B0.x, B0.y);
      MMA_BF16(dA[0], dA[1], dA[2], dA[3], ah[0], ah[1], ah[2], ah[3], B0.z, B0.w);
      MMA_BF16(dA[0], dA[1], dA[2], dA[3], al[0], al[1], al[2], al[3], B0.x, B0.y);
      MMA_BF16(dB[0], dB[1], dB[2], dB[3], ah[0], ah[1], ah[2], ah[3], B1.x, B1.y);
      MMA_BF16(dB[0], dB[1], dB[2], dB[3], ah[0], ah[1], ah[2], ah[3], B1.z, B1.w);
      MMA_BF16(dB[0], dB[1], dB[2], dB[3], al[0], al[1], al[2], al[3], B1.x, B1.y);
    }
    float* act11 = sm + OFF_ACT11;
    const float* sb2 = sm + OFF_SB2;
    int co0 = tig * 2, co1 = co0 + 1;
    if (ok0) {
      act11[co0 * 121 + p0] = lrelu(dA[0] + sb2[co0]);
      act11[co1 * 121 + p0] = lrelu(dA[1] + sb2[co1]);
      act11[(co0 + 8) * 121 + p0] = lrelu(dB[0] + sb2[co0 + 8]);
      act11[(co1 + 8) * 121 + p0] = lrelu(dB[1] + sb2[co1 + 8]);
    }
    if (ok1) {
      act11[co0 * 121 + p1] = lrelu(dA[2] + sb2[co0]);
      act11[co1 * 121 + p1] = lrelu(dA[3] + sb2[co1]);
      act11[(co0 + 8) * 121 + p1] = lrelu(dB[2] + sb2[co0 + 8]);
      act11[(co1 + 8) * 121 + p1] = lrelu(dB[3] + sb2[co1 + 8]);
    }
  }
  __syncthreads();

  // ---- phase 4: gaze11 in-place (176) ----
  if (tid < 176) {
    int c = tid / 11, h = tid - c * 11;
    float* row = sm + OFF_ACT11 + c * 121 + h * 11;
    const float* K = sm + OFF_K11;
    float a[11];
#pragma unroll
    for (int w = 0; w < 11; w++) a[w] = row[w];
    ull acc[6];
#pragma unroll
    for (int q = 0; q < 6; q++) acc[q] = 0ULL;
#pragma unroll
    for (int w = 0; w < 11; w++) {
      ull xx = pack2(a[w]);
      const ulonglong2* kr = (const ulonglong2*)(K + w * 12);
#pragma unroll
      for (int q = 0; q < 3; q++) {
        ulonglong2 kv = kr[q];
        ffma2(acc[2 * q], xx, kv.x);
        ffma2(acc[2 * q + 1], xx, kv.y);
      }
    }
#pragma unroll
    for (int q = 0; q < 5; q++) {
      float2 v = unpack2(acc[q]);
      row[2 * q] = v.x; row[2 * q + 1] = v.y;
    }
    row[10] = unpack2(acc[5]).x;
  }
  __syncthreads();

  // ---- phase 5: conv3 MMA (M=81, N=16, K=144), warps 0-5 ----
  if (warp < 6) {
    const float* act11 = sm + OFF_ACT11;
    const int* kt3 = (const int*)(sm + OFF_KT3);
    const uint4* wfrag = (const uint4*)(sm + OFF_W3F);
    int p0 = warp * 16 + g, p1 = p0 + 8;
    bool ok0 = p0 < 81, ok1 = p1 < 81;
    int oh0 = p0 / 9, ow0 = p0 - oh0 * 9;
    int oh1 = p1 / 9, ow1 = p1 - oh1 * 9;
    int pb0 = ok0 ? (oh0 * 11 + ow0) : 0;
    int pb1 = ok1 ? (oh1 * 11 + ow1) : 0;
    float dA[4] = {0.f, 0.f, 0.f, 0.f};
    float dB[4] = {0.f, 0.f, 0.f, 0.f};
    int k0 = tig * 2;
    for (int s = 0; s < 9; s++, k0 += 16) {
      uint4 B0 = wfrag[(s * 2 + 0) * 32 + lane];
      uint4 B1 = wfrag[(s * 2 + 1) * 32 + lane];
      int o0 = kt3[k0], o1 = kt3[k0 + 1], o2 = kt3[k0 + 8], o3 = kt3[k0 + 9];
      float e00 = ok0 ? act11[o0 + pb0] : 0.f, e01 = ok0 ? act11[o1 + pb0] : 0.f;
      float e02 = ok0 ? act11[o2 + pb0] : 0.f, e03 = ok0 ? act11[o3 + pb0] : 0.f;
      float e10 = ok1 ? act11[o0 + pb1] : 0.f, e11 = ok1 ? act11[o1 + pb1] : 0.f;
      float e12 = ok1 ? act11[o2 + pb1] : 0.f, e13 = ok1 ? act11[o3 + pb1] : 0.f;
      unsigned ah[4], al[4];
      SPLIT_PAIR(e00, e01, ah[0], al[0]);
      SPLIT_PAIR(e10, e11, ah[1], al[1]);
      SPLIT_PAIR(e02, e03, ah[2], al[2]);
      SPLIT_PAIR(e12, e13, ah[3], al[3]);
      MMA_BF16(dA[0], dA[1], dA[2], dA[3], ah[0], ah[1], ah[2], ah[3], B0.x, B0.y);
      MMA_BF16(dA[0], dA[1], dA[2], dA[3], ah[0], ah[1], ah[2], ah[3], B0.z, B0.w);
      MMA_BF16(dA[0], dA[1], dA[2], dA[3], al[0], al[1], al[2], al[3], B0.x, B0.y);
      MMA_BF16(dB[0], dB[1], dB[2], dB[3], ah[0], ah[1], ah[2], ah[3], B1.x, B1.y);
      MMA_BF16(dB[0], dB[1], dB[2], dB[3], ah[0], ah[1], ah[2], ah[3], B1.z, B1.w);
      MMA_BF16(dB[0], dB[1], dB[2], dB[3], al[0], al[1], al[2], al[3], B1.x, B1.y);
    }
    float* act9 = sm + OFF_ACT9;
    const float* sb3 = sm + OFF_SB3;
    int co0 = tig * 2, co1 = co0 + 1;
    if (ok0) {
      act9[co0 * 81 + p0] = lrelu(dA[0] + sb3[co0]);
      act9[co1 * 81 + p0] = lrelu(dA[1] + sb3[co1]);
      act9[(co0 + 8) * 81 + p0] = lrelu(dB[0] + sb3[co0 + 8]);
      act9[(co1 + 8) * 81 + p0] = lrelu(dB[1] + sb3[co1 + 8]);
    }
    if (ok1) {
      act9[co0 * 81 + p1] = lrelu(dA[2] + sb3[co0]);
      act9[co1 * 81 + p1] = lrelu(dA[3] + sb3[co1]);
      act9[(co0 + 8) * 81 + p1] = lrelu(dB[2] + sb3[co0 + 8]);
      act9[(co1 + 8) * 81 + p1] = lrelu(dB[3] + sb3[co1 + 8]);
    }
  }
  __syncthreads();

  // ---- phase 6: conv4 MMA (M=49, N=16, K=144), warps 0-3 -> g_xf + cm partials ----
  if (warp < 4) {
    const float* act9 = sm + OFF_ACT9;
    const int* kt4 = (const int*)(sm + OFF_KT4);
    const uint4* wfrag = (const uint4*)(sm + OFF_W4F);
    int p0 = warp * 16 + g, p1 = p0 + 8;
    bool ok0 = p0 < 49, ok1 = p1 < 49;
    int oh0 = p0 / 7, ow0 = p0 - oh0 * 7;
    int oh1 = p1 / 7, ow1 = p1 - oh1 * 7;
    int pb0 = ok0 ? (oh0 * 9 + ow0) : 0;
    int pb1 = ok1 ? (oh1 * 9 + ow1) : 0;
    float dA[4] = {0.f, 0.f, 0.f, 0.f};
    float dB[4] = {0.f, 0.f, 0.f, 0.f};
    int k0 = tig * 2;
    for (int s = 0; s < 9; s++, k0 += 16) {
      uint4 B0 = wfrag[(s * 2 + 0) * 32 + lane];
      uint4 B1 = wfrag[(s * 2 + 1) * 32 + lane];
      int o0 = kt4[k0], o1 = kt4[k0 + 1], o2 = kt4[k0 + 8], o3 = kt4[k0 + 9];
      float e00 = ok0 ? act9[o0 + pb0] : 0.f, e01 = ok0 ? act9[o1 + pb0] : 0.f;
      float e02 = ok0 ? act9[o2 + pb0] : 0.f, e03 = ok0 ? act9[o3 + pb0] : 0.f;
      float e10 = ok1 ? act9[o0 + pb1] : 0.f, e11 = ok1 ? act9[o1 + pb1] : 0.f;
      float e12 = ok1 ? act9[o2 + pb1] : 0.f, e13 = ok1 ? act9[o3 + pb1] : 0.f;
      unsigned ah[4], al[4];
      SPLIT_PAIR(e00, e01, ah[0], al[0]);
      SPLIT_PAIR(e10, e11, ah[1], al[1]);
      SPLIT_PAIR(e02, e03, ah[2], al[2]);
      SPLIT_PAIR(e12, e13, ah[3], al[3]);
      MMA_BF16(dA[0], dA[1], dA[2], dA[3], ah[0], ah[1], ah[2], ah[3], B0.x, B0.y);
      MMA_BF16(dA[0], dA[1], dA[2], dA[3], ah[0], ah[1], ah[2], ah[3], B0.z, B0.w);
      MMA_BF16(dA[0], dA[1], dA[2], dA[3], al[0], al[1], al[2], al[3], B0.x, B0.y);
      MMA_BF16(dB[0], dB[1], dB[2], dB[3], ah[0], ah[1], ah[2], ah[3], B1.x, B1.y);
      MMA_BF16(dB[0], dB[1], dB[2], dB[3], ah[0], ah[1], ah[2], ah[3], B1.z, B1.w);
      MMA_BF16(dB[0], dB[1], dB[2], dB[3], al[0], al[1], al[2], al[3], B1.x, B1.y);
    }
    const float* sb4 = sm + OFF_SB4;
    int co0 = tig * 2, co1 = co0 + 1;
    if (ok0) {
      float* xp = g_xf + (size_t)n * 784 + p0;
      float v0 = lrelu(dA[0] + sb4[co0]);
      float v1 = lrelu(dA[1] + sb4[co1]);
      float v2 = lrelu(dB[0] + sb4[co0 + 8]);
      float v3 = lrelu(dB[1] + sb4[co1 + 8]);
      xp[co0 * 49] = v0; xp[co1 * 49] = v1;
      xp[(co0 + 8) * 49] = v2; xp[(co1 + 8) * 49] = v3;
      sm[OFF_SCM + p0 * 4 + tig] = v0 + v1 + v2 + v3;
    }
    if (ok1) {
      float* xp = g_xf + (size_t)n * 784 + p1;
      float v0 = lrelu(dA[2] + sb4[co0]);
      float v1 = lrelu(dA[3] + sb4[co1]);
      float v2 = lrelu(dB[2] + sb4[co0 + 8]);
      float v3 = lrelu(dB[3] + sb4[co1 + 8]);
      xp[co0 * 49] = v0; xp[co1 * 49] = v1;
      xp[(co0 + 8) * 49] = v2; xp[(co1 + 8) * 49] = v3;
      sm[OFF_SCM + p1 * 4 + tig] = v0 + v1 + v2 + v3;
    }
  }
  __syncthreads();
  if (tid < 49) {
    const float* s4 = sm + OFF_SCM + tid * 4;
    g_cm[(size_t)n * 49 + tid] = (s4[0] + s4[1]) + (s4[2] + s4[3]);
  }
}

// ---------------- fc ----------------
__global__ __launch_bounds__(256) void k_fc(const float* __restrict__ w1,
                                            const float* __restrict__ b1,
                                            const float* __restrict__ w2,
                                            const float* __restrict__ b2) {
  __shared__ float As[64][17];
  __shared__ float Bs[16][68];
  __shared__ float prs[16][64];
  int tid = threadIdx.x;
  int s0 = blockIdx.x * 64;
  int sg = tid >> 4, jg = tid & 15;
  float acc[4][4];
#pragma unroll
  for (int i = 0; i < 4; i++)
#pragma unroll
    for (int u = 0; u < 4; u++) acc[i][u] = 0.f;
  for (int k0 = 0; k0 < 784; k0 += 16) {
    for (int i = tid; i < 1024; i += 256) {
      int s = i >> 4, kk = i & 15;
      As[s][kk] = g_xf[(size_t)(s0 + s) * 784 + k0 + kk];
    }
    for (int i = tid; i < 1024; i += 256) {
      int j = i >> 4, kk = i & 15;
      Bs[kk][j] = w1[j * 784 + k0 + kk];
    }
    __syncthreads();
#pragma unroll
    for (int kk = 0; kk < 16; kk++) {
      float av[4], bv[4];
#pragma unroll
      for (int i = 0; i < 4; i++) av[i] = As[sg * 4 + i][kk];
#pragma unroll
      for (int u = 0; u < 4; u++) bv[u] = Bs[kk][jg * 4 + u];
#pragma unroll
      for (int i = 0; i < 4; i++)
#pragma unroll
        for (int u = 0; u < 4; u++) acc[i][u] += av[i] * bv[u];
    }
    __syncthreads();
  }
#pragma unroll
  for (int i = 0; i < 4; i++) {
    float pr = 0.f;
#pragma unroll
    for (int u = 0; u < 4; u++) {
      int j = jg * 4 + u;
      float h = acc[i][u] + b1[j];
      h = lrelu(h);
      pr += h * w2[j];
    }
    prs[jg][sg * 4 + i] = pr;
  }
  __syncthreads();
  if (tid < 64) {
    float s = 0.f;
#pragma unroll
    for (int j = 0; j < 16; j++) s += prs[j][tid];
    g_r[s0 + tid] = s + b2[0];
  }
}

__global__ void k_reduce_r(float* __restrict__ out) {
  __shared__ float sab[64];
  int tid = threadIdx.x;
  int traj = tid >> 5, b = tid & 31;
  float s = 0.f, sa = 0.f;
  for (int t = 0; t < 64; t++) {
    float r = g_r[traj * 2048 + t * 32 + b];
    s += r;
    sa += fabsf(r);
  }
  out[tid] = s;
  sab[tid] = sa;
  __syncthreads();
  if (tid < 32) out[64 + tid] = sab[tid] + sab[32 + tid];
}

__global__ __launch_bounds__(256) void k_cmnorm(float* __restrict__ out) {
  __shared__ float sv[1568];
  __shared__ float smn[8], smx[8];
  __shared__ float fmn, fmx;
  int idx = blockIdx.x;
  int traj = idx >> 6, t = idx & 63;
  int tid = threadIdx.x;
  const float* base = g_cm + ((size_t)(traj * 2048 + t * 32)) * 49;
  float mn = 1e30f, mx = -1e30f;
  for (int i = tid; i < 1568; i += 256) {
    float v = base[i];
    sv[i] = v;
    mn = fminf(mn, v);
    mx = fmaxf(mx, v);
  }
#pragma unroll
  for (int o = 16; o; o >>= 1) {
    mn = fminf(mn, __shfl_xor_sync(0xffffffffu, mn, o));
    mx = fmaxf(mx, __shfl_xor_sync(0xffffffffu, mx, o));
  }
  if ((tid & 31) == 0) { smn[tid >> 5] = mn; smx[tid >> 5] = mx; }
  __syncthreads();
  if (tid == 0) {
    float a = smn[0], bb = smx[0];
    for (int i = 1; i < 8; i++) { a = fminf(a, smn[i]); bb = fmaxf(bb, smx[i]); }
    fmn = a; fmx = bb;
  }
  __syncthreads();
  float m = fmn, inv = 1.f / (fmx - m);
  float* o = out + 96 + (size_t)traj * 100352 + (size_t)t * 1568;
  for (int i = tid; i < 1568; i += 256) o[i] = (sv[i] - m) * inv;
}

extern "C" void kernel_launch(void* const* d_in, const int* in_sizes, int n_in,
                              void* d_out, int out_size) {
  const float* ti   = (const float*)d_in[0];
  const float* tj   = (const float*)d_in[1];
  const float* g26i = (const float*)d_in[2];
  const float* g11i = (const float*)d_in[3];
  const float* g26j = (const float*)d_in[4];
  const float* g11j = (const float*)d_in[5];
  const float* w1 = (const float*)d_in[6];  const float* b1 = (const float*)d_in[7];
  const float* w2 = (const float*)d_in[8];  const float* b2 = (const float*)d_in[9];
  const float* w3 = (const float*)d_in[10]; const float* b3 = (const float*)d_in[11];
  const float* w4 = (const float*)d_in[12]; const float* b4 = (const float*)d_in[13];
  const float* f1w = (const float*)d_in[14]; const float* f1b = (const float*)d_in[15];
  const float* f2w = (const float*)d_in[16]; const float* f2b = (const float*)d_in[17];
  float* out = (float*)d_out;

  cudaFuncSetAttribute(k_net, cudaFuncAttributeMaxDynamicSharedMemorySize,
                       SMEM_FLOATS * 4);

  k_prep<<<4, 512>>>(w1, w2, w3, w4);
  k_net<<<NTOT, TPB, SMEM_FLOATS * 4>>>(ti, tj, g26i, g26j, g11i, g11j,
                                        b1, b2, b3, b4);
  k_fc<<<NTOT / 64, 256>>>(f1w, f1b, f2w, f2b);
  k_reduce_r<<<1, 64>>>(out);
  k_cmnorm<<<128, 256>>>(out);
}

// round 15
// speedup vs baseline: 1.6177x; 1.0825x over previous
#include <cuda_runtime.h>
#include <math.h>

#define NPT 2048
#define NTOT 4096
#define TPB 416
typedef unsigned long long ull;

__device__ float g_xf[(size_t)NTOT * 784];
__device__ float g_cm[(size_t)NTOT * 49];
__device__ float g_r[NTOT];
// bf16-split fragment-ready weights (built once by k_prep)
__device__ uint4 g_w1frag[832];   // conv1 [s13][nt2][lane32]
__device__ uint4 g_w2frag[1600];  // conv2 [s25][nt2][lane32]
__device__ uint4 g_w3frag[576];   // conv3 [s9][nt2][lane32]
__device__ uint4 g_w4frag[576];   // conv4 [s9][nt2][lane32]

__device__ __forceinline__ float lrelu(float v) { return v >= 0.f ? v : 0.01f * v; }
__device__ __forceinline__ unsigned bf2pack(float hi_elem, float lo_elem) {
  unsigned u; asm("cvt.rn.bf16x2.f32 %0, %1, %2;" : "=r"(u) : "f"(hi_elem), "f"(lo_elem));
  return u;
}
#define MMA_BF16(d0,d1,d2,d3,a0,a1,a2,a3,b0,b1) \
  asm("mma.sync.aligned.m16n8k16.row.col.f32.bf16.bf16.f32 " \
      "{%0,%1,%2,%3},{%4,%5,%6,%7},{%8,%9},{%0,%1,%2,%3};" \
      : "+f"(d0),"+f"(d1),"+f"(d2),"+f"(d3) \
      : "r"(a0),"r"(a1),"r"(a2),"r"(a3),"r"(b0),"r"(b1))

#define SPLIT_PAIR(fx, fy, hi, lo_) do { \
  unsigned xb = __float_as_uint(fx), yb = __float_as_uint(fy); \
  hi = __byte_perm(xb, yb, 0x7632); \
  float lx = (fx) - __uint_as_float(xb & 0xffff0000u); \
  float ly = (fy) - __uint_as_float(yb & 0xffff0000u); \
  lo_ = bf2pack(ly, lx); \
} while (0)

// smem float offsets (27284 floats = 109136 B -> 2 blocks/SM)
#define OFF_ACT26 0        // 10816  (= [416][26] row-major)
#define OFF_W2F   10816    // 6400 (1600 uint4)
#define OFF_W3F   17216    // 2304 (576 uint4)
#define OFF_W4F   19520    // 2304 (576 uint4)
#define OFF_K26F  21824    // 1024 (256 uint4: [s2][nt4][lane32])
#define OFF_K11F  22848    // 256  (64 uint4: [nt2][lane32])
#define OFF_ACT11 23104    // 1936 (= [176][11] row-major)
#define OFF_ACT9  25040    // 1296
#define OFF_SB1   26336
#define OFF_SB2   26352
#define OFF_SB3   26368
#define OFF_SB4   26384
#define OFF_SCM   26400    // 196
#define OFF_KOFF  26596    // 400 ints (conv2)
#define OFF_KT3   26996    // 144 ints
#define OFF_KT4   27140    // 144 ints
#define SMEM_FLOATS 27284

__device__ __forceinline__ int koff(int k) {
  int ci = k & 3, t = k >> 2;
  int kw = t % 7, kh = t / 7;
  return kh * 336 + kw * 4 + ci;
}

// ---------------- one-time weight prep ----------------
__global__ void k_prep(const float* __restrict__ w1, const float* __restrict__ w2,
                       const float* __restrict__ w3, const float* __restrict__ w4) {
  int tid = blockIdx.x * blockDim.x + threadIdx.x;
  for (int idx = tid; idx < 832; idx += 2048) {
    int lane = idx & 31, sn = idx >> 5;
    int s = sn >> 1, nt = sn & 1;
    int tig = lane & 3, gq = lane >> 2;
    int co = nt * 8 + gq;
    float wv[4];
    int k0 = s * 16 + tig * 2;
#pragma unroll
    for (int e = 0; e < 4; e++) {
      int k = k0 + (e >> 1) * 8 + (e & 1);
      float w = 0.f;
      if (k < 196) {
        int ci = k & 3, t = k >> 2, kw = t % 7, kh = t / 7;
        w = w1[co * 196 + ci * 49 + kh * 7 + kw];
      }
      wv[e] = w;
    }
    unsigned hb[4]; float lo[4];
#pragma unroll
    for (int e = 0; e < 4; e++) {
      hb[e] = __float_as_uint(wv[e]) & 0xffff0000u;
      lo[e] = wv[e] - __uint_as_float(hb[e]);
    }
    uint4 out;
    out.x = (hb[0] >> 16) | (hb[1] & 0xffff0000u);
    out.y = (hb[2] >> 16) | (hb[3] & 0xffff0000u);
    out.z = bf2pack(lo[1], lo[0]);
    out.w = bf2pack(lo[3], lo[2]);
    g_w1frag[idx] = out;
  }
  for (int idx = tid; idx < 1600; idx += 2048) {
    int lane = idx & 31, sn = idx >> 5;
    int s = sn >> 1, nt = sn & 1;
    int tig = lane & 3, gq = lane >> 2;
    int co = nt * 8 + gq;
    float wv[4];
    int k0 = s * 16 + tig * 2;
#pragma unroll
    for (int e = 0; e < 4; e++) {
      int k = k0 + (e >> 1) * 8 + (e & 1);
      wv[e] = w2[co * 400 + k];
    }
    unsigned hb[4]; float lo[4];
#pragma unroll
    for (int e = 0; e < 4; e++) {
      hb[e] = __float_as_uint(wv[e]) & 0xffff0000u;
      lo[e] = wv[e] - __uint_as_float(hb[e]);
    }
    uint4 out;
    out.x = (hb[0] >> 16) | (hb[1] & 0xffff0000u);
    out.y = (hb[2] >> 16) | (hb[3] & 0xffff0000u);
    out.z = bf2pack(lo[1], lo[0]);
    out.w = bf2pack(lo[3], lo[2]);
    g_w2frag[idx] = out;
  }
  for (int idx = tid; idx < 1152; idx += 2048) {
    int which = idx >= 576;
    int id2 = idx - which * 576;
    const float* w = which ? w4 : w3;
    int lane = id2 & 31, sn = id2 >> 5;
    int s = sn >> 1, nt = sn & 1;
    int tig = lane & 3, gq = lane >> 2;
    int co = nt * 8 + gq;
    float wv[4];
    int k0 = s * 16 + tig * 2;
#pragma unroll
    for (int e = 0; e < 4; e++) {
      int k = k0 + (e >> 1) * 8 + (e & 1);
      wv[e] = w[co * 144 + k];
    }
    unsigned hb[4]; float lo[4];
#pragma unroll
    for (int e = 0; e < 4; e++) {
      hb[e] = __float_as_uint(wv[e]) & 0xffff0000u;
      lo[e] = wv[e] - __uint_as_float(hb[e]);
    }
    uint4 out;
    out.x = (hb[0] >> 16) | (hb[1] & 0xffff0000u);
    out.y = (hb[2] >> 16) | (hb[3] & 0xffff0000u);
    out.z = bf2pack(lo[1], lo[0]);
    out.w = bf2pack(lo[3], lo[2]);
    if (which) g_w4frag[id2] = out; else g_w3frag[id2] = out;
  }
}

__global__ __launch_bounds__(TPB, 2) void k_net(
    const float* __restrict__ ti, const float* __restrict__ tj,
    const float* __restrict__ g26i, const float* __restrict__ g26j,
    const float* __restrict__ g11i, const float* __restrict__ g11j,
    const float* __restrict__ b1, const float* __restrict__ b2,
    const float* __restrict__ b3, const float* __restrict__ b4) {
  extern __shared__ float sm[];
  int n = blockIdx.x, tid = threadIdx.x;
  const float sc = 1.0f / (0.7f * 0.3f);

  const float* x   = (n < NPT) ? ti   + (size_t)n * 28224 : tj   + (size_t)(n - NPT) * 28224;
  const float* g26 = (n < NPT) ? g26i + (size_t)n * 676   : g26j + (size_t)(n - NPT) * 676;
  const float* g11 = (n < NPT) ? g11i + (size_t)n * 121   : g11j + (size_t)(n - NPT) * 121;

  // ---- phase 0: fragments / gaze fragments / tables ----
  {
    uint4* w2f = (uint4*)(sm + OFF_W2F);
    for (int i = tid; i < 1600; i += TPB) w2f[i] = g_w2frag[i];
    uint4* w3f = (uint4*)(sm + OFF_W3F);
    for (int i = tid; i < 576; i += TPB) w3f[i] = g_w3frag[i];
    uint4* w4f = (uint4*)(sm + OFF_W4F);
    for (int i = tid; i < 576; i += TPB) w4f[i] = g_w4frag[i];
  }
  // gaze26 B fragments: [s2][nt4][lane32]; B[w][col] = (g26[w*26+col]-.3)*sc
  {
    uint4* kf = (uint4*)(sm + OFF_K26F);
    for (int i = tid; i < 256; i += TPB) {
      int lane = i & 31, sn = i >> 5;
      int s = sn >> 2, nt = sn & 3;
      int tig = lane & 3, gq = lane >> 2;
      int col = nt * 8 + gq;
      float wv[4];
      int w0 = s * 16 + tig * 2;
#pragma unroll
      for (int e = 0; e < 4; e++) {
        int w = w0 + (e >> 1) * 8 + (e & 1);
        wv[e] = (w < 26 && col < 26) ? (g26[w * 26 + col] - 0.3f) * sc : 0.f;
      }
      unsigned hb[4]; float lo[4];
#pragma unroll
      for (int e = 0; e < 4; e++) {
        hb[e] = __float_as_uint(wv[e]) & 0xffff0000u;
        lo[e] = wv[e] - __uint_as_float(hb[e]);
      }
      uint4 out;
      out.x = (hb[0] >> 16) | (hb[1] & 0xffff0000u);
      out.y = (hb[2] >> 16) | (hb[3] & 0xffff0000u);
      out.z = bf2pack(lo[1], lo[0]);
      out.w = bf2pack(lo[3], lo[2]);
      kf[i] = out;
    }
  }
  // gaze11 B fragments: [nt2][lane32]
  {
    uint4* kf = (uint4*)(sm + OFF_K11F);
    for (int i = tid; i < 64; i += TPB) {
      int lane = i & 31, nt = i >> 5;
      int tig = lane & 3, gq = lane >> 2;
      int col = nt * 8 + gq;
      float wv[4];
      int w0 = tig * 2;
#pragma unroll
      for (int e = 0; e < 4; e++) {
        int w = w0 + (e >> 1) * 8 + (e & 1);
        wv[e] = (w < 11 && col < 11) ? (g11[w * 11 + col] - 0.3f) * sc : 0.f;
      }
      unsigned hb[4]; float lo[4];
#pragma unroll
      for (int e = 0; e < 4; e++) {
        hb[e] = __float_as_uint(wv[e]) & 0xffff0000u;
        lo[e] = wv[e] - __uint_as_float(hb[e]);
      }
      uint4 out;
      out.x = (hb[0] >> 16) | (hb[1] & 0xffff0000u);
      out.y = (hb[2] >> 16) | (hb[3] & 0xffff0000u);
      out.z = bf2pack(lo[1], lo[0]);
      out.w = bf2pack(lo[3], lo[2]);
      kf[i] = out;
    }
  }
  {
    int* kt = (int*)(sm + OFF_KOFF);
    for (int k = tid; k < 400; k += TPB) {
      int ci = k / 25, t = k - ci * 25, kh = t / 5, kw = t - kh * 5;
      kt[k] = ci * 676 + kh * 26 + kw;
    }
    int* kt3 = (int*)(sm + OFF_KT3);
    int* kt4 = (int*)(sm + OFF_KT4);
    for (int k = tid; k < 144; k += TPB) {
      int ci = k / 9, t = k - ci * 9, kh = t / 3, kw = t - kh * 3;
      kt3[k] = ci * 121 + kh * 11 + kw;
      kt4[k] = ci * 81 + kh * 9 + kw;
    }
  }
  if (tid < 16) {
    sm[OFF_SB1 + tid] = b1[tid]; sm[OFF_SB2 + tid] = b2[tid];
    sm[OFF_SB3 + tid] = b3[tid]; sm[OFF_SB4 + tid] = b4[tid];
  }
  __syncthreads();

  int warp = tid >> 5, lane = tid & 31;
  int g = lane >> 2, tig = lane & 3;

  // ---- phase 1: conv1 MMA (M=676, N=16, K=196), A-prefetch pipeline ----
  {
    const float* sb1 = sm + OFF_SB1;
    float* sact = sm + OFF_ACT26;
    for (int pass = 0; pass < 4; pass++) {
      int tile = pass * 13 + warp;
      if (tile >= 43) break;
      float dA[4] = {0.f, 0.f, 0.f, 0.f};
      float dB[4] = {0.f, 0.f, 0.f, 0.f};
      int p0 = tile * 16 + g, p1 = p0 + 8;
      bool ok0 = p0 < 676, ok1 = p1 < 676;
      int oh0 = p0 / 26, ow0 = p0 - oh0 * 26;
      int oh1 = p1 / 26, ow1 = p1 - oh1 * 26;
      int base0 = ok0 ? (oh0 * 1008 + ow0 * 12) : 0;
      int base1 = ok1 ? (oh1 * 1008 + ow1 * 12) : 0;
      float2 v[4];
      {
        int k0 = tig * 2, k8 = k0 + 8;
        int off01 = koff(k0), off89 = koff(k8);
        v[0] = ok0 ? *(const float2*)(x + base0 + off01) : make_float2(0.f, 0.f);
        v[1] = ok1 ? *(const float2*)(x + base1 + off01) : make_float2(0.f, 0.f);
        v[2] = ok0 ? *(const float2*)(x + base0 + off89) : make_float2(0.f, 0.f);
        v[3] = ok1 ? *(const float2*)(x + base1 + off89) : make_float2(0.f, 0.f);
      }
      for (int s = 0; s < 13; s++) {
        uint4 B0 = g_w1frag[(s * 2 + 0) * 32 + lane];
        uint4 B1 = g_w1frag[(s * 2 + 1) * 32 + lane];
        float2 vn[4];
        if (s < 12) {
          int k0n = (s + 1) * 16 + tig * 2, k8n = k0n + 8;
          bool k01ok = k0n < 196, k89ok = k8n < 196;
          int off01 = koff(k01ok ? k0n : 0);
          int off89 = koff(k89ok ? k8n : 0);
          vn[0] = (ok0 && k01ok) ? *(const float2*)(x + base0 + off01) : make_float2(0.f, 0.f);
          vn[1] = (ok1 && k01ok) ? *(const float2*)(x + base1 + off01) : make_float2(0.f, 0.f);
          vn[2] = (ok0 && k89ok) ? *(const float2*)(x + base0 + off89) : make_float2(0.f, 0.f);
          vn[3] = (ok1 && k89ok) ? *(const float2*)(x + base1 + off89) : make_float2(0.f, 0.f);
        }
        unsigned ah[4], al[4];
#pragma unroll
        for (int q = 0; q < 4; q++) SPLIT_PAIR(v[q].x, v[q].y, ah[q], al[q]);
        MMA_BF16(dA[0], dA[1], dA[2], dA[3], ah[0], ah[1], ah[2], ah[3], B0.x, B0.y);
        MMA_BF16(dA[0], dA[1], dA[2], dA[3], ah[0], ah[1], ah[2], ah[3], B0.z, B0.w);
        MMA_BF16(dA[0], dA[1], dA[2], dA[3], al[0], al[1], al[2], al[3], B0.x, B0.y);
        MMA_BF16(dB[0], dB[1], dB[2], dB[3], ah[0], ah[1], ah[2], ah[3], B1.x, B1.y);
        MMA_BF16(dB[0], dB[1], dB[2], dB[3], ah[0], ah[1], ah[2], ah[3], B1.z, B1.w);
        MMA_BF16(dB[0], dB[1], dB[2], dB[3], al[0], al[1], al[2], al[3], B1.x, B1.y);
        if (s < 12) {
#pragma unroll
          for (int q = 0; q < 4; q++) v[q] = vn[q];
        }
      }
      int co0 = tig * 2, co1 = co0 + 1;
      if (ok0) {
        sact[co0 * 676 + p0] = lrelu(dA[0] + sb1[co0]);
        sact[co1 * 676 + p0] = lrelu(dA[1] + sb1[co1]);
        sact[(co0 + 8) * 676 + p0] = lrelu(dB[0] + sb1[co0 + 8]);
        sact[(co1 + 8) * 676 + p0] = lrelu(dB[1] + sb1[co1 + 8]);
      }
      if (ok1) {
        sact[co0 * 676 + p1] = lrelu(dA[2] + sb1[co0]);
        sact[co1 * 676 + p1] = lrelu(dA[3] + sb1[co1]);
        sact[(co0 + 8) * 676 + p1] = lrelu(dB[2] + sb1[co0 + 8]);
        sact[(co1 + 8) * 676 + p1] = lrelu(dB[3] + sb1[co1 + 8]);
      }
    }
  }
  __syncthreads();

  // ---- phase 2: gaze26 via MMA (M=416, N=26pad32, K=26pad32), in-place ----
  {
    const uint4* kf = (const uint4*)(sm + OFF_K26F);
    float* act = sm + OFF_ACT26;
    for (int pass = 0; pass < 2; pass++) {
      int tile = pass * 13 + warp;
      if (tile < 26) {
        int r0 = tile * 16 + g, r1 = r0 + 8;
        const float* a0p = act + r0 * 26;
        const float* a1p = act + r1 * 26;
        float d[4][4];
#pragma unroll
        for (int nt = 0; nt < 4; nt++)
#pragma unroll
          for (int e = 0; e < 4; e++) d[nt][e] = 0.f;
#pragma unroll
        for (int s = 0; s < 2; s++) {
          int k0 = s * 16 + tig * 2;
          int k8 = k0 + 8;
          bool ok8 = (k8 + 1) < 26;
          float2 v0 = *(const float2*)(a0p + k0);
          float2 v1 = *(const float2*)(a1p + k0);
          float2 v2 = ok8 ? *(const float2*)(a0p + k8) : make_float2(0.f, 0.f);
          float2 v3 = ok8 ? *(const float2*)(a1p + k8) : make_float2(0.f, 0.f);
          unsigned ah[4], al[4];
          SPLIT_PAIR(v0.x, v0.y, ah[0], al[0]);
          SPLIT_PAIR(v1.x, v1.y, ah[1], al[1]);
          SPLIT_PAIR(v2.x, v2.y, ah[2], al[2]);
          SPLIT_PAIR(v3.x, v3.y, ah[3], al[3]);
#pragma unroll
          for (int nt = 0; nt < 4; nt++) {
            uint4 B = kf[(s * 4 + nt) * 32 + lane];
            MMA_BF16(d[nt][0], d[nt][1], d[nt][2], d[nt][3],
                     ah[0], ah[1], ah[2], ah[3], B.x, B.y);
            MMA_BF16(d[nt][0], d[nt][1], d[nt][2], d[nt][3],
                     ah[0], ah[1], ah[2], ah[3], B.z, B.w);
            MMA_BF16(d[nt][0], d[nt][1], d[nt][2], d[nt][3],
                     al[0], al[1], al[2], al[3], B.x, B.y);
          }
        }
        float* w0p = act + r0 * 26;
        float* w1p = act + r1 * 26;
#pragma unroll
        for (int nt = 0; nt < 4; nt++) {
          int c0 = nt * 8 + tig * 2, c1 = c0 + 1;
          if (c0 < 26) { w0p[c0] = d[nt][0]; w1p[c0] = d[nt][2]; }
          if (c1 < 26) { w0p[c1] = d[nt][1]; w1p[c1] = d[nt][3]; }
        }
      }
    }
  }
  __syncthreads();

  // ---- phase 3: conv2 MMA (M=121, N=16, K=400), warps 0-7 ----
  if (warp < 8) {
    const float* sact = sm + OFF_ACT26;
    const int* kt = (const int*)(sm + OFF_KOFF);
    const uint4* wfrag = (const uint4*)(sm + OFF_W2F);
    int p0 = warp * 16 + g, p1 = p0 + 8;
    bool ok0 = p0 < 121, ok1 = p1 < 121;
    int oh0 = p0 / 11, ow0 = p0 - oh0 * 11;
    int oh1 = p1 / 11, ow1 = p1 - oh1 * 11;
    int pb0 = ok0 ? (oh0 * 52 + ow0 * 2) : 0;
    int pb1 = ok1 ? (oh1 * 52 + ow1 * 2) : 0;
    float dA[4] = {0.f, 0.f, 0.f, 0.f};
    float dB[4] = {0.f, 0.f, 0.f, 0.f};
    int k0 = tig * 2;
    for (int s = 0; s < 25; s++, k0 += 16) {
      uint4 B0 = wfrag[(s * 2 + 0) * 32 + lane];
      uint4 B1 = wfrag[(s * 2 + 1) * 32 + lane];
      int o0 = kt[k0], o1 = kt[k0 + 1], o2 = kt[k0 + 8], o3 = kt[k0 + 9];
      float e00 = ok0 ? sact[o0 + pb0] : 0.f, e01 = ok0 ? sact[o1 + pb0] : 0.f;
      float e02 = ok0 ? sact[o2 + pb0] : 0.f, e03 = ok0 ? sact[o3 + pb0] : 0.f;
      float e10 = ok1 ? sact[o0 + pb1] : 0.f, e11 = ok1 ? sact[o1 + pb1] : 0.f;
      float e12 = ok1 ? sact[o2 + pb1] : 0.f, e13 = ok1 ? sact[o3 + pb1] : 0.f;
      unsigned ah[4], al[4];
      SPLIT_PAIR(e00, e01, ah[0], al[0]);
      SPLIT_PAIR(e10, e11, ah[1], al[1]);
      SPLIT_PAIR(e02, e03, ah[2], al[2]);
      SPLIT_PAIR(e12, e13, ah[3], al[3]);
      MMA_BF16(dA[0], dA[1], dA[2], dA[3], ah[0], ah[1], ah[2], ah[3], B0.x, B0.y);
      MMA_BF16(dA[0], dA[1], dA[2], dA[3], ah[0], ah[1], ah[2], ah[3], B0.z, B0.w);
      MMA_BF16(dA[0], dA[1], dA[2], dA[3], al[0], al[1], al[2], al[3], B0.x, B0.y);
      MMA_BF16(dB[0], dB[1], dB[2], dB[3], ah[0], ah[1], ah[2], ah[3], B1.x, B1.y);
      MMA_BF16(dB[0], dB[1], dB[2], dB[3], ah[0], ah[1], ah[2], ah[3], B1.z, B1.w);
      MMA_BF16(dB[0], dB[1], dB[2], dB[3], al[0], al[1], al[2], al[3], B1.x, B1.y);
    }
    float* act11 = sm + OFF_ACT11;
    const float* sb2 = sm + OFF_SB2;
    int co0 = tig * 2, co1 = co0 + 1;
    if (ok0) {
      act11[co0 * 121 + p0] = lrelu(dA[0] + sb2[co0]);
      act11[co1 * 121 + p0] = lrelu(dA[1] + sb2[co1]);
      act11[(co0 + 8) * 121 + p0] = lrelu(dB[0] + sb2[co0 + 8]);
      act11[(co1 + 8) * 121 + p0] = lrelu(dB[1] + sb2[co1 + 8]);
    }
    if (ok1) {
      act11[co0 * 121 + p1] = lrelu(dA[2] + sb2[co0]);
      act11[co1 * 121 + p1] = lrelu(dA[3] + sb2[co1]);
      act11[(co0 + 8) * 121 + p1] = lrelu(dB[2] + sb2[co0 + 8]);
      act11[(co1 + 8) * 121 + p1] = lrelu(dB[3] + sb2[co1 + 8]);
    }
  }
  __syncthreads();

  // ---- phase 4: gaze11 via MMA (M=176, N=11pad16, K=11pad16), warps 0-10, in-place ----
  if (warp < 11) {
    const uint4* kf = (const uint4*)(sm + OFF_K11F);
    float* act = sm + OFF_ACT11;
    int r0 = warp * 16 + g, r1 = r0 + 8;
    const float* a0p = act + r0 * 11;
    const float* a1p = act + r1 * 11;
    int k0 = tig * 2, k8 = k0 + 8;
    float a00 = a0p[k0], a01 = a0p[k0 + 1];
    float a10 = a1p[k0], a11 = a1p[k0 + 1];
    float a02 = (k8 < 11) ? a0p[k8] : 0.f;
    float a03 = (k8 + 1 < 11) ? a0p[k8 + 1] : 0.f;
    float a12 = (k8 < 11) ? a1p[k8] : 0.f;
    float a13 = (k8 + 1 < 11) ? a1p[k8 + 1] : 0.f;
    unsigned ah[4], al[4];
    SPLIT_PAIR(a00, a01, ah[0], al[0]);
    SPLIT_PAIR(a10, a11, ah[1], al[1]);
    SPLIT_PAIR(a02, a03, ah[2], al[2]);
    SPLIT_PAIR(a12, a13, ah[3], al[3]);
    float d[2][4];
#pragma unroll
    for (int nt = 0; nt < 2; nt++)
#pragma unroll
      for (int e = 0; e < 4; e++) d[nt][e] = 0.f;
#pragma unroll
    for (int nt = 0; nt < 2; nt++) {
      uint4 B = kf[nt * 32 + lane];
      MMA_BF16(d[nt][0], d[nt][1], d[nt][2], d[nt][3],
               ah[0], ah[1], ah[2], ah[3], B.x, B.y);
      MMA_BF16(d[nt][0], d[nt][1], d[nt][2], d[nt][3],
               ah[0], ah[1], ah[2], ah[3], B.z, B.w);
      MMA_BF16(d[nt][0], d[nt][1], d[nt][2], d[nt][3],
               al[0], al[1], al[2], al[3], B.x, B.y);
    }
    float* w0p = act + r0 * 11;
    float* w1p = act + r1 * 11;
#pragma unroll
    for (int nt = 0; nt < 2; nt++) {
      int c0 = nt * 8 + tig * 2, c1 = c0 + 1;
      if (c0 < 11) { w0p[c0] = d[nt][0]; w1p[c0] = d[nt][2]; }
      if (c1 < 11) { w0p[c1] = d[nt][1]; w1p[c1] = d[nt][3]; }
    }
  }
  __syncthreads();

  // ---- phase 5: conv3 MMA (M=81, N=16, K=144), warps 0-5 ----
  if (warp < 6) {
    const float* act11 = sm + OFF_ACT11;
    const int* kt3 = (const int*)(sm + OFF_KT3);
    const uint4* wfrag = (const uint4*)(sm + OFF_W3F);
    int p0 = warp * 16 + g, p1 = p0 + 8;
    bool ok0 = p0 < 81, ok1 = p1 < 81;
    int oh0 = p0 / 9, ow0 = p0 - oh0 * 9;
    int oh1 = p1 / 9, ow1 = p1 - oh1 * 9;
    int pb0 = ok0 ? (oh0 * 11 + ow0) : 0;
    int pb1 = ok1 ? (oh1 * 11 + ow1) : 0;
    float dA[4] = {0.f, 0.f, 0.f, 0.f};
    float dB[4] = {0.f, 0.f, 0.f, 0.f};
    int k0 = tig * 2;
    for (int s = 0; s < 9; s++, k0 += 16) {
      uint4 B0 = wfrag[(s * 2 + 0) * 32 + lane];
      uint4 B1 = wfrag[(s * 2 + 1) * 32 + lane];
      int o0 = kt3[k0], o1 = kt3[k0 + 1], o2 = kt3[k0 + 8], o3 = kt3[k0 + 9];
      float e00 = ok0 ? act11[o0 + pb0] : 0.f, e01 = ok0 ? act11[o1 + pb0] : 0.f;
      float e02 = ok0 ? act11[o2 + pb0] : 0.f, e03 = ok0 ? act11[o3 + pb0] : 0.f;
      float e10 = ok1 ? act11[o0 + pb1] : 0.f, e11 = ok1 ? act11[o1 + pb1] : 0.f;
      float e12 = ok1 ? act11[o2 + pb1] : 0.f, e13 = ok1 ? act11[o3 + pb1] : 0.f;
      unsigned ah[4], al[4];
      SPLIT_PAIR(e00, e01, ah[0], al[0]);
      SPLIT_PAIR(e10, e11, ah[1], al[1]);
      SPLIT_PAIR(e02, e03, ah[2], al[2]);
      SPLIT_PAIR(e12, e13, ah[3], al[3]);
      MMA_BF16(dA[0], dA[1], dA[2], dA[3], ah[0], ah[1], ah[2], ah[3], B0.x, B0.y);
      MMA_BF16(dA[0], dA[1], dA[2], dA[3], ah[0], ah[1], ah[2], ah[3], B0.z, B0.w);
      MMA_BF16(dA[0], dA[1], dA[2], dA[3], al[0], al[1], al[2], al[3], B0.x, B0.y);
      MMA_BF16(dB[0], dB[1], dB[2], dB[3], ah[0], ah[1], ah[2], ah[3], B1.x, B1.y);
      MMA_BF16(dB[0], dB[1], dB[2], dB[3], ah[0], ah[1], ah[2], ah[3], B1.z, B1.w);
      MMA_BF16(dB[0], dB[1], dB[2], dB[3], al[0], al[1], al[2], al[3], B1.x, B1.y);
    }
    float* act9 = sm + OFF_ACT9;
    const float* sb3 = sm + OFF_SB3;
    int co0 = tig * 2, co1 = co0 + 1;
    if (ok0) {
      act9[co0 * 81 + p0] = lrelu(dA[0] + sb3[co0]);
      act9[co1 * 81 + p0] = lrelu(dA[1] + sb3[co1]);
      act9[(co0 + 8) * 81 + p0] = lrelu(dB[0] + sb3[co0 + 8]);
      act9[(co1 + 8) * 81 + p0] = lrelu(dB[1] + sb3[co1 + 8]);
    }
    if (ok1) {
      act9[co0 * 81 + p1] = lrelu(dA[2] + sb3[co0]);
      act9[co1 * 81 + p1] = lrelu(dA[3] + sb3[co1]);
      act9[(co0 + 8) * 81 + p1] = lrelu(dB[2] + sb3[co0 + 8]);
      act9[(co1 + 8) * 81 + p1] = lrelu(dB[3] + sb3[co1 + 8]);
    }
  }
  __syncthreads();

  // ---- phase 6: conv4 MMA (M=49, N=16, K=144), warps 0-3 ----
  if (warp < 4) {
    const float* act9 = sm + OFF_ACT9;
    const int* kt4 = (const int*)(sm + OFF_KT4);
    const uint4* wfrag = (const uint4*)(sm + OFF_W4F);
    int p0 = warp * 16 + g, p1 = p0 + 8;
    bool ok0 = p0 < 49, ok1 = p1 < 49;
    int oh0 = p0 / 7, ow0 = p0 - oh0 * 7;
    int oh1 = p1 / 7, ow1 = p1 - oh1 * 7;
    int pb0 = ok0 ? (oh0 * 9 + ow0) : 0;
    int pb1 = ok1 ? (oh1 * 9 + ow1) : 0;
    float dA[4] = {0.f, 0.f, 0.f, 0.f};
    float dB[4] = {0.f, 0.f, 0.f, 0.f};
    int k0 = tig * 2;
    for (int s = 0; s < 9; s++, k0 += 16) {
      uint4 B0 = wfrag[(s * 2 + 0) * 32 + lane];
      uint4 B1 = wfrag[(s * 2 + 1) * 32 + lane];
      int o0 = kt4[k0], o1 = kt4[k0 + 1], o2 = kt4[k0 + 8], o3 = kt4[k0 + 9];
      float e00 = ok0 ? act9[o0 + pb0] : 0.f, e01 = ok0 ? act9[o1 + pb0] : 0.f;
      float e02 = ok0 ? act9[o2 + pb0] : 0.f, e03 = ok0 ? act9[o3 + pb0] : 0.f;
      float e10 = ok1 ? act9[o0 + pb1] : 0.f, e11 = ok1 ? act9[o1 + pb1] : 0.f;
      float e12 = ok1 ? act9[o2 + pb1] : 0.f, e13 = ok1 ? act9[o3 + pb1] : 0.f;
      unsigned ah[4], al[4];
      SPLIT_PAIR(e00, e01, ah[0], al[0]);
      SPLIT_PAIR(e10, e11, ah[1], al[1]);
      SPLIT_PAIR(e02, e03, ah[2], al[2]);
      SPLIT_PAIR(e12, e13, ah[3], al[3]);
      MMA_BF16(dA[0], dA[1], dA[2], dA[3], ah[0], ah[1], ah[2], ah[3], B0.x, B0.y);
      MMA_BF16(dA[0], dA[1], dA[2], dA[3], ah[0], ah[1], ah[2], ah[3], B0.z, B0.w);
      MMA_BF16(dA[0], dA[1], dA[2], dA[3], al[0], al[1], al[2], al[3], B0.x, B0.y);
      MMA_BF16(dB[0], dB[1], dB[2], dB[3], ah[0], ah[1], ah[2], ah[3], B1.x, B1.y);
      MMA_BF16(dB[0], dB[1], dB[2], dB[3], ah[0], ah[1], ah[2], ah[3], B1.z, B1.w);
      MMA_BF16(dB[0], dB[1], dB[2], dB[3], al[0], al[1], al[2], al[3], B1.x, B1.y);
    }
    const float* sb4 = sm + OFF_SB4;
    int co0 = tig * 2, co1 = co0 + 1;
    if (ok0) {
      float* xp = g_xf + (size_t)n * 784 + p0;
      float v0 = lrelu(dA[0] + sb4[co0]);
      float v1 = lrelu(dA[1] + sb4[co1]);
      float v2 = lrelu(dB[0] + sb4[co0 + 8]);
      float v3 = lrelu(dB[1] + sb4[co1 + 8]);
      xp[co0 * 49] = v0; xp[co1 * 49] = v1;
      xp[(co0 + 8) * 49] = v2; xp[(co1 + 8) * 49] = v3;
      sm[OFF_SCM + p0 * 4 + tig] = v0 + v1 + v2 + v3;
    }
    if (ok1) {
      float* xp = g_xf + (size_t)n * 784 + p1;
      float v0 = lrelu(dA[2] + sb4[co0]);
      float v1 = lrelu(dA[3] + sb4[co1]);
      float v2 = lrelu(dB[2] + sb4[co0 + 8]);
      float v3 = lrelu(dB[3] + sb4[co1 + 8]);
      xp[co0 * 49] = v0; xp[co1 * 49] = v1;
      xp[(co0 + 8) * 49] = v2; xp[(co1 + 8) * 49] = v3;
      sm[OFF_SCM + p1 * 4 + tig] = v0 + v1 + v2 + v3;
    }
  }
  __syncthreads();
  if (tid < 49) {
    const float* s4 = sm + OFF_SCM + tid * 4;
    g_cm[(size_t)n * 49 + tid] = (s4[0] + s4[1]) + (s4[2] + s4[3]);
  }
}

// ---------------- fc ----------------
__global__ __launch_bounds__(256) void k_fc(const float* __restrict__ w1,
                                            const float* __restrict__ b1,
                                            const float* __restrict__ w2,
                                            const float* __restrict__ b2) {
  __shared__ float As[64][17];
  __shared__ float Bs[16][68];
  __shared__ float prs[16][64];
  int tid = threadIdx.x;
  int s0 = blockIdx.x * 64;
  int sg = tid >> 4, jg = tid & 15;
  float acc[4][4];
#pragma unroll
  for (int i = 0; i < 4; i++)
#pragma unroll
    for (int u = 0; u < 4; u++) acc[i][u] = 0.f;
  for (int k0 = 0; k0 < 784; k0 += 16) {
    for (int i = tid; i < 1024; i += 256) {
      int s = i >> 4, kk = i & 15;
      As[s][kk] = g_xf[(size_t)(s0 + s) * 784 + k0 + kk];
    }
    for (int i = tid; i < 1024; i += 256) {
      int j = i >> 4, kk = i & 15;
      Bs[kk][j] = w1[j * 784 + k0 + kk];
    }
    __syncthreads();
#pragma unroll
    for (int kk = 0; kk < 16; kk++) {
      float av[4], bv[4];
#pragma unroll
      for (int i = 0; i < 4; i++) av[i] = As[sg * 4 + i][kk];
#pragma unroll
      for (int u = 0; u < 4; u++) bv[u] = Bs[kk][jg * 4 + u];
#pragma unroll
      for (int i = 0; i < 4; i++)
#pragma unroll
        for (int u = 0; u < 4; u++) acc[i][u] += av[i] * bv[u];
    }
    __syncthreads();
  }
#pragma unroll
  for (int i = 0; i < 4; i++) {
    float pr = 0.f;
#pragma unroll
    for (int u = 0; u < 4; u++) {
      int j = jg * 4 + u;
      float h = acc[i][u] + b1[j];
      h = lrelu(h);
      pr += h * w2[j];
    }
    prs[jg][sg * 4 + i] = pr;
  }
  __syncthreads();
  if (tid < 64) {
    float s = 0.f;
#pragma unroll
    for (int j = 0; j < 16; j++) s += prs[j][tid];
    g_r[s0 + tid] = s + b2[0];
  }
}

__global__ void k_reduce_r(float* __restrict__ out) {
  __shared__ float sab[64];
  int tid = threadIdx.x;
  int traj = tid >> 5, b = tid & 31;
  float s = 0.f, sa = 0.f;
  for (int t = 0; t < 64; t++) {
    float r = g_r[traj * 2048 + t * 32 + b];
    s += r;
    sa += fabsf(r);
  }
  out[tid] = s;
  sab[tid] = sa;
  __syncthreads();
  if (tid < 32) out[64 + tid] = sab[tid] + sab[32 + tid];
}

__global__ __launch_bounds__(256) void k_cmnorm(float* __restrict__ out) {
  __shared__ float sv[1568];
  __shared__ float smn[8], smx[8];
  __shared__ float fmn, fmx;
  int idx = blockIdx.x;
  int traj = idx >> 6, t = idx & 63;
  int tid = threadIdx.x;
  const float* base = g_cm + ((size_t)(traj * 2048 + t * 32)) * 49;
  float mn = 1e30f, mx = -1e30f;
  for (int i = tid; i < 1568; i += 256) {
    float v = base[i];
    sv[i] = v;
    mn = fminf(mn, v);
    mx = fmaxf(mx, v);
  }
#pragma unroll
  for (int o = 16; o; o >>= 1) {
    mn = fminf(mn, __shfl_xor_sync(0xffffffffu, mn, o));
    mx = fmaxf(mx, __shfl_xor_sync(0xffffffffu, mx, o));
  }
  if ((tid & 31) == 0) { smn[tid >> 5] = mn; smx[tid >> 5] = mx; }
  __syncthreads();
  if (tid == 0) {
    float a = smn[0], bb = smx[0];
    for (int i = 1; i < 8; i++) { a = fminf(a, smn[i]); bb = fmaxf(bb, smx[i]); }
    fmn = a; fmx = bb;
  }
  __syncthreads();
  float m = fmn, inv = 1.f / (fmx - m);
  float* o = out + 96 + (size_t)traj * 100352 + (size_t)t * 1568;
  for (int i = tid; i < 1568; i += 256) o[i] = (sv[i] - m) * inv;
}

extern "C" void kernel_launch(void* const* d_in, const int* in_sizes, int n_in,
                              void* d_out, int out_size) {
  const float* ti   = (const float*)d_in[0];
  const float* tj   = (const float*)d_in[1];
  const float* g26i = (const float*)d_in[2];
  const float* g11i = (const float*)d_in[3];
  const float* g26j = (const float*)d_in[4];
  const float* g11j = (const float*)d_in[5];
  const float* w1 = (const float*)d_in[6];  const float* b1 = (const float*)d_in[7];
  const float* w2 = (const float*)d_in[8];  const float* b2 = (const float*)d_in[9];
  const float* w3 = (const float*)d_in[10]; const float* b3 = (const float*)d_in[11];
  const float* w4 = (const float*)d_in[12]; const float* b4 = (const float*)d_in[13];
  const float* f1w = (const float*)d_in[14]; const float* f1b = (const float*)d_in[15];
  const float* f2w = (const float*)d_in[16]; const float* f2b = (const float*)d_in[17];
  float* out = (float*)d_out;

  cudaFuncSetAttribute(k_net, cudaFuncAttributeMaxDynamicSharedMemorySize,
                       SMEM_FLOATS * 4);

  k_prep<<<4, 512>>>(w1, w2, w3, w4);
  k_net<<<NTOT, TPB, SMEM_FLOATS * 4>>>(ti, tj, g26i, g26j, g11i, g11j,
                                        b1, b2, b3, b4);
  k_fc<<<NTOT / 64, 256>>>(f1w, f1b, f2w, f2b);
  k_reduce_r<<<1, 64>>>(out);
  k_cmnorm<<<128, 256>>>(out);
}

// round 16
// speedup vs baseline: 1.7340x; 1.0719x over previous
#include <cuda_runtime.h>
#include <math.h>

#define NPT 2048
#define NTOT 4096
#define TPB 480
typedef unsigned long long ull;

__device__ float g_xf[(size_t)NTOT * 784];
__device__ float g_cm[(size_t)NTOT * 49];
__device__ float g_r[NTOT];
// bf16-split fragment-ready weights (built once by k_prep)
__device__ uint4 g_w1frag[832];   // conv1 [s13][nt2][lane32]
__device__ uint4 g_w2frag[1600];  // conv2 [s25][nt2][lane32]
__device__ uint4 g_w3frag[576];   // conv3 [s9][nt2][lane32]
__device__ uint4 g_w4frag[576];   // conv4 [s9][nt2][lane32]

__device__ __forceinline__ float lrelu(float v) { return v >= 0.f ? v : 0.01f * v; }
__device__ __forceinline__ unsigned bf2pack(float hi_elem, float lo_elem) {
  unsigned u; asm("cvt.rn.bf16x2.f32 %0, %1, %2;" : "=r"(u) : "f"(hi_elem), "f"(lo_elem));
  return u;
}
#define MMA_BF16(d0,d1,d2,d3,a0,a1,a2,a3,b0,b1) \
  asm("mma.sync.aligned.m16n8k16.row.col.f32.bf16.bf16.f32 " \
      "{%0,%1,%2,%3},{%4,%5,%6,%7},{%8,%9},{%0,%1,%2,%3};" \
      : "+f"(d0),"+f"(d1),"+f"(d2),"+f"(d3) \
      : "r"(a0),"r"(a1),"r"(a2),"r"(a3),"r"(b0),"r"(b1))

#define SPLIT_PAIR(fx, fy, hi, lo_) do { \
  unsigned xb = __float_as_uint(fx), yb = __float_as_uint(fy); \
  hi = __byte_perm(xb, yb, 0x7632); \
  float lx = (fx) - __uint_as_float(xb & 0xffff0000u); \
  float ly = (fy) - __uint_as_float(yb & 0xffff0000u); \
  lo_ = bf2pack(ly, lx); \
} while (0)

// smem float offsets (27284 floats = 109136 B -> 2 blocks/SM)
#define OFF_ACT26 0        // 10816  (= [416][26] row-major)
#define OFF_W2F   10816    // 6400 (1600 uint4)
#define OFF_W3F   17216    // 2304 (576 uint4)
#define OFF_W4F   19520    // 2304 (576 uint4)
#define OFF_K26F  21824    // 1024 (256 uint4: [s2][nt4][lane32])
#define OFF_K11F  22848    // 256  (64 uint4: [nt2][lane32])
#define OFF_ACT11 23104    // 1936 (= [176][11] row-major)
#define OFF_ACT9  25040    // 1296
#define OFF_SB2   26352
#define OFF_SB3   26368
#define OFF_SB4   26384
#define OFF_SCM   26400    // 196
#define OFF_KOFF  26596    // 400 ints (conv2)
#define OFF_KT3   26996    // 144 ints
#define OFF_KT4   27140    // 144 ints
#define SMEM_FLOATS 27284

__device__ __forceinline__ int koff(int k) {
  int ci = k & 3, t = k >> 2;
  int kw = t % 7, kh = t / 7;
  return kh * 336 + kw * 4 + ci;
}

// ---------------- one-time weight prep ----------------
__global__ void k_prep(const float* __restrict__ w1, const float* __restrict__ w2,
                       const float* __restrict__ w3, const float* __restrict__ w4) {
  int tid = blockIdx.x * blockDim.x + threadIdx.x;
  for (int idx = tid; idx < 832; idx += 2048) {
    int lane = idx & 31, sn = idx >> 5;
    int s = sn >> 1, nt = sn & 1;
    int tig = lane & 3, gq = lane >> 2;
    int co = nt * 8 + gq;
    float wv[4];
    int k0 = s * 16 + tig * 2;
#pragma unroll
    for (int e = 0; e < 4; e++) {
      int k = k0 + (e >> 1) * 8 + (e & 1);
      float w = 0.f;
      if (k < 196) {
        int ci = k & 3, t = k >> 2, kw = t % 7, kh = t / 7;
        w = w1[co * 196 + ci * 49 + kh * 7 + kw];
      }
      wv[e] = w;
    }
    unsigned hb[4]; float lo[4];
#pragma unroll
    for (int e = 0; e < 4; e++) {
      hb[e] = __float_as_uint(wv[e]) & 0xffff0000u;
      lo[e] = wv[e] - __uint_as_float(hb[e]);
    }
    uint4 out;
    out.x = (hb[0] >> 16) | (hb[1] & 0xffff0000u);
    out.y = (hb[2] >> 16) | (hb[3] & 0xffff0000u);
    out.z = bf2pack(lo[1], lo[0]);
    out.w = bf2pack(lo[3], lo[2]);
    g_w1frag[idx] = out;
  }
  for (int idx = tid; idx < 1600; idx += 2048) {
    int lane = idx & 31, sn = idx >> 5;
    int s = sn >> 1, nt = sn & 1;
    int tig = lane & 3, gq = lane >> 2;
    int co = nt * 8 + gq;
    float wv[4];
    int k0 = s * 16 + tig * 2;
#pragma unroll
    for (int e = 0; e < 4; e++) {
      int k = k0 + (e >> 1) * 8 + (e & 1);
      wv[e] = w2[co * 400 + k];
    }
    unsigned hb[4]; float lo[4];
#pragma unroll
    for (int e = 0; e < 4; e++) {
      hb[e] = __float_as_uint(wv[e]) & 0xffff0000u;
      lo[e] = wv[e] - __uint_as_float(hb[e]);
    }
    uint4 out;
    out.x = (hb[0] >> 16) | (hb[1] & 0xffff0000u);
    out.y = (hb[2] >> 16) | (hb[3] & 0xffff0000u);
    out.z = bf2pack(lo[1], lo[0]);
    out.w = bf2pack(lo[3], lo[2]);
    g_w2frag[idx] = out;
  }
  for (int idx = tid; idx < 1152; idx += 2048) {
    int which = idx >= 576;
    int id2 = idx - which * 576;
    const float* w = which ? w4 : w3;
    int lane = id2 & 31, sn = id2 >> 5;
    int s = sn >> 1, nt = sn & 1;
    int tig = lane & 3, gq = lane >> 2;
    int co = nt * 8 + gq;
    float wv[4];
    int k0 = s * 16 + tig * 2;
#pragma unroll
    for (int e = 0; e < 4; e++) {
      int k = k0 + (e >> 1) * 8 + (e & 1);
      wv[e] = w[co * 144 + k];
    }
    unsigned hb[4]; float lo[4];
#pragma unroll
    for (int e = 0; e < 4; e++) {
      hb[e] = __float_as_uint(wv[e]) & 0xffff0000u;
      lo[e] = wv[e] - __uint_as_float(hb[e]);
    }
    uint4 out;
    out.x = (hb[0] >> 16) | (hb[1] & 0xffff0000u);
    out.y = (hb[2] >> 16) | (hb[3] & 0xffff0000u);
    out.z = bf2pack(lo[1], lo[0]);
    out.w = bf2pack(lo[3], lo[2]);
    if (which) g_w4frag[id2] = out; else g_w3frag[id2] = out;
  }
}

__global__ __launch_bounds__(TPB, 2) void k_net(
    const float* __restrict__ ti, const float* __restrict__ tj,
    const float* __restrict__ g26i, const float* __restrict__ g26j,
    const float* __restrict__ g11i, const float* __restrict__ g11j,
    const float* __restrict__ b1, const float* __restrict__ b2,
    const float* __restrict__ b3, const float* __restrict__ b4) {
  extern __shared__ float sm[];
  int n = blockIdx.x, tid = threadIdx.x;
  const float sc = 1.0f / (0.7f * 0.3f);

  const float* x   = (n < NPT) ? ti   + (size_t)n * 28224 : tj   + (size_t)(n - NPT) * 28224;
  const float* g26 = (n < NPT) ? g26i + (size_t)n * 676   : g26j + (size_t)(n - NPT) * 676;
  const float* g11 = (n < NPT) ? g11i + (size_t)n * 121   : g11j + (size_t)(n - NPT) * 121;

  // ---- phase 0 (overlaps conv1; no barrier needed before conv1) ----
  {
    uint4* w2f = (uint4*)(sm + OFF_W2F);
    for (int i = tid; i < 1600; i += TPB) w2f[i] = g_w2frag[i];
    uint4* w3f = (uint4*)(sm + OFF_W3F);
    for (int i = tid; i < 576; i += TPB) w3f[i] = g_w3frag[i];
    uint4* w4f = (uint4*)(sm + OFF_W4F);
    for (int i = tid; i < 576; i += TPB) w4f[i] = g_w4frag[i];
  }
  // gaze26 B fragments: [s2][nt4][lane32]
  {
    uint4* kf = (uint4*)(sm + OFF_K26F);
    for (int i = tid; i < 256; i += TPB) {
      int lane = i & 31, sn = i >> 5;
      int s = sn >> 2, nt = sn & 3;
      int tig = lane & 3, gq = lane >> 2;
      int col = nt * 8 + gq;
      float wv[4];
      int w0 = s * 16 + tig * 2;
#pragma unroll
      for (int e = 0; e < 4; e++) {
        int w = w0 + (e >> 1) * 8 + (e & 1);
        wv[e] = (w < 26 && col < 26) ? (g26[w * 26 + col] - 0.3f) * sc : 0.f;
      }
      unsigned hb[4]; float lo[4];
#pragma unroll
      for (int e = 0; e < 4; e++) {
        hb[e] = __float_as_uint(wv[e]) & 0xffff0000u;
        lo[e] = wv[e] - __uint_as_float(hb[e]);
      }
      uint4 out;
      out.x = (hb[0] >> 16) | (hb[1] & 0xffff0000u);
      out.y = (hb[2] >> 16) | (hb[3] & 0xffff0000u);
      out.z = bf2pack(lo[1], lo[0]);
      out.w = bf2pack(lo[3], lo[2]);
      kf[i] = out;
    }
  }
  // gaze11 B fragments: [nt2][lane32]
  {
    uint4* kf = (uint4*)(sm + OFF_K11F);
    for (int i = tid; i < 64; i += TPB) {
      int lane = i & 31, nt = i >> 5;
      int tig = lane & 3, gq = lane >> 2;
      int col = nt * 8 + gq;
      float wv[4];
      int w0 = tig * 2;
#pragma unroll
      for (int e = 0; e < 4; e++) {
        int w = w0 + (e >> 1) * 8 + (e & 1);
        wv[e] = (w < 11 && col < 11) ? (g11[w * 11 + col] - 0.3f) * sc : 0.f;
      }
      unsigned hb[4]; float lo[4];
#pragma unroll
      for (int e = 0; e < 4; e++) {
        hb[e] = __float_as_uint(wv[e]) & 0xffff0000u;
        lo[e] = wv[e] - __uint_as_float(hb[e]);
      }
      uint4 out;
      out.x = (hb[0] >> 16) | (hb[1] & 0xffff0000u);
      out.y = (hb[2] >> 16) | (hb[3] & 0xffff0000u);
      out.z = bf2pack(lo[1], lo[0]);
      out.w = bf2pack(lo[3], lo[2]);
      kf[i] = out;
    }
  }
  {
    int* kt = (int*)(sm + OFF_KOFF);
    for (int k = tid; k < 400; k += TPB) {
      int ci = k / 25, t = k - ci * 25, kh = t / 5, kw = t - kh * 5;
      kt[k] = ci * 676 + kh * 26 + kw;
    }
    int* kt3 = (int*)(sm + OFF_KT3);
    int* kt4 = (int*)(sm + OFF_KT4);
    for (int k = tid; k < 144; k += TPB) {
      int ci = k / 9, t = k - ci * 9, kh = t / 3, kw = t - kh * 3;
      kt3[k] = ci * 121 + kh * 11 + kw;
      kt4[k] = ci * 81 + kh * 9 + kw;
    }
  }
  if (tid < 16) {
    sm[OFF_SB2 + tid] = b2[tid];
    sm[OFF_SB3 + tid] = b3[tid];
    sm[OFF_SB4 + tid] = b4[tid];
  }

  int warp = tid >> 5, lane = tid & 31;
  int g = lane >> 2, tig = lane & 3;

  // ---- phase 1: conv1 MMA (M=676, N=16, K=196), 3 passes of 15 warps ----
  // Reads only global (x, g_w1frag, b1); writes ACT26 — safe to overlap phase 0.
  {
    float* sact = sm + OFF_ACT26;
    for (int pass = 0; pass < 3; pass++) {
      int tile = pass * 15 + warp;
      if (tile >= 43) break;
      float dA[4] = {0.f, 0.f, 0.f, 0.f};
      float dB[4] = {0.f, 0.f, 0.f, 0.f};
      int p0 = tile * 16 + g, p1 = p0 + 8;
      bool ok0 = p0 < 676, ok1 = p1 < 676;
      int oh0 = p0 / 26, ow0 = p0 - oh0 * 26;
      int oh1 = p1 / 26, ow1 = p1 - oh1 * 26;
      int base0 = ok0 ? (oh0 * 1008 + ow0 * 12) : 0;
      int base1 = ok1 ? (oh1 * 1008 + ow1 * 12) : 0;
      float2 v[4];
      {
        int k0 = tig * 2, k8 = k0 + 8;
        int off01 = koff(k0), off89 = koff(k8);
        v[0] = ok0 ? *(const float2*)(x + base0 + off01) : make_float2(0.f, 0.f);
        v[1] = ok1 ? *(const float2*)(x + base1 + off01) : make_float2(0.f, 0.f);
        v[2] = ok0 ? *(const float2*)(x + base0 + off89) : make_float2(0.f, 0.f);
        v[3] = ok1 ? *(const float2*)(x + base1 + off89) : make_float2(0.f, 0.f);
      }
      for (int s = 0; s < 13; s++) {
        uint4 B0 = g_w1frag[(s * 2 + 0) * 32 + lane];
        uint4 B1 = g_w1frag[(s * 2 + 1) * 32 + lane];
        float2 vn[4];
        if (s < 12) {
          int k0n = (s + 1) * 16 + tig * 2, k8n = k0n + 8;
          bool k01ok = k0n < 196, k89ok = k8n < 196;
          int off01 = koff(k01ok ? k0n : 0);
          int off89 = koff(k89ok ? k8n : 0);
          vn[0] = (ok0 && k01ok) ? *(const float2*)(x + base0 + off01) : make_float2(0.f, 0.f);
          vn[1] = (ok1 && k01ok) ? *(const float2*)(x + base1 + off01) : make_float2(0.f, 0.f);
          vn[2] = (ok0 && k89ok) ? *(const float2*)(x + base0 + off89) : make_float2(0.f, 0.f);
          vn[3] = (ok1 && k89ok) ? *(const float2*)(x + base1 + off89) : make_float2(0.f, 0.f);
        }
        unsigned ah[4], al[4];
#pragma unroll
        for (int q = 0; q < 4; q++) SPLIT_PAIR(v[q].x, v[q].y, ah[q], al[q]);
        MMA_BF16(dA[0], dA[1], dA[2], dA[3], ah[0], ah[1], ah[2], ah[3], B0.x, B0.y);
        MMA_BF16(dA[0], dA[1], dA[2], dA[3], ah[0], ah[1], ah[2], ah[3], B0.z, B0.w);
        MMA_BF16(dA[0], dA[1], dA[2], dA[3], al[0], al[1], al[2], al[3], B0.x, B0.y);
        MMA_BF16(dB[0], dB[1], dB[2], dB[3], ah[0], ah[1], ah[2], ah[3], B1.x, B1.y);
        MMA_BF16(dB[0], dB[1], dB[2], dB[3], ah[0], ah[1], ah[2], ah[3], B1.z, B1.w);
        MMA_BF16(dB[0], dB[1], dB[2], dB[3], al[0], al[1], al[2], al[3], B1.x, B1.y);
        if (s < 12) {
#pragma unroll
          for (int q = 0; q < 4; q++) v[q] = vn[q];
        }
      }
      int co0 = tig * 2, co1 = co0 + 1;
      float bb0 = b1[co0], bb1 = b1[co1], bb2 = b1[co0 + 8], bb3 = b1[co1 + 8];
      if (ok0) {
        sact[co0 * 676 + p0] = lrelu(dA[0] + bb0);
        sact[co1 * 676 + p0] = lrelu(dA[1] + bb1);
        sact[(co0 + 8) * 676 + p0] = lrelu(dB[0] + bb2);
        sact[(co1 + 8) * 676 + p0] = lrelu(dB[1] + bb3);
      }
      if (ok1) {
        sact[co0 * 676 + p1] = lrelu(dA[2] + bb0);
        sact[co1 * 676 + p1] = lrelu(dA[3] + bb1);
        sact[(co0 + 8) * 676 + p1] = lrelu(dB[2] + bb2);
        sact[(co1 + 8) * 676 + p1] = lrelu(dB[3] + bb3);
      }
    }
  }
  __syncthreads();

  // ---- phase 2: gaze26 via MMA (M=416, N=26pad32, K=26pad32), in-place ----
  {
    const uint4* kf = (const uint4*)(sm + OFF_K26F);
    float* act = sm + OFF_ACT26;
    for (int pass = 0; pass < 2; pass++) {
      int tile = pass * 15 + warp;
      if (tile < 26) {
        int r0 = tile * 16 + g, r1 = r0 + 8;
        const float* a0p = act + r0 * 26;
        const float* a1p = act + r1 * 26;
        float d[4][4];
#pragma unroll
        for (int nt = 0; nt < 4; nt++)
#pragma unroll
          for (int e = 0; e < 4; e++) d[nt][e] = 0.f;
#pragma unroll
        for (int s = 0; s < 2; s++) {
          int k0 = s * 16 + tig * 2;
          int k8 = k0 + 8;
          bool ok8 = (k8 + 1) < 26;
          float2 v0 = *(const float2*)(a0p + k0);
          float2 v1 = *(const float2*)(a1p + k0);
          float2 v2 = ok8 ? *(const float2*)(a0p + k8) : make_float2(0.f, 0.f);
          float2 v3 = ok8 ? *(const float2*)(a1p + k8) : make_float2(0.f, 0.f);
          unsigned ah[4], al[4];
          SPLIT_PAIR(v0.x, v0.y, ah[0], al[0]);
          SPLIT_PAIR(v1.x, v1.y, ah[1], al[1]);
          SPLIT_PAIR(v2.x, v2.y, ah[2], al[2]);
          SPLIT_PAIR(v3.x, v3.y, ah[3], al[3]);
#pragma unroll
          for (int nt = 0; nt < 4; nt++) {
            uint4 B = kf[(s * 4 + nt) * 32 + lane];
            MMA_BF16(d[nt][0], d[nt][1], d[nt][2], d[nt][3],
                     ah[0], ah[1], ah[2], ah[3], B.x, B.y);
            MMA_BF16(d[nt][0], d[nt][1], d[nt][2], d[nt][3],
                     ah[0], ah[1], ah[2], ah[3], B.z, B.w);
            MMA_BF16(d[nt][0], d[nt][1], d[nt][2], d[nt][3],
                     al[0], al[1], al[2], al[3], B.x, B.y);
          }
        }
        float* w0p = act + r0 * 26;
        float* w1p = act + r1 * 26;
#pragma unroll
        for (int nt = 0; nt < 4; nt++) {
          int c0 = nt * 8 + tig * 2, c1 = c0 + 1;
          if (c0 < 26) { w0p[c0] = d[nt][0]; w1p[c0] = d[nt][2]; }
          if (c1 < 26) { w0p[c1] = d[nt][1]; w1p[c1] = d[nt][3]; }
        }
      }
    }
  }
  __syncthreads();

  // ---- phase 3: conv2 MMA (M=121, N=16, K=400), warps 0-7 ----
  if (warp < 8) {
    const float* sact = sm + OFF_ACT26;
    const int* kt = (const int*)(sm + OFF_KOFF);
    const uint4* wfrag = (const uint4*)(sm + OFF_W2F);
    int p0 = warp * 16 + g, p1 = p0 + 8;
    bool ok0 = p0 < 121, ok1 = p1 < 121;
    int oh0 = p0 / 11, ow0 = p0 - oh0 * 11;
    int oh1 = p1 / 11, ow1 = p1 - oh1 * 11;
    int pb0 = ok0 ? (oh0 * 52 + ow0 * 2) : 0;
    int pb1 = ok1 ? (oh1 * 52 + ow1 * 2) : 0;
    float dA[4] = {0.f, 0.f, 0.f, 0.f};
    float dB[4] = {0.f, 0.f, 0.f, 0.f};
    int k0 = tig * 2;
    for (int s = 0; s < 25; s++, k0 += 16) {
      uint4 B0 = wfrag[(s * 2 + 0) * 32 + lane];
      uint4 B1 = wfrag[(s * 2 + 1) * 32 + lane];
      int o0 = kt[k0], o1 = kt[k0 + 1], o2 = kt[k0 + 8], o3 = kt[k0 + 9];
      float e00 = ok0 ? sact[o0 + pb0] : 0.f, e01 = ok0 ? sact[o1 + pb0] : 0.f;
      float e02 = ok0 ? sact[o2 + pb0] : 0.f, e03 = ok0 ? sact[o3 + pb0] : 0.f;
      float e10 = ok1 ? sact[o0 + pb1] : 0.f, e11 = ok1 ? sact[o1 + pb1] : 0.f;
      float e12 = ok1 ? sact[o2 + pb1] : 0.f, e13 = ok1 ? sact[o3 + pb1] : 0.f;
      unsigned ah[4], al[4];
      SPLIT_PAIR(e00, e01, ah[0], al[0]);
      SPLIT_PAIR(e10, e11, ah[1], al[1]);
      SPLIT_PAIR(e02, e03, ah[2], al[2]);
      SPLIT_PAIR(e12, e13, ah[3], al[3]);
      MMA_BF16(dA[0], dA[1], dA[2], dA[3], ah[0], ah[1], ah[2], ah[3], B0.x, B0.y);
      MMA_BF16(dA[0], dA[1], dA[2], dA[3], ah[0], ah[1], ah[2], ah[3], B0.z, B0.w);
      MMA_BF16(dA[0], dA[1], dA[2], dA[3], al[0], al[1], al[2], al[3], B0.x, B0.y);
      MMA_BF16(dB[0], dB[1], dB[2], dB[3], ah[0], ah[1], ah[2], ah[3], B1.x, B1.y);
      MMA_BF16(dB[0], dB[1], dB[2], dB[3], ah[0], ah[1], ah[2], ah[3], B1.z, B1.w);
      MMA_BF16(dB[0], dB[1], dB[2], dB[3], al[0], al[1], al[2], al[3], B1.x, B1.y);
    }
    float* act11 = sm + OFF_ACT11;
    const float* sb2 = sm + OFF_SB2;
    int co0 = tig * 2, co1 = co0 + 1;
    if (ok0) {
      act11[co0 * 121 + p0] = lrelu(dA[0] + sb2[co0]);
      act11[co1 * 121 + p0] = lrelu(dA[1] + sb2[co1]);
      act11[(co0 + 8) * 121 + p0] = lrelu(dB[0] + sb2[co0 + 8]);
      act11[(co1 + 8) * 121 + p0] = lrelu(dB[1] + sb2[co1 + 8]);
    }
    if (ok1) {
      act11[co0 * 121 + p1] = lrelu(dA[2] + sb2[co0]);
      act11[co1 * 121 + p1] = lrelu(dA[3] + sb2[co1]);
      act11[(co0 + 8) * 121 + p1] = lrelu(dB[2] + sb2[co0 + 8]);
      act11[(co1 + 8) * 121 + p1] = lrelu(dB[3] + sb2[co1 + 8]);
    }
  }
  __syncthreads();

  // ---- phase 4: gaze11 via MMA (M=176, N=11pad16, K=11pad16), warps 0-10, in-place ----
  if (warp < 11) {
    const uint4* kf = (const uint4*)(sm + OFF_K11F);
    float* act = sm + OFF_ACT11;
    int r0 = warp * 16 + g, r1 = r0 + 8;
    const float* a0p = act + r0 * 11;
    const float* a1p = act + r1 * 11;
    int k0 = tig * 2, k8 = k0 + 8;
    float a00 = a0p[k0], a01 = a0p[k0 + 1];
    float a10 = a1p[k0], a11 = a1p[k0 + 1];
    float a02 = (k8 < 11) ? a0p[k8] : 0.f;
    float a03 = (k8 + 1 < 11) ? a0p[k8 + 1] : 0.f;
    float a12 = (k8 < 11) ? a1p[k8] : 0.f;
    float a13 = (k8 + 1 < 11) ? a1p[k8 + 1] : 0.f;
    unsigned ah[4], al[4];
    SPLIT_PAIR(a00, a01, ah[0], al[0]);
    SPLIT_PAIR(a10, a11, ah[1], al[1]);
    SPLIT_PAIR(a02, a03, ah[2], al[2]);
    SPLIT_PAIR(a12, a13, ah[3], al[3]);
    float d[2][4];
#pragma unroll
    for (int nt = 0; nt < 2; nt++)
#pragma unroll
      for (int e = 0; e < 4; e++) d[nt][e] = 0.f;
#pragma unroll
    for (int nt = 0; nt < 2; nt++) {
      uint4 B = kf[nt * 32 + lane];
      MMA_BF16(d[nt][0], d[nt][1], d[nt][2], d[nt][3],
               ah[0], ah[1], ah[2], ah[3], B.x, B.y);
      MMA_BF16(d[nt][0], d[nt][1], d[nt][2], d[nt][3],
               ah[0], ah[1], ah[2], ah[3], B.z, B.w);
      MMA_BF16(d[nt][0], d[nt][1], d[nt][2], d[nt][3],
               al[0], al[1], al[2], al[3], B.x, B.y);
    }
    float* w0p = act + r0 * 11;
    float* w1p = act + r1 * 11;
#pragma unroll
    for (int nt = 0; nt < 2; nt++) {
      int c0 = nt * 8 + tig * 2, c1 = c0 + 1;
      if (c0 < 11) { w0p[c0] = d[nt][0]; w1p[c0] = d[nt][2]; }
      if (c1 < 11) { w0p[c1] = d[nt][1]; w1p[c1] = d[nt][3]; }
    }
  }
  __syncthreads();

  // ---- phase 5: conv3 MMA (M=81, N=16, K=144), warps 0-5 ----
  if (warp < 6) {
    const float* act11 = sm + OFF_ACT11;
    const int* kt3 = (const int*)(sm + OFF_KT3);
    const uint4* wfrag = (const uint4*)(sm + OFF_W3F);
    int p0 = warp * 16 + g, p1 = p0 + 8;
    bool ok0 = p0 < 81, ok1 = p1 < 81;
    int oh0 = p0 / 9, ow0 = p0 - oh0 * 9;
    int oh1 = p1 / 9, ow1 = p1 - oh1 * 9;
    int pb0 = ok0 ? (oh0 * 11 + ow0) : 0;
    int pb1 = ok1 ? (oh1 * 11 + ow1) : 0;
    float dA[4] = {0.f, 0.f, 0.f, 0.f};
    float dB[4] = {0.f, 0.f, 0.f, 0.f};
    int k0 = tig * 2;
    for (int s = 0; s < 9; s++, k0 += 16) {
      uint4 B0 = wfrag[(s * 2 + 0) * 32 + lane];
      uint4 B1 = wfrag[(s * 2 + 1) * 32 + lane];
      int o0 = kt3[k0], o1 = kt3[k0 + 1], o2 = kt3[k0 + 8], o3 = kt3[k0 + 9];
      float e00 = ok0 ? act11[o0 + pb0] : 0.f, e01 = ok0 ? act11[o1 + pb0] : 0.f;
      float e02 = ok0 ? act11[o2 + pb0] : 0.f, e03 = ok0 ? act11[o3 + pb0] : 0.f;
      float e10 = ok1 ? act11[o0 + pb1] : 0.f, e11 = ok1 ? act11[o1 + pb1] : 0.f;
      float e12 = ok1 ? act11[o2 + pb1] : 0.f, e13 = ok1 ? act11[o3 + pb1] : 0.f;
      unsigned ah[4], al[4];
      SPLIT_PAIR(e00, e01, ah[0], al[0]);
      SPLIT_PAIR(e10, e11, ah[1], al[1]);
      SPLIT_PAIR(e02, e03, ah[2], al[2]);
      SPLIT_PAIR(e12, e13, ah[3], al[3]);
      MMA_BF16(dA[0], dA[1], dA[2], dA[3], ah[0], ah[1], ah[2], ah[3], B0.x, B0.y);
      MMA_BF16(dA[0], dA[1], dA[2], dA[3], ah[0], ah[1], ah[2], ah[3], B0.z, B0.w);
      MMA_BF16(dA[0], dA[1], dA[2], dA[3], al[0], al[1], al[2], al[3], B0.x, B0.y);
      MMA_BF16(dB[0], dB[1], dB[2], dB[3], ah[0], ah[1], ah[2], ah[3], B1.x, B1.y);
      MMA_BF16(dB[0], dB[1], dB[2], dB[3], ah[0], ah[1], ah[2], ah[3], B1.z, B1.w);
      MMA_BF16(dB[0], dB[1], dB[2], dB[3], al[0], al[1], al[2], al[3], B1.x, B1.y);
    }
    float* act9 = sm + OFF_ACT9;
    const float* sb3 = sm + OFF_SB3;
    int co0 = tig * 2, co1 = co0 + 1;
    if (ok0) {
      act9[co0 * 81 + p0] = lrelu(dA[0] + sb3[co0]);
      act9[co1 * 81 + p0] = lrelu(dA[1] + sb3[co1]);
      act9[(co0 + 8) * 81 + p0] = lrelu(dB[0] + sb3[co0 + 8]);
      act9[(co1 + 8) * 81 + p0] = lrelu(dB[1] + sb3[co1 + 8]);
    }
    if (ok1) {
      act9[co0 * 81 + p1] = lrelu(dA[2] + sb3[co0]);
      act9[co1 * 81 + p1] = lrelu(dA[3] + sb3[co1]);
      act9[(co0 + 8) * 81 + p1] = lrelu(dB[2] + sb3[co0 + 8]);
      act9[(co1 + 8) * 81 + p1] = lrelu(dB[3] + sb3[co1 + 8]);
    }
  }
  __syncthreads();

  // ---- phase 6: conv4 MMA (M=49, N=16, K=144), warps 0-3 ----
  if (warp < 4) {
    const float* act9 = sm + OFF_ACT9;
    const int* kt4 = (const int*)(sm + OFF_KT4);
    const uint4* wfrag = (const uint4*)(sm + OFF_W4F);
    int p0 = warp * 16 + g, p1 = p0 + 8;
    bool ok0 = p0 < 49, ok1 = p1 < 49;
    int oh0 = p0 / 7, ow0 = p0 - oh0 * 7;
    int oh1 = p1 / 7, ow1 = p1 - oh1 * 7;
    int pb0 = ok0 ? (oh0 * 9 + ow0) : 0;
    int pb1 = ok1 ? (oh1 * 9 + ow1) : 0;
    float dA[4] = {0.f, 0.f, 0.f, 0.f};
    float dB[4] = {0.f, 0.f, 0.f, 0.f};
    int k0 = tig * 2;
    for (int s = 0; s < 9; s++, k0 += 16) {
      uint4 B0 = wfrag[(s * 2 + 0) * 32 + lane];
      uint4 B1 = wfrag[(s * 2 + 1) * 32 + lane];
      int o0 = kt4[k0], o1 = kt4[k0 + 1], o2 = kt4[k0 + 8], o3 = kt4[k0 + 9];
      float e00 = ok0 ? act9[o0 + pb0] : 0.f, e01 = ok0 ? act9[o1 + pb0] : 0.f;
      float e02 = ok0 ? act9[o2 + pb0] : 0.f, e03 = ok0 ? act9[o3 + pb0] : 0.f;
      float e10 = ok1 ? act9[o0 + pb1] : 0.f, e11 = ok1 ? act9[o1 + pb1] : 0.f;
      float e12 = ok1 ? act9[o2 + pb1] : 0.f, e13 = ok1 ? act9[o3 + pb1] : 0.f;
      unsigned ah[4], al[4];
      SPLIT_PAIR(e00, e01, ah[0], al[0]);
      SPLIT_PAIR(e10, e11, ah[1], al[1]);
      SPLIT_PAIR(e02, e03, ah[2], al[2]);
      SPLIT_PAIR(e12, e13, ah[3], al[3]);
      MMA_BF16(dA[0], dA[1], dA[2], dA[3], ah[0], ah[1], ah[2], ah[3], B0.x, B0.y);
      MMA_BF16(dA[0], dA[1], dA[2], dA[3], ah[0], ah[1], ah[2], ah[3], B0.z, B0.w);
      MMA_BF16(dA[0], dA[1], dA[2], dA[3], al[0], al[1], al[2], al[3], B0.x, B0.y);
      MMA_BF16(dB[0], dB[1], dB[2], dB[3], ah[0], ah[1], ah[2], ah[3], B1.x, B1.y);
      MMA_BF16(dB[0], dB[1], dB[2], dB[3], ah[0], ah[1], ah[2], ah[3], B1.z, B1.w);
      MMA_BF16(dB[0], dB[1], dB[2], dB[3], al[0], al[1], al[2], al[3], B1.x, B1.y);
    }
    const float* sb4 = sm + OFF_SB4;
    int co0 = tig * 2, co1 = co0 + 1;
    if (ok0) {
      float* xp = g_xf + (size_t)n * 784 + p0;
      float v0 = lrelu(dA[0] + sb4[co0]);
      float v1 = lrelu(dA[1] + sb4[co1]);
      float v2 = lrelu(dB[0] + sb4[co0 + 8]);
      float v3 = lrelu(dB[1] + sb4[co1 + 8]);
      xp[co0 * 49] = v0; xp[co1 * 49] = v1;
      xp[(co0 + 8) * 49] = v2; xp[(co1 + 8) * 49] = v3;
      sm[OFF_SCM + p0 * 4 + tig] = v0 + v1 + v2 + v3;
    }
    if (ok1) {
      float* xp = g_xf + (size_t)n * 784 + p1;
      float v0 = lrelu(dA[2] + sb4[co0]);
      float v1 = lrelu(dA[3] + sb4[co1]);
      float v2 = lrelu(dB[2] + sb4[co0 + 8]);
      float v3 = lrelu(dB[3] + sb4[co1 + 8]);
      xp[co0 * 49] = v0; xp[co1 * 49] = v1;
      xp[(co0 + 8) * 49] = v2; xp[(co1 + 8) * 49] = v3;
      sm[OFF_SCM + p1 * 4 + tig] = v0 + v1 + v2 + v3;
    }
  }
  __syncthreads();
  if (tid < 49) {
    const float* s4 = sm + OFF_SCM + tid * 4;
    g_cm[(size_t)n * 49 + tid] = (s4[0] + s4[1]) + (s4[2] + s4[3]);
  }
}

// ---------------- fc ----------------
__global__ __launch_bounds__(256) void k_fc(const float* __restrict__ w1,
                                            const float* __restrict__ b1,
                                            const float* __restrict__ w2,
                                            const float* __restrict__ b2) {
  __shared__ float As[64][17];
  __shared__ float Bs[16][68];
  __shared__ float prs[16][64];
  int tid = threadIdx.x;
  int s0 = blockIdx.x * 64;
  int sg = tid >> 4, jg = tid & 15;
  float acc[4][4];
#pragma unroll
  for (int i = 0; i < 4; i++)
#pragma unroll
    for (int u = 0; u < 4; u++) acc[i][u] = 0.f;
  for (int k0 = 0; k0 < 784; k0 += 16) {
    for (int i = tid; i < 1024; i += 256) {
      int s = i >> 4, kk = i & 15;
      As[s][kk] = g_xf[(size_t)(s0 + s) * 784 + k0 + kk];
    }
    for (int i = tid; i < 1024; i += 256) {
      int j = i >> 4, kk = i & 15;
      Bs[kk][j] = w1[j * 784 + k0 + kk];
    }
    __syncthreads();
#pragma unroll
    for (int kk = 0; kk < 16; kk++) {
      float av[4], bv[4];
#pragma unroll
      for (int i = 0; i < 4; i++) av[i] = As[sg * 4 + i][kk];
#pragma unroll
      for (int u = 0; u < 4; u++) bv[u] = Bs[kk][jg * 4 + u];
#pragma unroll
      for (int i = 0; i < 4; i++)
#pragma unroll
        for (int u = 0; u < 4; u++) acc[i][u] += av[i] * bv[u];
    }
    __syncthreads();
  }
#pragma unroll
  for (int i = 0; i < 4; i++) {
    float pr = 0.f;
#pragma unroll
    for (int u = 0; u < 4; u++) {
      int j = jg * 4 + u;
      float h = acc[i][u] + b1[j];
      h = lrelu(h);
      pr += h * w2[j];
    }
    prs[jg][sg * 4 + i] = pr;
  }
  __syncthreads();
  if (tid < 64) {
    float s = 0.f;
#pragma unroll
    for (int j = 0; j < 16; j++) s += prs[j][tid];
    g_r[s0 + tid] = s + b2[0];
  }
}

__global__ void k_reduce_r(float* __restrict__ out) {
  __shared__ float sab[64];
  int tid = threadIdx.x;
  int traj = tid >> 5, b = tid & 31;
  float s = 0.f, sa = 0.f;
  for (int t = 0; t < 64; t++) {
    float r = g_r[traj * 2048 + t * 32 + b];
    s += r;
    sa += fabsf(r);
  }
  out[tid] = s;
  sab[tid] = sa;
  __syncthreads();
  if (tid < 32) out[64 + tid] = sab[tid] + sab[32 + tid];
}

__global__ __launch_bounds__(256) void k_cmnorm(float* __restrict__ out) {
  __shared__ float sv[1568];
  __shared__ float smn[8], smx[8];
  __shared__ float fmn, fmx;
  int idx = blockIdx.x;
  int traj = idx >> 6, t = idx & 63;
  int tid = threadIdx.x;
  const float* base = g_cm + ((size_t)(traj * 2048 + t * 32)) * 49;
  float mn = 1e30f, mx = -1e30f;
  for (int i = tid; i < 1568; i += 256) {
    float v = base[i];
    sv[i] = v;
    mn = fminf(mn, v);
    mx = fmaxf(mx, v);
  }
#pragma unroll
  for (int o = 16; o; o >>= 1) {
    mn = fminf(mn, __shfl_xor_sync(0xffffffffu, mn, o));
    mx = fmaxf(mx, __shfl_xor_sync(0xffffffffu, mx, o));
  }
  if ((tid & 31) == 0) { smn[tid >> 5] = mn; smx[tid >> 5] = mx; }
  __syncthreads();
  if (tid == 0) {
    float a = smn[0], bb = smx[0];
    for (int i = 1; i < 8; i++) { a = fminf(a, smn[i]); bb = fmaxf(bb, smx[i]); }
    fmn = a; fmx = bb;
  }
  __syncthreads();
  float m = fmn, inv = 1.f / (fmx - m);
  float* o = out + 96 + (size_t)traj * 100352 + (size_t)t * 1568;
  for (int i = tid; i < 1568; i += 256) o[i] = (sv[i] - m) * inv;
}

extern "C" void kernel_launch(void* const* d_in, const int* in_sizes, int n_in,
                              void* d_out, int out_size) {
  const float* ti   = (const float*)d_in[0];
  const float* tj   = (const float*)d_in[1];
  const float* g26i = (const float*)d_in[2];
  const float* g11i = (const float*)d_in[3];
  const float* g26j = (const float*)d_in[4];
  const float* g11j = (const float*)d_in[5];
  const float* w1 = (const float*)d_in[6];  const float* b1 = (const float*)d_in[7];
  const float* w2 = (const float*)d_in[8];  const float* b2 = (const float*)d_in[9];
  const float* w3 = (const float*)d_in[10]; const float* b3 = (const float*)d_in[11];
  const float* w4 = (const float*)d_in[12]; const float* b4 = (const float*)d_in[13];
  const float* f1w = (const float*)d_in[14]; const float* f1b = (const float*)d_in[15];
  const float* f2w = (const float*)d_in[16]; const float* f2b = (const float*)d_in[17];
  float* out = (float*)d_out;

  cudaFuncSetAttribute(k_net, cudaFuncAttributeMaxDynamicSharedMemorySize,
                       SMEM_FLOATS * 4);

  k_prep<<<4, 512>>>(w1, w2, w3, w4);
  k_net<<<NTOT, TPB, SMEM_FLOATS * 4>>>(ti, tj, g26i, g26j, g11i, g11j,
                                        b1, b2, b3, b4);
  k_fc<<<NTOT / 64, 256>>>(f1w, f1b, f2w, f2b);
  k_reduce_r<<<1, 64>>>(out);
  k_cmnorm<<<128, 256>>>(out);
}

// round 17
// speedup vs baseline: 1.7878x; 1.0310x over previous
#include <cuda_runtime.h>
#include <math.h>

#define NPT 2048
#define NTOT 4096
#define TPB 512
typedef unsigned long long ull;

__device__ float g_xf[(size_t)NTOT * 784];
__device__ float g_cm[(size_t)NTOT * 49];
__device__ float g_r[NTOT];
// bf16-split fragment-ready weights (built once by k_prep)
__device__ uint4 g_w1frag[832];   // conv1 [s13][nt2][lane32]
__device__ uint4 g_w2frag[1600];  // conv2 [s25][nt2][lane32]
__device__ uint4 g_w3frag[576];   // conv3 [s9][nt2][lane32]
__device__ uint4 g_w4frag[576];   // conv4 [s9][nt2][lane32]

__device__ __forceinline__ float lrelu(float v) { return v >= 0.f ? v : 0.01f * v; }
__device__ __forceinline__ unsigned bf2pack(float hi_elem, float lo_elem) {
  unsigned u; asm("cvt.rn.bf16x2.f32 %0, %1, %2;" : "=r"(u) : "f"(hi_elem), "f"(lo_elem));
  return u;
}
#define MMA_BF16(d0,d1,d2,d3,a0,a1,a2,a3,b0,b1) \
  asm("mma.sync.aligned.m16n8k16.row.col.f32.bf16.bf16.f32 " \
      "{%0,%1,%2,%3},{%4,%5,%6,%7},{%8,%9},{%0,%1,%2,%3};" \
      : "+f"(d0),"+f"(d1),"+f"(d2),"+f"(d3) \
      : "r"(a0),"r"(a1),"r"(a2),"r"(a3),"r"(b0),"r"(b1))

#define SPLIT_PAIR(fx, fy, hi, lo_) do { \
  unsigned xb = __float_as_uint(fx), yb = __float_as_uint(fy); \
  hi = __byte_perm(xb, yb, 0x7632); \
  float lx = (fx) - __uint_as_float(xb & 0xffff0000u); \
  float ly = (fy) - __uint_as_float(yb & 0xffff0000u); \
  lo_ = bf2pack(ly, lx); \
} while (0)

// smem float offsets (27268 floats = 109072 B -> 2 blocks/SM)
#define OFF_ACT26 0        // 10816 (= [416][26]); PBUF3/PBUF4 overlay after conv2
#define OFF_W2F   10816    // 6400 (1600 uint4)
#define OFF_W3F   17216    // 2304 (576 uint4)
#define OFF_W4F   19520    // 2304 (576 uint4)
#define OFF_K26F  21824    // 1024 (dead after phase 2)
#define OFF_ACT9  22848    // 1296 (written phase 5)
#define OFF_PBUF2 21824    // 2048 overlay of K26F+ACT9 (used only during phase 3)
#define OFF_K11F  24144    // 256  (live until phase 4)
#define OFF_ACT11 24400    // 1936
#define OFF_SB2   26336
#define OFF_SB3   26352
#define OFF_SB4   26368
#define OFF_SCM   26384    // 196
#define OFF_KOFF  26580    // 400 ints
#define OFF_KT3   26980    // 144 ints
#define OFF_KT4   27124    // 144 ints
#define SMEM_FLOATS 27268
#define OFF_PBUF3 0        // 1536 overlay of ACT26 (phase 5)
#define OFF_PBUF4 0        // 1024 overlay of ACT26 (phase 6)

__device__ __forceinline__ int koff(int k) {
  int ci = k & 3, t = k >> 2;
  int kw = t % 7, kh = t / 7;
  return kh * 336 + kw * 4 + ci;
}

// ---------------- one-time weight prep ----------------
__global__ void k_prep(const float* __restrict__ w1, const float* __restrict__ w2,
                       const float* __restrict__ w3, const float* __restrict__ w4) {
  int tid = blockIdx.x * blockDim.x + threadIdx.x;
  for (int idx = tid; idx < 832; idx += 2048) {
    int lane = idx & 31, sn = idx >> 5;
    int s = sn >> 1, nt = sn & 1;
    int tig = lane & 3, gq = lane >> 2;
    int co = nt * 8 + gq;
    float wv[4];
    int k0 = s * 16 + tig * 2;
#pragma unroll
    for (int e = 0; e < 4; e++) {
      int k = k0 + (e >> 1) * 8 + (e & 1);
      float w = 0.f;
      if (k < 196) {
        int ci = k & 3, t = k >> 2, kw = t % 7, kh = t / 7;
        w = w1[co * 196 + ci * 49 + kh * 7 + kw];
      }
      wv[e] = w;
    }
    unsigned hb[4]; float lo[4];
#pragma unroll
    for (int e = 0; e < 4; e++) {
      hb[e] = __float_as_uint(wv[e]) & 0xffff0000u;
      lo[e] = wv[e] - __uint_as_float(hb[e]);
    }
    uint4 out;
    out.x = (hb[0] >> 16) | (hb[1] & 0xffff0000u);
    out.y = (hb[2] >> 16) | (hb[3] & 0xffff0000u);
    out.z = bf2pack(lo[1], lo[0]);
    out.w = bf2pack(lo[3], lo[2]);
    g_w1frag[idx] = out;
  }
  for (int idx = tid; idx < 1600; idx += 2048) {
    int lane = idx & 31, sn = idx >> 5;
    int s = sn >> 1, nt = sn & 1;
    int tig = lane & 3, gq = lane >> 2;
    int co = nt * 8 + gq;
    float wv[4];
    int k0 = s * 16 + tig * 2;
#pragma unroll
    for (int e = 0; e < 4; e++) {
      int k = k0 + (e >> 1) * 8 + (e & 1);
      wv[e] = w2[co * 400 + k];
    }
    unsigned hb[4]; float lo[4];
#pragma unroll
    for (int e = 0; e < 4; e++) {
      hb[e] = __float_as_uint(wv[e]) & 0xffff0000u;
      lo[e] = wv[e] - __uint_as_float(hb[e]);
    }
    uint4 out;
    out.x = (hb[0] >> 16) | (hb[1] & 0xffff0000u);
    out.y = (hb[2] >> 16) | (hb[3] & 0xffff0000u);
    out.z = bf2pack(lo[1], lo[0]);
    out.w = bf2pack(lo[3], lo[2]);
    g_w2frag[idx] = out;
  }
  for (int idx = tid; idx < 1152; idx += 2048) {
    int which = idx >= 576;
    int id2 = idx - which * 576;
    const float* w = which ? w4 : w3;
    int lane = id2 & 31, sn = id2 >> 5;
    int s = sn >> 1, nt = sn & 1;
    int tig = lane & 3, gq = lane >> 2;
    int co = nt * 8 + gq;
    float wv[4];
    int k0 = s * 16 + tig * 2;
#pragma unroll
    for (int e = 0; e < 4; e++) {
      int k = k0 + (e >> 1) * 8 + (e & 1);
      wv[e] = w[co * 144 + k];
    }
    unsigned hb[4]; float lo[4];
#pragma unroll
    for (int e = 0; e < 4; e++) {
      hb[e] = __float_as_uint(wv[e]) & 0xffff0000u;
      lo[e] = wv[e] - __uint_as_float(hb[e]);
    }
    uint4 out;
    out.x = (hb[0] >> 16) | (hb[1] & 0xffff0000u);
    out.y = (hb[2] >> 16) | (hb[3] & 0xffff0000u);
    out.z = bf2pack(lo[1], lo[0]);
    out.w = bf2pack(lo[3], lo[2]);
    if (which) g_w4frag[id2] = out; else g_w3frag[id2] = out;
  }
}

__global__ __launch_bounds__(TPB, 2) void k_net(
    const float* __restrict__ ti, const float* __restrict__ tj,
    const float* __restrict__ g26i, const float* __restrict__ g26j,
    const float* __restrict__ g11i, const float* __restrict__ g11j,
    const float* __restrict__ b1, const float* __restrict__ b2,
    const float* __restrict__ b3, const float* __restrict__ b4) {
  extern __shared__ float sm[];
  int n = blockIdx.x, tid = threadIdx.x;
  const float sc = 1.0f / (0.7f * 0.3f);

  const float* x   = (n < NPT) ? ti   + (size_t)n * 28224 : tj   + (size_t)(n - NPT) * 28224;
  const float* g26 = (n < NPT) ? g26i + (size_t)n * 676   : g26j + (size_t)(n - NPT) * 676;
  const float* g11 = (n < NPT) ? g11i + (size_t)n * 121   : g11j + (size_t)(n - NPT) * 121;

  // ---- phase 0 (overlaps conv1; no barrier before conv1) ----
  {
    uint4* w2f = (uint4*)(sm + OFF_W2F);
    for (int i = tid; i < 1600; i += TPB) w2f[i] = g_w2frag[i];
    uint4* w3f = (uint4*)(sm + OFF_W3F);
    for (int i = tid; i < 576; i += TPB) w3f[i] = g_w3frag[i];
    uint4* w4f = (uint4*)(sm + OFF_W4F);
    for (int i = tid; i < 576; i += TPB) w4f[i] = g_w4frag[i];
  }
  {
    uint4* kf = (uint4*)(sm + OFF_K26F);
    for (int i = tid; i < 256; i += TPB) {
      int lane = i & 31, sn = i >> 5;
      int s = sn >> 2, nt = sn & 3;
      int tig = lane & 3, gq = lane >> 2;
      int col = nt * 8 + gq;
      float wv[4];
      int w0 = s * 16 + tig * 2;
#pragma unroll
      for (int e = 0; e < 4; e++) {
        int w = w0 + (e >> 1) * 8 + (e & 1);
        wv[e] = (w < 26 && col < 26) ? (g26[w * 26 + col] - 0.3f) * sc : 0.f;
      }
      unsigned hb[4]; float lo[4];
#pragma unroll
      for (int e = 0; e < 4; e++) {
        hb[e] = __float_as_uint(wv[e]) & 0xffff0000u;
        lo[e] = wv[e] - __uint_as_float(hb[e]);
      }
      uint4 out;
      out.x = (hb[0] >> 16) | (hb[1] & 0xffff0000u);
      out.y = (hb[2] >> 16) | (hb[3] & 0xffff0000u);
      out.z = bf2pack(lo[1], lo[0]);
      out.w = bf2pack(lo[3], lo[2]);
      kf[i] = out;
    }
  }
  {
    uint4* kf = (uint4*)(sm + OFF_K11F);
    for (int i = tid; i < 64; i += TPB) {
      int lane = i & 31, nt = i >> 5;
      int tig = lane & 3, gq = lane >> 2;
      int col = nt * 8 + gq;
      float wv[4];
      int w0 = tig * 2;
#pragma unroll
      for (int e = 0; e < 4; e++) {
        int w = w0 + (e >> 1) * 8 + (e & 1);
        wv[e] = (w < 11 && col < 11) ? (g11[w * 11 + col] - 0.3f) * sc : 0.f;
      }
      unsigned hb[4]; float lo[4];
#pragma unroll
      for (int e = 0; e < 4; e++) {
        hb[e] = __float_as_uint(wv[e]) & 0xffff0000u;
        lo[e] = wv[e] - __uint_as_float(hb[e]);
      }
      uint4 out;
      out.x = (hb[0] >> 16) | (hb[1] & 0xffff0000u);
      out.y = (hb[2] >> 16) | (hb[3] & 0xffff0000u);
      out.z = bf2pack(lo[1], lo[0]);
      out.w = bf2pack(lo[3], lo[2]);
      kf[i] = out;
    }
  }
  {
    int* kt = (int*)(sm + OFF_KOFF);
    for (int k = tid; k < 400; k += TPB) {
      int ci = k / 25, t = k - ci * 25, kh = t / 5, kw = t - kh * 5;
      kt[k] = ci * 676 + kh * 26 + kw;
    }
    int* kt3 = (int*)(sm + OFF_KT3);
    int* kt4 = (int*)(sm + OFF_KT4);
    for (int k = tid; k < 144; k += TPB) {
      int ci = k / 9, t = k - ci * 9, kh = t / 3, kw = t - kh * 3;
      kt3[k] = ci * 121 + kh * 11 + kw;
      kt4[k] = ci * 81 + kh * 9 + kw;
    }
  }
  if (tid < 16) {
    sm[OFF_SB2 + tid] = b2[tid];
    sm[OFF_SB3 + tid] = b3[tid];
    sm[OFF_SB4 + tid] = b4[tid];
  }

  int warp = tid >> 5, lane = tid & 31;
  int g = lane >> 2, tig = lane & 3;

  // ---- phase 1: conv1 MMA (M=676, N=16, K=196), 3 passes of 16 warps ----
  {
    float* sact = sm + OFF_ACT26;
    for (int pass = 0; pass < 3; pass++) {
      int tile = pass * 16 + warp;
      if (tile >= 43) break;
      float dA[4] = {0.f, 0.f, 0.f, 0.f};
      float dB[4] = {0.f, 0.f, 0.f, 0.f};
      int p0 = tile * 16 + g, p1 = p0 + 8;
      bool ok0 = p0 < 676, ok1 = p1 < 676;
      int oh0 = p0 / 26, ow0 = p0 - oh0 * 26;
      int oh1 = p1 / 26, ow1 = p1 - oh1 * 26;
      int base0 = ok0 ? (oh0 * 1008 + ow0 * 12) : 0;
      int base1 = ok1 ? (oh1 * 1008 + ow1 * 12) : 0;
      for (int s = 0; s < 13; s++) {
        int k0 = s * 16 + tig * 2, k8 = k0 + 8;
        bool k01ok = k0 < 196, k89ok = k8 < 196;
        int off01 = koff(k01ok ? k0 : 0);
        int off89 = koff(k89ok ? k8 : 0);
        uint4 B0 = g_w1frag[(s * 2 + 0) * 32 + lane];
        uint4 B1 = g_w1frag[(s * 2 + 1) * 32 + lane];
        float2 v[4];
        v[0] = (ok0 && k01ok) ? *(const float2*)(x + base0 + off01) : make_float2(0.f, 0.f);
        v[1] = (ok1 && k01ok) ? *(const float2*)(x + base1 + off01) : make_float2(0.f, 0.f);
        v[2] = (ok0 && k89ok) ? *(const float2*)(x + base0 + off89) : make_float2(0.f, 0.f);
        v[3] = (ok1 && k89ok) ? *(const float2*)(x + base1 + off89) : make_float2(0.f, 0.f);
        unsigned ah[4], al[4];
#pragma unroll
        for (int q = 0; q < 4; q++) SPLIT_PAIR(v[q].x, v[q].y, ah[q], al[q]);
        MMA_BF16(dA[0], dA[1], dA[2], dA[3], ah[0], ah[1], ah[2], ah[3], B0.x, B0.y);
        MMA_BF16(dA[0], dA[1], dA[2], dA[3], ah[0], ah[1], ah[2], ah[3], B0.z, B0.w);
        MMA_BF16(dA[0], dA[1], dA[2], dA[3], al[0], al[1], al[2], al[3], B0.x, B0.y);
        MMA_BF16(dB[0], dB[1], dB[2], dB[3], ah[0], ah[1], ah[2], ah[3], B1.x, B1.y);
        MMA_BF16(dB[0], dB[1], dB[2], dB[3], ah[0], ah[1], ah[2], ah[3], B1.z, B1.w);
        MMA_BF16(dB[0], dB[1], dB[2], dB[3], al[0], al[1], al[2], al[3], B1.x, B1.y);
      }
      int co0 = tig * 2, co1 = co0 + 1;
      float bb0 = b1[co0], bb1 = b1[co1], bb2 = b1[co0 + 8], bb3 = b1[co1 + 8];
      if (ok0) {
        sact[co0 * 676 + p0] = lrelu(dA[0] + bb0);
        sact[co1 * 676 + p0] = lrelu(dA[1] + bb1);
        sact[(co0 + 8) * 676 + p0] = lrelu(dB[0] + bb2);
        sact[(co1 + 8) * 676 + p0] = lrelu(dB[1] + bb3);
      }
      if (ok1) {
        sact[co0 * 676 + p1] = lrelu(dA[2] + bb0);
        sact[co1 * 676 + p1] = lrelu(dA[3] + bb1);
        sact[(co0 + 8) * 676 + p1] = lrelu(dB[2] + bb2);
        sact[(co1 + 8) * 676 + p1] = lrelu(dB[3] + bb3);
      }
    }
  }
  __syncthreads();

  // ---- phase 2: gaze26 via MMA (M=416, N/K pad32), in-place ----
  {
    const uint4* kf = (const uint4*)(sm + OFF_K26F);
    float* act = sm + OFF_ACT26;
    for (int pass = 0; pass < 2; pass++) {
      int tile = pass * 16 + warp;
      if (tile < 26) {
        int r0 = tile * 16 + g, r1 = r0 + 8;
        const float* a0p = act + r0 * 26;
        const float* a1p = act + r1 * 26;
        float d[4][4];
#pragma unroll
        for (int nt = 0; nt < 4; nt++)
#pragma unroll
          for (int e = 0; e < 4; e++) d[nt][e] = 0.f;
#pragma unroll
        for (int s = 0; s < 2; s++) {
          int k0 = s * 16 + tig * 2;
          int k8 = k0 + 8;
          bool ok8 = (k8 + 1) < 26;
          float2 v0 = *(const float2*)(a0p + k0);
          float2 v1 = *(const float2*)(a1p + k0);
          float2 v2 = ok8 ? *(const float2*)(a0p + k8) : make_float2(0.f, 0.f);
          float2 v3 = ok8 ? *(const float2*)(a1p + k8) : make_float2(0.f, 0.f);
          unsigned ah[4], al[4];
          SPLIT_PAIR(v0.x, v0.y, ah[0], al[0]);
          SPLIT_PAIR(v1.x, v1.y, ah[1], al[1]);
          SPLIT_PAIR(v2.x, v2.y, ah[2], al[2]);
          SPLIT_PAIR(v3.x, v3.y, ah[3], al[3]);
#pragma unroll
          for (int nt = 0; nt < 4; nt++) {
            uint4 B = kf[(s * 4 + nt) * 32 + lane];
            MMA_BF16(d[nt][0], d[nt][1], d[nt][2], d[nt][3],
                     ah[0], ah[1], ah[2], ah[3], B.x, B.y);
            MMA_BF16(d[nt][0], d[nt][1], d[nt][2], d[nt][3],
                     ah[0], ah[1], ah[2], ah[3], B.z, B.w);
            MMA_BF16(d[nt][0], d[nt][1], d[nt][2], d[nt][3],
                     al[0], al[1], al[2], al[3], B.x, B.y);
          }
        }
        float* w0p = act + r0 * 26;
        float* w1p = act + r1 * 26;
#pragma unroll
        for (int nt = 0; nt < 4; nt++) {
          int c0 = nt * 8 + tig * 2, c1 = c0 + 1;
          if (c0 < 26) { w0p[c0] = d[nt][0]; w1p[c0] = d[nt][2]; }
          if (c1 < 26) { w0p[c1] = d[nt][1]; w1p[c1] = d[nt][3]; }
        }
      }
    }
  }
  __syncthreads();

  // ---- phase 3: conv2 MMA (M=121, N=16, K=400), 2-way K-split, 16 units ----
  {
    int tile = warp & 7, khalf = warp >> 3;
    const float* sact = sm + OFF_ACT26;
    const int* kt = (const int*)(sm + OFF_KOFF);
    const uint4* wfrag = (const uint4*)(sm + OFF_W2F);
    int p0 = tile * 16 + g, p1 = p0 + 8;
    bool ok0 = p0 < 121, ok1 = p1 < 121;
    int oh0 = p0 / 11, ow0 = p0 - oh0 * 11;
    int oh1 = p1 / 11, ow1 = p1 - oh1 * 11;
    int pb0 = ok0 ? (oh0 * 52 + ow0 * 2) : 0;
    int pb1 = ok1 ? (oh1 * 52 + ow1 * 2) : 0;
    float dA[4] = {0.f, 0.f, 0.f, 0.f};
    float dB[4] = {0.f, 0.f, 0.f, 0.f};
    int sbeg = khalf ? 13 : 0, send = khalf ? 25 : 13;
    int k0 = sbeg * 16 + tig * 2;
    for (int s = sbeg; s < send; s++, k0 += 16) {
      uint4 B0 = wfrag[(s * 2 + 0) * 32 + lane];
      uint4 B1 = wfrag[(s * 2 + 1) * 32 + lane];
      int o0 = kt[k0], o1 = kt[k0 + 1], o2 = kt[k0 + 8], o3 = kt[k0 + 9];
      float e00 = ok0 ? sact[o0 + pb0] : 0.f, e01 = ok0 ? sact[o1 + pb0] : 0.f;
      float e02 = ok0 ? sact[o2 + pb0] : 0.f, e03 = ok0 ? sact[o3 + pb0] : 0.f;
      float e10 = ok1 ? sact[o0 + pb1] : 0.f, e11 = ok1 ? sact[o1 + pb1] : 0.f;
      float e12 = ok1 ? sact[o2 + pb1] : 0.f, e13 = ok1 ? sact[o3 + pb1] : 0.f;
      unsigned ah[4], al[4];
      SPLIT_PAIR(e00, e01, ah[0], al[0]);
      SPLIT_PAIR(e10, e11, ah[1], al[1]);
      SPLIT_PAIR(e02, e03, ah[2], al[2]);
      SPLIT_PAIR(e12, e13, ah[3], al[3]);
      MMA_BF16(dA[0], dA[1], dA[2], dA[3], ah[0], ah[1], ah[2], ah[3], B0.x, B0.y);
      MMA_BF16(dA[0], dA[1], dA[2], dA[3], ah[0], ah[1], ah[2], ah[3], B0.z, B0.w);
      MMA_BF16(dA[0], dA[1], dA[2], dA[3], al[0], al[1], al[2], al[3], B0.x, B0.y);
      MMA_BF16(dB[0], dB[1], dB[2], dB[3], ah[0], ah[1], ah[2], ah[3], B1.x, B1.y);
      MMA_BF16(dB[0], dB[1], dB[2], dB[3], ah[0], ah[1], ah[2], ah[3], B1.z, B1.w);
      MMA_BF16(dB[0], dB[1], dB[2], dB[3], al[0], al[1], al[2], al[3], B1.x, B1.y);
    }
    float* pb = sm + OFF_PBUF2 + tile * 256 + lane * 8;
    if (khalf) {
#pragma unroll
      for (int e = 0; e < 4; e++) { pb[e] = dA[e]; pb[4 + e] = dB[e]; }
    }
    __syncthreads();
    if (!khalf) {
#pragma unroll
      for (int e = 0; e < 4; e++) { dA[e] += pb[e]; dB[e] += pb[4 + e]; }
      float* act11 = sm + OFF_ACT11;
      const float* sb2 = sm + OFF_SB2;
      int co0 = tig * 2, co1 = co0 + 1;
      if (ok0) {
        act11[co0 * 121 + p0] = lrelu(dA[0] + sb2[co0]);
        act11[co1 * 121 + p0] = lrelu(dA[1] + sb2[co1]);
        act11[(co0 + 8) * 121 + p0] = lrelu(dB[0] + sb2[co0 + 8]);
        act11[(co1 + 8) * 121 + p0] = lrelu(dB[1] + sb2[co1 + 8]);
      }
      if (ok1) {
        act11[co0 * 121 + p1] = lrelu(dA[2] + sb2[co0]);
        act11[co1 * 121 + p1] = lrelu(dA[3] + sb2[co1]);
        act11[(co0 + 8) * 121 + p1] = lrelu(dB[2] + sb2[co0 + 8]);
        act11[(co1 + 8) * 121 + p1] = lrelu(dB[3] + sb2[co1 + 8]);
      }
    }
  }
  __syncthreads();

  // ---- phase 4: gaze11 via MMA (M=176), warps 0-10, in-place ----
  if (warp < 11) {
    const uint4* kf = (const uint4*)(sm + OFF_K11F);
    float* act = sm + OFF_ACT11;
    int r0 = warp * 16 + g, r1 = r0 + 8;
    const float* a0p = act + r0 * 11;
    const float* a1p = act + r1 * 11;
    int k0 = tig * 2, k8 = k0 + 8;
    float a00 = a0p[k0], a01 = a0p[k0 + 1];
    float a10 = a1p[k0], a11 = a1p[k0 + 1];
    float a02 = (k8 < 11) ? a0p[k8] : 0.f;
    float a03 = (k8 + 1 < 11) ? a0p[k8 + 1] : 0.f;
    float a12 = (k8 < 11) ? a1p[k8] : 0.f;
    float a13 = (k8 + 1 < 11) ? a1p[k8 + 1] : 0.f;
    unsigned ah[4], al[4];
    SPLIT_PAIR(a00, a01, ah[0], al[0]);
    SPLIT_PAIR(a10, a11, ah[1], al[1]);
    SPLIT_PAIR(a02, a03, ah[2], al[2]);
    SPLIT_PAIR(a12, a13, ah[3], al[3]);
    float d[2][4];
#pragma unroll
    for (int nt = 0; nt < 2; nt++)
#pragma unroll
      for (int e = 0; e < 4; e++) d[nt][e] = 0.f;
#pragma unroll
    for (int nt = 0; nt < 2; nt++) {
      uint4 B = kf[nt * 32 + lane];
      MMA_BF16(d[nt][0], d[nt][1], d[nt][2], d[nt][3],
               ah[0], ah[1], ah[2], ah[3], B.x, B.y);
      MMA_BF16(d[nt][0], d[nt][1], d[nt][2], d[nt][3],
               ah[0], ah[1], ah[2], ah[3], B.z, B.w);
      MMA_BF16(d[nt][0], d[nt][1], d[nt][2], d[nt][3],
               al[0], al[1], al[2], al[3], B.x, B.y);
    }
    float* w0p = act + r0 * 11;
    float* w1p = act + r1 * 11;
#pragma unroll
    for (int nt = 0; nt < 2; nt++) {
      int c0 = nt * 8 + tig * 2, c1 = c0 + 1;
      if (c0 < 11) { w0p[c0] = d[nt][0]; w1p[c0] = d[nt][2]; }
      if (c1 < 11) { w0p[c1] = d[nt][1]; w1p[c1] = d[nt][3]; }
    }
  }
  __syncthreads();

  // ---- phase 5: conv3 MMA (M=81, N=16, K=144), 2-way K-split, 12 units ----
  {
    bool active = warp < 12;
    int tile = 0, khalf = 0;
    float dA[4] = {0.f, 0.f, 0.f, 0.f};
    float dB[4] = {0.f, 0.f, 0.f, 0.f};
    bool ok0 = false, ok1 = false;
    int p0 = 0, p1 = 0;
    if (active) {
      tile = warp % 6; khalf = warp / 6;
      const float* act11 = sm + OFF_ACT11;
      const int* kt3 = (const int*)(sm + OFF_KT3);
      const uint4* wfrag = (const uint4*)(sm + OFF_W3F);
      p0 = tile * 16 + g; p1 = p0 + 8;
      ok0 = p0 < 81; ok1 = p1 < 81;
      int oh0 = p0 / 9, ow0 = p0 - oh0 * 9;
      int oh1 = p1 / 9, ow1 = p1 - oh1 * 9;
      int pb0 = ok0 ? (oh0 * 11 + ow0) : 0;
      int pb1 = ok1 ? (oh1 * 11 + ow1) : 0;
      int sbeg = khalf ? 5 : 0, send = khalf ? 9 : 5;
      int k0 = sbeg * 16 + tig * 2;
      for (int s = sbeg; s < send; s++, k0 += 16) {
        uint4 B0 = wfrag[(s * 2 + 0) * 32 + lane];
        uint4 B1 = wfrag[(s * 2 + 1) * 32 + lane];
        int o0 = kt3[k0], o1 = kt3[k0 + 1], o2 = kt3[k0 + 8], o3 = kt3[k0 + 9];
        float e00 = ok0 ? act11[o0 + pb0] : 0.f, e01 = ok0 ? act11[o1 + pb0] : 0.f;
        float e02 = ok0 ? act11[o2 + pb0] : 0.f, e03 = ok0 ? act11[o3 + pb0] : 0.f;
        float e10 = ok1 ? act11[o0 + pb1] : 0.f, e11 = ok1 ? act11[o1 + pb1] : 0.f;
        float e12 = ok1 ? act11[o2 + pb1] : 0.f, e13 = ok1 ? act11[o3 + pb1] : 0.f;
        unsigned ah[4], al[4];
        SPLIT_PAIR(e00, e01, ah[0], al[0]);
        SPLIT_PAIR(e10, e11, ah[1], al[1]);
        SPLIT_PAIR(e02, e03, ah[2], al[2]);
        SPLIT_PAIR(e12, e13, ah[3], al[3]);
        MMA_BF16(dA[0], dA[1], dA[2], dA[3], ah[0], ah[1], ah[2], ah[3], B0.x, B0.y);
        MMA_BF16(dA[0], dA[1], dA[2], dA[3], ah[0], ah[1], ah[2], ah[3], B0.z, B0.w);
        MMA_BF16(dA[0], dA[1], dA[2], dA[3], al[0], al[1], al[2], al[3], B0.x, B0.y);
        MMA_BF16(dB[0], dB[1], dB[2], dB[3], ah[0], ah[1], ah[2], ah[3], B1.x, B1.y);
        MMA_BF16(dB[0], dB[1], dB[2], dB[3], ah[0], ah[1], ah[2], ah[3], B1.z, B1.w);
        MMA_BF16(dB[0], dB[1], dB[2], dB[3], al[0], al[1], al[2], al[3], B1.x, B1.y);
      }
      if (khalf) {
        float* pb = sm + OFF_PBUF3 + tile * 256 + lane * 8;
#pragma unroll
        for (int e = 0; e < 4; e++) { pb[e] = dA[e]; pb[4 + e] = dB[e]; }
      }
    }
    __syncthreads();
    if (active && !khalf) {
      const float* pb = sm + OFF_PBUF3 + tile * 256 + lane * 8;
#pragma unroll
      for (int e = 0; e < 4; e++) { dA[e] += pb[e]; dB[e] += pb[4 + e]; }
      float* act9 = sm + OFF_ACT9;
      const float* sb3 = sm + OFF_SB3;
      int co0 = tig * 2, co1 = co0 + 1;
      if (ok0) {
        act9[co0 * 81 + p0] = lrelu(dA[0] + sb3[co0]);
        act9[co1 * 81 + p0] = lrelu(dA[1] + sb3[co1]);
        act9[(co0 + 8) * 81 + p0] = lrelu(dB[0] + sb3[co0 + 8]);
        act9[(co1 + 8) * 81 + p0] = lrelu(dB[1] + sb3[co1 + 8]);
      }
      if (ok1) {
        act9[co0 * 81 + p1] = lrelu(dA[2] + sb3[co0]);
        act9[co1 * 81 + p1] = lrelu(dA[3] + sb3[co1]);
        act9[(co0 + 8) * 81 + p1] = lrelu(dB[2] + sb3[co0 + 8]);
        act9[(co1 + 8) * 81 + p1] = lrelu(dB[3] + sb3[co1 + 8]);
      }
    }
  }
  __syncthreads();

  // ---- phase 6: conv4 MMA (M=49, N=16, K=144), 2-way K-split, 8 units ----
  {
    bool active = warp < 8;
    int tile = 0, khalf = 0;
    float dA[4] = {0.f, 0.f, 0.f, 0.f};
    float dB[4] = {0.f, 0.f, 0.f, 0.f};
    bool ok0 = false, ok1 = false;
    int p0 = 0, p1 = 0;
    if (active) {
      tile = warp & 3; khalf = warp >> 2;
      const float* act9 = sm + OFF_ACT9;
      const int* kt4 = (const int*)(sm + OFF_KT4);
      const uint4* wfrag = (const uint4*)(sm + OFF_W4F);
      p0 = tile * 16 + g; p1 = p0 + 8;
      ok0 = p0 < 49; ok1 = p1 < 49;
      int oh0 = p0 / 7, ow0 = p0 - oh0 * 7;
      int oh1 = p1 / 7, ow1 = p1 - oh1 * 7;
      int pb0 = ok0 ? (oh0 * 9 + ow0) : 0;
      int pb1 = ok1 ? (oh1 * 9 + ow1) : 0;
      int sbeg = khalf ? 5 : 0, send = khalf ? 9 : 5;
      int k0 = sbeg * 16 + tig * 2;
      for (int s = sbeg; s < send; s++, k0 += 16) {
        uint4 B0 = wfrag[(s * 2 + 0) * 32 + lane];
        uint4 B1 = wfrag[(s * 2 + 1) * 32 + lane];
        int o0 = kt4[k0], o1 = kt4[k0 + 1], o2 = kt4[k0 + 8], o3 = kt4[k0 + 9];
        float e00 = ok0 ? act9[o0 + pb0] : 0.f, e01 = ok0 ? act9[o1 + pb0] : 0.f;
        float e02 = ok0 ? act9[o2 + pb0] : 0.f, e03 = ok0 ? act9[o3 + pb0] : 0.f;
        float e10 = ok1 ? act9[o0 + pb1] : 0.f, e11 = ok1 ? act9[o1 + pb1] : 0.f;
        float e12 = ok1 ? act9[o2 + pb1] : 0.f, e13 = ok1 ? act9[o3 + pb1] : 0.f;
        unsigned ah[4], al[4];
        SPLIT_PAIR(e00, e01, ah[0], al[0]);
        SPLIT_PAIR(e10, e11, ah[1], al[1]);
        SPLIT_PAIR(e02, e03, ah[2], al[2]);
        SPLIT_PAIR(e12, e13, ah[3], al[3]);
        MMA_BF16(dA[0], dA[1], dA[2], dA[3], ah[0], ah[1], ah[2], ah[3], B0.x, B0.y);
        MMA_BF16(dA[0], dA[1], dA[2], dA[3], ah[0], ah[1], ah[2], ah[3], B0.z, B0.w);
        MMA_BF16(dA[0], dA[1], dA[2], dA[3], al[0], al[1], al[2], al[3], B0.x, B0.y);
        MMA_BF16(dB[0], dB[1], dB[2], dB[3], ah[0], ah[1], ah[2], ah[3], B1.x, B1.y);
        MMA_BF16(dB[0], dB[1], dB[2], dB[3], ah[0], ah[1], ah[2], ah[3], B1.z, B1.w);
        MMA_BF16(dB[0], dB[1], dB[2], dB[3], al[0], al[1], al[2], al[3], B1.x, B1.y);
      }
      if (khalf) {
        float* pb = sm + OFF_PBUF4 + tile * 256 + lane * 8;
#pragma unroll
        for (int e = 0; e < 4; e++) { pb[e] = dA[e]; pb[4 + e] = dB[e]; }
      }
    }
    __syncthreads();
    if (active && !khalf) {
      const float* pb = sm + OFF_PBUF4 + tile * 256 + lane * 8;
#pragma unroll
      for (int e = 0; e < 4; e++) { dA[e] += pb[e]; dB[e] += pb[4 + e]; }
      const float* sb4 = sm + OFF_SB4;
      int co0 = tig * 2, co1 = co0 + 1;
      if (ok0) {
        float* xp = g_xf + (size_t)n * 784 + p0;
        float v0 = lrelu(dA[0] + sb4[co0]);
        float v1 = lrelu(dA[1] + sb4[co1]);
        float v2 = lrelu(dB[0] + sb4[co0 + 8]);
        float v3 = lrelu(dB[1] + sb4[co1 + 8]);
        xp[co0 * 49] = v0; xp[co1 * 49] = v1;
        xp[(co0 + 8) * 49] = v2; xp[(co1 + 8) * 49] = v3;
        sm[OFF_SCM + p0 * 4 + tig] = v0 + v1 + v2 + v3;
      }
      if (ok1) {
        float* xp = g_xf + (size_t)n * 784 + p1;
        float v0 = lrelu(dA[2] + sb4[co0]);
        float v1 = lrelu(dA[3] + sb4[co1]);
        float v2 = lrelu(dB[2] + sb4[co0 + 8]);
        float v3 = lrelu(dB[3] + sb4[co1 + 8]);
        xp[co0 * 49] = v0; xp[co1 * 49] = v1;
        xp[(co0 + 8) * 49] = v2; xp[(co1 + 8) * 49] = v3;
        sm[OFF_SCM + p1 * 4 + tig] = v0 + v1 + v2 + v3;
      }
    }
  }
  __syncthreads();
  if (tid < 49) {
    const float* s4 = sm + OFF_SCM + tid * 4;
    g_cm[(size_t)n * 49 + tid] = (s4[0] + s4[1]) + (s4[2] + s4[3]);
  }
}

// ---------------- fc ----------------
__global__ __launch_bounds__(256) void k_fc(const float* __restrict__ w1,
                                            const float* __restrict__ b1,
                                            const float* __restrict__ w2,
                                            const float* __restrict__ b2) {
  __shared__ float As[64][17];
  __shared__ float Bs[16][68];
  __shared__ float prs[16][64];
  int tid = threadIdx.x;
  int s0 = blockIdx.x * 64;
  int sg = tid >> 4, jg = tid & 15;
  float acc[4][4];
#pragma unroll
  for (int i = 0; i < 4; i++)
#pragma unroll
    for (int u = 0; u < 4; u++) acc[i][u] = 0.f;
  for (int k0 = 0; k0 < 784; k0 += 16) {
    for (int i = tid; i < 1024; i += 256) {
      int s = i >> 4, kk = i & 15;
      As[s][kk] = g_xf[(size_t)(s0 + s) * 784 + k0 + kk];
    }
    for (int i = tid; i < 1024; i += 256) {
      int j = i >> 4, kk = i & 15;
      Bs[kk][j] = w1[j * 784 + k0 + kk];
    }
    __syncthreads();
#pragma unroll
    for (int kk = 0; kk < 16; kk++) {
      float av[4], bv[4];
#pragma unroll
      for (int i = 0; i < 4; i++) av[i] = As[sg * 4 + i][kk];
#pragma unroll
      for (int u = 0; u < 4; u++) bv[u] = Bs[kk][jg * 4 + u];
#pragma unroll
      for (int i = 0; i < 4; i++)
#pragma unroll
        for (int u = 0; u < 4; u++) acc[i][u] += av[i] * bv[u];
    }
    __syncthreads();
  }
#pragma unroll
  for (int i = 0; i < 4; i++) {
    float pr = 0.f;
#pragma unroll
    for (int u = 0; u < 4; u++) {
      int j = jg * 4 + u;
      float h = acc[i][u] + b1[j];
      h = lrelu(h);
      pr += h * w2[j];
    }
    prs[jg][sg * 4 + i] = pr;
  }
  __syncthreads();
  if (tid < 64) {
    float s = 0.f;
#pragma unroll
    for (int j = 0; j < 16; j++) s += prs[j][tid];
    g_r[s0 + tid] = s + b2[0];
  }
}

__global__ void k_reduce_r(float* __restrict__ out) {
  __shared__ float sab[64];
  int tid = threadIdx.x;
  int traj = tid >> 5, b = tid & 31;
  float s = 0.f, sa = 0.f;
  for (int t = 0; t < 64; t++) {
    float r = g_r[traj * 2048 + t * 32 + b];
    s += r;
    sa += fabsf(r);
  }
  out[tid] = s;
  sab[tid] = sa;
  __syncthreads();
  if (tid < 32) out[64 + tid] = sab[tid] + sab[32 + tid];
}

__global__ __launch_bounds__(256) void k_cmnorm(float* __restrict__ out) {
  __shared__ float sv[1568];
  __shared__ float smn[8], smx[8];
  __shared__ float fmn, fmx;
  int idx = blockIdx.x;
  int traj = idx >> 6, t = idx & 63;
  int tid = threadIdx.x;
  const float* base = g_cm + ((size_t)(traj * 2048 + t * 32)) * 49;
  float mn = 1e30f, mx = -1e30f;
  for (int i = tid; i < 1568; i += 256) {
    float v = base[i];
    sv[i] = v;
    mn = fminf(mn, v);
    mx = fmaxf(mx, v);
  }
#pragma unroll
  for (int o = 16; o; o >>= 1) {
    mn = fminf(mn, __shfl_xor_sync(0xffffffffu, mn, o));
    mx = fmaxf(mx, __shfl_xor_sync(0xffffffffu, mx, o));
  }
  if ((tid & 31) == 0) { smn[tid >> 5] = mn; smx[tid >> 5] = mx; }
  __syncthreads();
  if (tid == 0) {
    float a = smn[0], bb = smx[0];
    for (int i = 1; i < 8; i++) { a = fminf(a, smn[i]); bb = fmaxf(bb, smx[i]); }
    fmn = a; fmx = bb;
  }
  __syncthreads();
  float m = fmn, inv = 1.f / (fmx - m);
  float* o = out + 96 + (size_t)traj * 100352 + (size_t)t * 1568;
  for (int i = tid; i < 1568; i += 256) o[i] = (sv[i] - m) * inv;
}

extern "C" void kernel_launch(void* const* d_in, const int* in_sizes, int n_in,
                              void* d_out, int out_size) {
  const float* ti   = (const float*)d_in[0];
  const float* tj   = (const float*)d_in[1];
  const float* g26i = (const float*)d_in[2];
  const float* g11i = (const float*)d_in[3];
  const float* g26j = (const float*)d_in[4];
  const float* g11j = (const float*)d_in[5];
  const float* w1 = (const float*)d_in[6];  const float* b1 = (const float*)d_in[7];
  const float* w2 = (const float*)d_in[8];  const float* b2 = (const float*)d_in[9];
  const float* w3 = (const float*)d_in[10]; const float* b3 = (const float*)d_in[11];
  const float* w4 = (const float*)d_in[12]; const float* b4 = (const float*)d_in[13];
  const float* f1w = (const float*)d_in[14]; const float* f1b = (const float*)d_in[15];
  const float* f2w = (const float*)d_in[16]; const float* f2b = (const float*)d_in[17];
  float* out = (float*)d_out;

  cudaFuncSetAttribute(k_net, cudaFuncAttributeMaxDynamicSharedMemorySize,
                       SMEM_FLOATS * 4);

  k_prep<<<4, 512>>>(w1, w2, w3, w4);
  k_net<<<NTOT, TPB, SMEM_FLOATS * 4>>>(ti, tj, g26i, g26j, g11i, g11j,
                                        b1, b2, b3, b4);
  k_fc<<<NTOT / 64, 256>>>(f1w, f1b, f2w, f2b);
  k_reduce_r<<<1, 64>>>(out);
  k_cmnorm<<<128, 256>>>(out);
}